// round 7
// baseline (speedup 1.0000x reference)
#include <cuda_runtime.h>
#include <cuda_bf16.h>
#include <math.h>
#include <stdint.h>

#define Bn 8
#define Cn 256
#define Hn 64
#define Wn 64
#define NHn 4
#define HDn 64
#define NTOK 1024
#define KFn 256

typedef __nv_bfloat16 bf;

// ---------------- static scratch ----------------
__device__ bf    g_colh[33554432], g_coll[33554432];
__device__ bf    g_xdh[2097152],  g_xdl[2097152];
__device__ bf    g_qch[6291456],  g_qcl[6291456];
__device__ bf    g_qfh[6291456],  g_qfl[6291456];
__device__ float g_S[33554432];
__device__ bf    g_Ph[33554432],  g_Pl[33554432];
__device__ float g_score[Bn*NHn*NTOK];
__device__ int   g_topk[Bn*NHn*KFn];
__device__ float g_outc[Bn*Cn*1024];
__device__ bf    g_tokh[2097152], g_tokl[2097152];
__device__ float g_outfT[2097152];
__device__ float g_coarse4[33554432];
__device__ float g_coarse[8388608];
__device__ float g_y0[8388608];
__device__ bf    g_t1h[8388608],  g_t1l[8388608];
__device__ bf    g_wdh[1048576],  g_wdl[1048576];
__device__ bf    g_Wph[1048576],  g_Wpl[1048576];
__device__ bf    g_wqch[12288],   g_wqcl[12288];
__device__ bf    g_wqfh[12288],   g_wqfl[12288];
__device__ bf    g_pwh[65536],    g_pwl[65536];
__device__ float g_bn1sc[Cn], g_bn1sh[Cn], g_bn2sc[Cn], g_bn2sh[Cn];

// ================= helpers =================
__device__ __forceinline__ void ldsm4(uint32_t* r, uint32_t addr) {
    asm volatile("ldmatrix.sync.aligned.m8n8.x4.shared.b16 {%0,%1,%2,%3}, [%4];"
                 : "=r"(r[0]), "=r"(r[1]), "=r"(r[2]), "=r"(r[3]) : "r"(addr));
}
__device__ __forceinline__ void ldsm4t(uint32_t* r, uint32_t addr) {
    asm volatile("ldmatrix.sync.aligned.m8n8.x4.trans.shared.b16 {%0,%1,%2,%3}, [%4];"
                 : "=r"(r[0]), "=r"(r[1]), "=r"(r[2]), "=r"(r[3]) : "r"(addr));
}
__device__ __forceinline__ void mma16816(float* d, const uint32_t* a, const uint32_t* b) {
    asm volatile("mma.sync.aligned.m16n8k16.row.col.f32.bf16.bf16.f32 "
                 "{%0,%1,%2,%3},{%4,%5,%6,%7},{%8,%9},{%0,%1,%2,%3};"
                 : "+f"(d[0]), "+f"(d[1]), "+f"(d[2]), "+f"(d[3])
                 : "r"(a[0]), "r"(a[1]), "r"(a[2]), "r"(a[3]), "r"(b[0]), "r"(b[1]));
}
__device__ __forceinline__ void cpa16(uint32_t dst, const void* src) {
    asm volatile("cp.async.cg.shared.global [%0], [%1], 16;" :: "r"(dst), "l"(src));
}
#define CP_COMMIT() asm volatile("cp.async.commit_group;" ::: "memory")
#define CP_WAIT0()  asm volatile("cp.async.wait_group 0;" ::: "memory")

__device__ __forceinline__ uint32_t packbf2(float a, float b) {
    __nv_bfloat162 t;
    t.x = __float2bfloat16_rn(a); t.y = __float2bfloat16_rn(b);
    return *(uint32_t*)&t;
}
__device__ __forceinline__ void split4(float4 f, uint2& hv, uint2& lv) {
    float hx = __bfloat162float(__float2bfloat16_rn(f.x));
    float hy = __bfloat162float(__float2bfloat16_rn(f.y));
    float hz = __bfloat162float(__float2bfloat16_rn(f.z));
    float hw = __bfloat162float(__float2bfloat16_rn(f.w));
    hv.x = packbf2(f.x, f.y);           hv.y = packbf2(f.z, f.w);
    lv.x = packbf2(f.x - hx, f.y - hy); lv.y = packbf2(f.z - hz, f.w - hw);
}
__device__ __forceinline__ void split1(float a, bf* oh, bf* ol) {
    bf h = __float2bfloat16_rn(a);
    *oh = h;
    *ol = __float2bfloat16_rn(a - __bfloat162float(h));
}

// ================= HMMA GEMM, layout-exact smem slots =================
template<bool ATR, bool BKN, bool M64T>
__global__ __launch_bounds__(256) void hgemm(
    const bf* __restrict__ Agh, const bf* __restrict__ Agl,
    const bf* __restrict__ Bgh, const bf* __restrict__ Bgl,
    float* __restrict__ Cf, bf* __restrict__ Ch, bf* __restrict__ Cl,
    int M, int N, int K, int lda, int ldb, int ldc,
    long long sA, long long sB, long long sC, int zamask,
    float alpha, const float* __restrict__ rowScale, const float* __restrict__ rowShift,
    float lo, float hi)
{
    constexpr int MT    = M64T ? 64 : 128;
    constexpr int NFP   = M64T ? 2 : 4;
    constexpr int NWS   = M64T ? 32 : 64;
    constexpr int ASLOT = ATR ? 8704 : MT * 80;
    constexpr int BSLOT = BKN ? 8704 : 10240;
    constexpr int STG   = 2 * (ASLOT + BSLOT);
    extern __shared__ char sm[];
    const uint32_t smb = (uint32_t)__cvta_generic_to_shared(sm);
    const int tid = threadIdx.x;
    const int wid = tid >> 5, lane = tid & 31;
    const int grp = lane >> 2, tig = lane & 3;
    const int z = blockIdx.z;
    const int za = z & zamask;
    Agh += (size_t)za * sA; Agl += (size_t)za * sA;
    Bgh += (size_t)z * sB;  Bgl += (size_t)z * sB;
    if (Cf) Cf += (size_t)z * sC;
    if (Ch) { Ch += (size_t)z * sC; Cl += (size_t)z * sC; }
    const int m0 = blockIdx.y * MT, n0 = blockIdx.x * 128;
    const int mw = M64T ? (wid >> 2) : (wid >> 1);
    const int nw = M64T ? (wid & 3) : (wid & 1);

    float acc[2][2*NFP][4];
    #pragma unroll
    for (int i = 0; i < 2; i++)
        #pragma unroll
        for (int j = 0; j < 2*NFP; j++)
            #pragma unroll
            for (int q = 0; q < 4; q++) acc[i][j][q] = 0.f;

    const int nch = K >> 5;

    auto stage_copy = [&](int c, int s) {
        const int k0 = c << 5;
        const uint32_t Ab = smb + s * STG;
        const uint32_t Bb = Ab + 2 * ASLOT;
        #pragma unroll
        for (int p = 0; p < ((!ATR && M64T) ? 1 : 2); p++) {
            int id = tid + (p << 8);
            if (!ATR) {
                int m = id >> 2, part = id & 3;
                size_t off = (size_t)(m0 + m) * lda + k0 + part * 8;
                uint32_t d = Ab + m * 80 + part * 16;
                cpa16(d, Agh + off);
                cpa16(d + ASLOT, Agl + off);
            } else {
                int k = id >> 4, part = id & 15;
                size_t off = (size_t)(k0 + k) * lda + m0 + part * 8;
                uint32_t d = Ab + k * 272 + part * 16;
                cpa16(d, Agh + off);
                cpa16(d + ASLOT, Agl + off);
            }
        }
        #pragma unroll
        for (int p = 0; p < 2; p++) {
            int id = tid + (p << 8);
            if (BKN) {
                int k = id >> 4, part = id & 15;
                size_t off = (size_t)(k0 + k) * ldb + n0 + part * 8;
                uint32_t d = Bb + k * 272 + part * 16;
                cpa16(d, Bgh + off);
                cpa16(d + BSLOT, Bgl + off);
            } else {
                int n = id >> 2, part = id & 3;
                size_t off = (size_t)(n0 + n) * ldb + k0 + part * 8;
                uint32_t d = Bb + n * 80 + part * 16;
                cpa16(d, Bgh + off);
                cpa16(d + BSLOT, Bgl + off);
            }
        }
    };

    auto compute = [&](int s) {
        const uint32_t Ab = smb + s * STG;
        const uint32_t Bb = Ab + 2 * ASLOT;
        const int i = lane >> 3;
        #pragma unroll
        for (int kk = 0; kk < 32; kk += 16) {
            uint32_t ah[2][4], al[2][4];
            #pragma unroll
            for (int mf = 0; mf < 2; mf++) {
                uint32_t addr;
                if (!ATR) {
                    addr = Ab + (uint32_t)((mw * 32 + mf * 16 + (lane & 15)) * 80 + (kk + (lane >> 4) * 8) * 2);
                    ldsm4(ah[mf], addr); ldsm4(al[mf], addr + ASLOT);
                } else {
                    addr = Ab + (uint32_t)((kk + (i >> 1) * 8 + (lane & 7)) * 272 + (mw * 32 + mf * 16 + (i & 1) * 8) * 2);
                    ldsm4t(ah[mf], addr); ldsm4t(al[mf], addr + ASLOT);
                }
            }
            uint32_t bh[NFP][4], bl[NFP][4];
            #pragma unroll
            for (int nfp = 0; nfp < NFP; nfp++) {
                uint32_t addr;
                if (BKN) {
                    addr = Bb + (uint32_t)((kk + (i & 1) * 8 + (lane & 7)) * 272 + (nw * NWS + nfp * 16 + (i >> 1) * 8) * 2);
                    ldsm4t(bh[nfp], addr); ldsm4t(bl[nfp], addr + BSLOT);
                } else {
                    addr = Bb + (uint32_t)((nw * NWS + nfp * 16 + (i >> 1) * 8 + (lane & 7)) * 80 + (kk + (i & 1) * 8) * 2);
                    ldsm4(bh[nfp], addr); ldsm4(bl[nfp], addr + BSLOT);
                }
            }
            #pragma unroll
            for (int pass = 0; pass < 3; pass++) {
                #pragma unroll
                for (int nfp = 0; nfp < NFP; nfp++) {
                    #pragma unroll
                    for (int mf = 0; mf < 2; mf++) {
                        #pragma unroll
                        for (int h = 0; h < 2; h++) {
                            const uint32_t* a = (pass == 2) ? al[mf] : ah[mf];
                            const uint32_t* b = ((pass == 1) ? bl[nfp] : bh[nfp]) + h * 2;
                            mma16816(acc[mf][nfp * 2 + h], a, b);
                        }
                    }
                }
            }
        }
    };

    stage_copy(0, 0); CP_COMMIT();
    for (int c = 0; c < nch; c++) {
        CP_WAIT0();
        __syncthreads();
        if (c + 1 < nch) { stage_copy(c + 1, (c + 1) & 1); CP_COMMIT(); }
        compute(c & 1);
    }
    __syncthreads();

    // ---- epilogue ----
    float* stg = (float*)sm;   // [MT][132]
    #pragma unroll
    for (int mf = 0; mf < 2; mf++) {
        int r0 = mw * 32 + mf * 16 + grp;
        float av0 = alpha, av1 = alpha, sh0 = 0.f, sh1 = 0.f;
        if (rowScale) { av0 *= rowScale[m0 + r0]; av1 *= rowScale[m0 + r0 + 8]; }
        if (rowShift) { sh0 = rowShift[m0 + r0]; sh1 = rowShift[m0 + r0 + 8]; }
        #pragma unroll
        for (int nf = 0; nf < 2*NFP; nf++) {
            int cb = nw * NWS + nf * 8 + tig * 2;
            float* d = acc[mf][nf];
            stg[r0 * 132 + cb]           = fminf(fmaxf(d[0] * av0 + sh0, lo), hi);
            stg[r0 * 132 + cb + 1]       = fminf(fmaxf(d[1] * av0 + sh0, lo), hi);
            stg[(r0 + 8) * 132 + cb]     = fminf(fmaxf(d[2] * av1 + sh1, lo), hi);
            stg[(r0 + 8) * 132 + cb + 1] = fminf(fmaxf(d[3] * av1 + sh1, lo), hi);
        }
    }
    __syncthreads();
    if (Cf) {
        #pragma unroll
        for (int it = 0; it < MT/8; it++) {
            int lin = tid + (it << 8);
            int rr = lin >> 5, c4 = (lin & 31) << 2;
            *(float4*)(Cf + (size_t)(m0 + rr) * ldc + n0 + c4) = *(float4*)&stg[rr * 132 + c4];
        }
    } else {
        #pragma unroll
        for (int it = 0; it < MT/8; it++) {
            int lin = tid + (it << 8);
            int rr = lin >> 5, c4 = (lin & 31) << 2;
            float4 v = *(float4*)&stg[rr * 132 + c4];
            uint2 hv, lv;
            split4(v, hv, lv);
            size_t o = (size_t)(m0 + rr) * ldc + n0 + c4;
            *(uint2*)(Ch + o) = hv;
            *(uint2*)(Cl + o) = lv;
        }
    }
}

// ---------------- fused weight prep ----------------
#define PREP_O2 1048576
#define PREP_O3 1060864
#define PREP_O4 1073152
#define PREP_O5 1138688
#define PREP_O6 2187264
#define PREP_END 2187776
__global__ void k_prep_all(const float* __restrict__ down_w,
                           const float* __restrict__ wqkv_c, const float* __restrict__ wqkv_f,
                           const float* __restrict__ pw_w,   const float* __restrict__ up_w,
                           const float* __restrict__ bn1_g, const float* __restrict__ bn1_b,
                           const float* __restrict__ bn1_m, const float* __restrict__ bn1_v,
                           const float* __restrict__ bn2_g, const float* __restrict__ bn2_b,
                           const float* __restrict__ bn2_m, const float* __restrict__ bn2_v) {
    int idx = blockIdx.x * 256 + threadIdx.x;
    if (idx < PREP_O2) {
        split1(down_w[idx], g_wdh + idx, g_wdl + idx);
    } else if (idx < PREP_O3) {
        int i = idx - PREP_O2;
        int m = i / 64, k = i % 64;
        split1(wqkv_c[k * 192 + m], g_wqch + i, g_wqcl + i);
    } else if (idx < PREP_O4) {
        int i = idx - PREP_O3;
        int m = i / 64, k = i % 64;
        split1(wqkv_f[k * 192 + m], g_wqfh + i, g_wqfl + i);
    } else if (idx < PREP_O5) {
        int i = idx - PREP_O4;
        split1(pw_w[i], g_pwh + i, g_pwl + i);
    } else if (idx < PREP_O6) {
        int i = idx - PREP_O5;
        int k = i & 1023, co = (i >> 10) & 255, p = i >> 18;
        int tj = k & 1, ti = (k >> 1) & 1, ci = k >> 2;
        int px = p & 1, py = p >> 1;
        int kh = (py == 0) ? (ti == 0 ? 1 : 3) : (ti == 0 ? 0 : 2);
        int kw = (px == 0) ? (tj == 0 ? 1 : 3) : (tj == 0 ? 0 : 2);
        split1(up_w[((ci << 8) + co) * 16 + kh*4 + kw], g_Wph + i, g_Wpl + i);
    } else if (idx < PREP_END) {
        int i = idx - PREP_O6;
        int c = i & 255;
        if (i < 256) {
            float inv = bn1_g[c] / sqrtf(bn1_v[c] + 1e-5f);
            g_bn1sc[c] = inv;
            g_bn1sh[c] = bn1_b[c] - bn1_m[c] * inv;
        } else {
            float inv = bn2_g[c] / sqrtf(bn2_v[c] + 1e-5f);
            g_bn2sc[c] = inv;
            g_bn2sh[c] = bn2_b[c] - bn2_m[c] * inv;
        }
    }
}

// ---------------- elementwise kernels ----------------
__global__ void k_im2col_down(const float* __restrict__ x) {
    int idx = blockIdx.x * 256 + threadIdx.x;
    int q  = idx & 255;
    int k  = (idx >> 8) & 4095;
    int b  = idx >> 20;
    int kw = k & 3, kh = (k >> 2) & 3, ci = k >> 4;
    int ow0 = (q & 7) << 2, oh = q >> 3;
    int ih = oh*2 - 1 + kh;
    const float* xr = x + ((long long)b*Cn + ci)*(Hn*Wn) + ih*Wn;
    float4 r;
    float* rp = (float*)&r;
    #pragma unroll
    for (int j = 0; j < 4; j++) {
        int iw = (ow0 + j)*2 - 1 + kw;
        rp[j] = (ih >= 0 && ih < Hn && iw >= 0 && iw < Wn) ? xr[iw] : 0.f;
    }
    uint2 hv, lv; split4(r, hv, lv);
    size_t o = ((size_t)idx) << 2;
    *(uint2*)&g_colh[o] = hv;
    *(uint2*)&g_coll[o] = lv;
}

__global__ void k_im2col_up() {
    int idx = blockIdx.x * 256 + threadIdx.x;
    int q = idx & 255;
    int k = (idx >> 8) & 1023;
    int s = idx >> 18;
    int tj = k & 1, ti = (k >> 1) & 1, ci = k >> 2;
    int px = s & 1, py = (s >> 1) & 1, b = s >> 2;
    int c0 = (q & 7) << 2, a = q >> 3;
    int iy = (py == 0) ? (ti == 0 ? a : a - 1) : (ti == 0 ? a + 1 : a);
    int dx = (px == 0) ? (tj == 0 ? 0 : -1) : (tj == 0 ? 1 : 0);
    const float* orow = g_outc + ((long long)b*Cn + ci)*1024 + iy*32;
    float4 r;
    float* rp = (float*)&r;
    bool rowok = (iy >= 0 && iy < 32);
    #pragma unroll
    for (int j = 0; j < 4; j++) {
        int ix = c0 + j + dx;
        rp[j] = (rowok && ix >= 0 && ix < 32) ? orow[ix] : 0.f;
    }
    uint2 hv, lv; split4(r, hv, lv);
    size_t o = ((size_t)idx) << 2;
    *(uint2*)&g_colh[o] = hv;
    *(uint2*)&g_coll[o] = lv;
}

__global__ void k_interleave() {
    int idx = blockIdx.x * 256 + threadIdx.x;
    int n = idx & 1023, co = (idx >> 10) & 255, s = idx >> 18;
    int px = s & 1, py = (s >> 1) & 1, b = s >> 2;
    int c = n & 31, a = n >> 5;
    float v = g_coarse4[idx];
    long long o = ((long long)b*Cn + co)*4096 + (2*a + py)*64 + (2*c + px);
    g_coarse[o] = v;
    g_y0[o] = v;
}

__global__ __launch_bounds__(256) void k_softmax(const float* __restrict__ S,
                                                 bf* __restrict__ Ph, bf* __restrict__ Pl) {
    __shared__ float red[8];
    long long row = blockIdx.x;
    const float* p = S + row * 1024;
    int tid = threadIdx.x;
    float4 v = ((const float4*)p)[tid];
    float mx = fmaxf(fmaxf(v.x, v.y), fmaxf(v.z, v.w));
    #pragma unroll
    for (int o = 16; o; o >>= 1) mx = fmaxf(mx, __shfl_xor_sync(0xffffffffu, mx, o));
    if ((tid & 31) == 0) red[tid >> 5] = mx;
    __syncthreads();
    if (tid == 0) {
        float m = red[0];
        #pragma unroll
        for (int i = 1; i < 8; i++) m = fmaxf(m, red[i]);
        red[0] = m;
    }
    __syncthreads();
    mx = red[0];
    __syncthreads();
    float e0 = __expf(v.x - mx), e1 = __expf(v.y - mx);
    float e2 = __expf(v.z - mx), e3 = __expf(v.w - mx);
    float s = (e0 + e1) + (e2 + e3);
    #pragma unroll
    for (int o = 16; o; o >>= 1) s += __shfl_xor_sync(0xffffffffu, s, o);
    if ((tid & 31) == 0) red[tid >> 5] = s;
    __syncthreads();
    if (tid == 0) {
        float t = 0.f;
        #pragma unroll
        for (int i = 0; i < 8; i++) t += red[i];
        red[0] = t;
    }
    __syncthreads();
    float inv = 1.f / red[0];
    float4 r;
    r.x = e0 * inv; r.y = e1 * inv; r.z = e2 * inv; r.w = e3 * inv;
    uint2 hv, lv; split4(r, hv, lv);
    size_t o = row * 1024 + (size_t)tid * 4;
    *(uint2*)(Ph + o) = hv;
    *(uint2*)(Pl + o) = lv;
}

// column sums of P (hi+lo), 2 columns per thread via packed loads
__global__ void k_colsum() {
    int z = blockIdx.x >> 1;
    int m2 = ((blockIdx.x & 1) << 8) + threadIdx.x;   // column pair index 0..511
    const uint32_t* ph = (const uint32_t*)(g_Ph + (long long)z * 1048576) + m2;
    const uint32_t* pl = (const uint32_t*)(g_Pl + (long long)z * 1048576) + m2;
    float s0 = 0.f, s1 = 0.f;
    #pragma unroll 8
    for (int n = 0; n < 1024; n++) {
        long long o = (long long)n << 9;
        __nv_bfloat162 h = *(const __nv_bfloat162*)&ph[o];
        __nv_bfloat162 l = *(const __nv_bfloat162*)&pl[o];
        s0 += __bfloat162float(h.x) + __bfloat162float(l.x);
        s1 += __bfloat162float(h.y) + __bfloat162float(l.y);
    }
    g_score[z * 1024 + m2 * 2]     = s0;
    g_score[z * 1024 + m2 * 2 + 1] = s1;
}

__global__ __launch_bounds__(512) void k_topk() {
    __shared__ float v[1024];
    __shared__ int   ix[1024];
    int z = blockIdx.x, tid = threadIdx.x;
    for (int i = tid; i < 1024; i += 512) { v[i] = g_score[z*1024 + i]; ix[i] = i; }
    __syncthreads();
    for (int k = 2; k <= 1024; k <<= 1) {
        for (int j = k >> 1; j > 0; j >>= 1) {
            for (int i = tid; i < 1024; i += 512) {
                int l = i ^ j;
                if (l > i) {
                    bool up = ((i & k) == 0);
                    bool sw = up ? (v[i] < v[l]) : (v[i] > v[l]);
                    if (sw) {
                        float tv = v[i]; v[i] = v[l]; v[l] = tv;
                        int ti2 = ix[i]; ix[i] = ix[l]; ix[l] = ti2;
                    }
                }
            }
            __syncthreads();
        }
    }
    for (int i = tid; i < KFn; i += 512) g_topk[z*KFn + i] = ix[i];
}

__global__ void k_gather_fine() {
    int idx = blockIdx.x * 256 + threadIdx.x;
    int t = idx & 1023, d = (idx >> 10) & 63, z = idx >> 16;
    int ki = t >> 2, i = (t >> 1) & 1, j = t & 1;
    int p = g_topk[(z << 8) + ki];
    int pi = p >> 5, pj = p & 31;
    int b = z >> 2, h = z & 3;
    float v = g_coarse[((long long)b*Cn + (h*HDn + d))*4096 + (2*pi + i)*64 + (2*pj + j)];
    split1(v, g_tokh + idx, g_tokl + idx);
}

__global__ void k_scatter() {
    int idx = blockIdx.x * 256 + threadIdx.x;
    int t = idx & 1023, d = (idx >> 10) & 63, z = idx >> 16;
    int ki = t >> 2, i = (t >> 1) & 1, j = t & 1;
    int p = g_topk[(z << 8) + ki];
    int pi = p >> 5, pj = p & 31;
    int b = z >> 2, h = z & 3;
    g_y0[((long long)b*Cn + (h*HDn + d))*4096 + (2*pi + i)*64 + (2*pj + j)] += g_outfT[idx];
}

__global__ void k_dw(const float* __restrict__ dw_w) {
    int idx = blockIdx.x * 256 + threadIdx.x;
    int x4 = (idx & 15) << 2, y = (idx >> 4) & 63, c = (idx >> 10) & 255, b = idx >> 18;
    const float* base = g_y0 + ((long long)b*Cn + c)*4096;
    const float* wp = dw_w + c*9;
    float s[4] = {0.f, 0.f, 0.f, 0.f};
    #pragma unroll
    for (int ky = 0; ky < 3; ky++) {
        int yy = y + ky - 1;
        if (yy < 0 || yy >= 64) continue;
        const float* row = base + yy*64;
        float4 mid = *(const float4*)(row + x4);
        float lft = (x4 > 0)  ? row[x4 - 1] : 0.f;
        float rgt = (x4 < 60) ? row[x4 + 4] : 0.f;
        float w0 = wp[ky*3], w1 = wp[ky*3 + 1], w2 = wp[ky*3 + 2];
        s[0] = fmaf(lft,   w0, fmaf(mid.x, w1, fmaf(mid.y, w2, s[0])));
        s[1] = fmaf(mid.x, w0, fmaf(mid.y, w1, fmaf(mid.z, w2, s[1])));
        s[2] = fmaf(mid.y, w0, fmaf(mid.z, w1, fmaf(mid.w, w2, s[2])));
        s[3] = fmaf(mid.z, w0, fmaf(mid.w, w1, fmaf(rgt,   w2, s[3])));
    }
    float sc = g_bn1sc[c], sh = g_bn1sh[c];
    float4 r;
    r.x = fminf(fmaxf(s[0]*sc + sh, 0.f), 6.f);
    r.y = fminf(fmaxf(s[1]*sc + sh, 0.f), 6.f);
    r.z = fminf(fmaxf(s[2]*sc + sh, 0.f), 6.f);
    r.w = fminf(fmaxf(s[3]*sc + sh, 0.f), 6.f);
    uint2 hv, lv; split4(r, hv, lv);
    size_t o = ((size_t)b*Cn + c)*4096 + y*64 + x4;
    *(uint2*)&g_t1h[o] = hv;
    *(uint2*)&g_t1l[o] = lv;
}

// ---------------- host ----------------
struct GArgs {
    const bf *Ah, *Al, *Bh, *Bl;
    float* Cf; bf *Ch, *Cl;
};
static inline int smem_for(bool atr, bool bkn, bool m64) {
    int aslot = atr ? 8704 : (m64 ? 64 : 128) * 80;
    int bslot = bkn ? 8704 : 10240;
    int two = 2 * 2 * (aslot + bslot);
    int epi = (m64 ? 64 : 128) * 132 * 4;
    return two > epi ? two : epi;
}
// mode 0: A=MxK,B=KxN ; mode 1: A=KxM,B=KxN ; mode 2: A=MxK,B=NxK
static void tg(int mode, bool m64, GArgs g,
               int M, int N, int K, int lda, int ldb, int ldc,
               long long sA, long long sB, long long sC, int Z, int zamask,
               float alpha, const float* sc, const float* sh, float lo, float hi)
{
    dim3 grid(N / 128, M / (m64 ? 64 : 128), Z), blk(256);
    if (mode == 0 && !m64) {
        int shm = smem_for(false, true, false);
        cudaFuncSetAttribute(hgemm<false,true,false>, cudaFuncAttributeMaxDynamicSharedMemorySize, shm);
        hgemm<false,true,false><<<grid, blk, shm>>>(g.Ah, g.Al, g.Bh, g.Bl, g.Cf, g.Ch, g.Cl,
            M, N, K, lda, ldb, ldc, sA, sB, sC, zamask, alpha, sc, sh, lo, hi);
    } else if (mode == 0 && m64) {
        int shm = smem_for(false, true, true);
        cudaFuncSetAttribute(hgemm<false,true,true>, cudaFuncAttributeMaxDynamicSharedMemorySize, shm);
        hgemm<false,true,true><<<grid, blk, shm>>>(g.Ah, g.Al, g.Bh, g.Bl, g.Cf, g.Ch, g.Cl,
            M, N, K, lda, ldb, ldc, sA, sB, sC, zamask, alpha, sc, sh, lo, hi);
    } else if (mode == 1) {
        int shm = smem_for(true, true, false);
        cudaFuncSetAttribute(hgemm<true,true,false>, cudaFuncAttributeMaxDynamicSharedMemorySize, shm);
        hgemm<true,true,false><<<grid, blk, shm>>>(g.Ah, g.Al, g.Bh, g.Bl, g.Cf, g.Ch, g.Cl,
            M, N, K, lda, ldb, ldc, sA, sB, sC, zamask, alpha, sc, sh, lo, hi);
    } else {
        int shm = smem_for(false, false, true);
        cudaFuncSetAttribute(hgemm<false,false,true>, cudaFuncAttributeMaxDynamicSharedMemorySize, shm);
        hgemm<false,false,true><<<grid, blk, shm>>>(g.Ah, g.Al, g.Bh, g.Bl, g.Cf, g.Ch, g.Cl,
            M, N, K, lda, ldb, ldc, sA, sB, sC, zamask, alpha, sc, sh, lo, hi);
    }
}

extern "C" void kernel_launch(void* const* d_in, const int* in_sizes, int n_in,
                              void* d_out, int out_size)
{
    const float* x      = (const float*)d_in[0];
    const float* down_w = (const float*)d_in[1];
    const float* down_b = (const float*)d_in[2];
    const float* up_w   = (const float*)d_in[3];
    const float* up_b   = (const float*)d_in[4];
    const float* wqkv_c = (const float*)d_in[5];
    const float* bqkv_c = (const float*)d_in[6];
    const float* wqkv_f = (const float*)d_in[7];
    const float* bqkv_f = (const float*)d_in[8];
    const float* dw_w   = (const float*)d_in[9];
    const float* bn1_g  = (const float*)d_in[10];
    const float* bn1_b  = (const float*)d_in[11];
    const float* bn1_m  = (const float*)d_in[12];
    const float* bn1_v  = (const float*)d_in[13];
    const float* pw_w   = (const float*)d_in[14];
    const float* bn2_g  = (const float*)d_in[15];
    const float* bn2_b  = (const float*)d_in[16];
    const float* bn2_m  = (const float*)d_in[17];
    const float* bn2_v  = (const float*)d_in[18];
    float* out = (float*)d_out;

    #define SYM(p, s) cudaGetSymbolAddress((void**)&p, s)
    bf *colh, *coll, *xdh, *xdl, *qch, *qcl, *qfh, *qfl, *Ph, *Pl, *tokh, *tokl;
    bf *t1h, *t1l, *wdh, *wdl, *Wph, *Wpl, *wqch, *wqcl, *wqfh, *wqfl, *pwh, *pwl;
    float *S, *outc, *c4, *outf;
    float *b2s, *b2h;
    SYM(colh, g_colh); SYM(coll, g_coll); SYM(xdh, g_xdh); SYM(xdl, g_xdl);
    SYM(qch, g_qch); SYM(qcl, g_qcl); SYM(qfh, g_qfh); SYM(qfl, g_qfl);
    SYM(Ph, g_Ph); SYM(Pl, g_Pl); SYM(tokh, g_tokh); SYM(tokl, g_tokl);
    SYM(t1h, g_t1h); SYM(t1l, g_t1l); SYM(wdh, g_wdh); SYM(wdl, g_wdl);
    SYM(Wph, g_Wph); SYM(Wpl, g_Wpl); SYM(wqch, g_wqch); SYM(wqcl, g_wqcl);
    SYM(wqfh, g_wqfh); SYM(wqfl, g_wqfl); SYM(pwh, g_pwh); SYM(pwl, g_pwl);
    SYM(S, g_S); SYM(outc, g_outc); SYM(c4, g_coarse4);
    SYM(outf, g_outfT);
    SYM(b2s, g_bn2sc); SYM(b2h, g_bn2sh);
    #undef SYM

    const float NEG = -3.0e38f, POS = 3.0e38f;
    const int ZM = 0x7fffffff;

    k_prep_all<<<(PREP_END + 255)/256, 256>>>(down_w, wqkv_c, wqkv_f, pw_w, up_w,
        bn1_g, bn1_b, bn1_m, bn1_v, bn2_g, bn2_b, bn2_m, bn2_v);

    // ---- down conv -> xd planes
    k_im2col_down<<<32768, 256>>>(x);
    tg(0, true, {wdh, wdl, colh, coll, nullptr, xdh, xdl}, 256, 1024, 4096, 4096, 1024, 1024,
       0, 4096LL*1024, 256LL*1024, Bn, ZM, 1.f, nullptr, down_b, NEG, POS);

    // ---- coarse QKV
    tg(0, true, {wqch, wqcl, xdh, xdl, nullptr, qch, qcl}, 192, 1024, 64, 64, 1024, 1024,
       0, 65536, 196608, 32, ZM, 1.f, nullptr, bqkv_c, NEG, POS);

    // ---- coarse S, softmax, colsum, topk
    tg(1, false, {qch, qcl, qch + 65536, qcl + 65536, S, nullptr, nullptr}, 1024, 1024, 64, 1024, 1024, 1024,
       196608, 196608, 1048576, 32, ZM, 0.125f, nullptr, nullptr, NEG, POS);
    k_softmax<<<32768, 256>>>(S, Ph, Pl);
    k_colsum<<<64, 256>>>();
    k_topk<<<32, 512>>>();

    // ---- coarse PV
    tg(2, true, {qch + 131072, qcl + 131072, Ph, Pl, outc, nullptr, nullptr}, 64, 1024, 1024, 1024, 1024, 1024,
       196608, 1048576, 65536, 32, ZM, 1.f, nullptr, nullptr, NEG, POS);

    // ---- up conv transpose: ONE fused launch over (b,par)
    k_im2col_up<<<32768, 256>>>();
    tg(0, false, {Wph, Wpl, colh, coll, c4, nullptr, nullptr}, 256, 1024, 1024, 1024, 1024, 1024,
       262144, 1048576, 262144, 32, 3, 1.f, nullptr, up_b, NEG, POS);
    k_interleave<<<32768, 256>>>();

    // ---- fine attention
    k_gather_fine<<<8192, 256>>>();
    tg(0, true, {wqfh, wqfl, tokh, tokl, nullptr, qfh, qfl}, 192, 1024, 64, 64, 1024, 1024,
       0, 65536, 196608, 32, ZM, 1.f, nullptr, bqkv_f, NEG, POS);
    tg(1, false, {qfh, qfl, qfh + 65536, qfl + 65536, S, nullptr, nullptr}, 1024, 1024, 64, 1024, 1024, 1024,
       196608, 196608, 1048576, 32, ZM, 0.125f, nullptr, nullptr, NEG, POS);
    k_softmax<<<32768, 256>>>(S, Ph, Pl);
    tg(2, true, {qfh + 131072, qfl + 131072, Ph, Pl, outf, nullptr, nullptr}, 64, 1024, 1024, 1024, 1024, 1024,
       196608, 1048576, 65536, 32, ZM, 1.f, nullptr, nullptr, NEG, POS);

    // ---- residual add, depthwise, pointwise
    k_scatter<<<8192, 256>>>();
    k_dw<<<8192, 256>>>(dw_w);
    tg(0, false, {pwh, pwl, t1h, t1l, out, nullptr, nullptr}, 256, 4096, 256, 256, 4096, 4096,
       0, 1048576, 1048576, Bn, ZM, 1.f, b2s, b2h, 0.f, 6.f);
}

// round 8
// speedup vs baseline: 1.0020x; 1.0020x over previous
#include <cuda_runtime.h>
#include <cuda_bf16.h>
#include <math.h>
#include <stdint.h>

#define Bn 8
#define Cn 256
#define Hn 64
#define Wn 64
#define NHn 4
#define HDn 64
#define NTOK 1024
#define KFn 256

typedef __nv_bfloat16 bf;

// ---------------- static scratch ----------------
__device__ bf    g_colh[33554432], g_coll[33554432];
__device__ bf    g_xdh[2097152],  g_xdl[2097152];
__device__ bf    g_qch[6291456],  g_qcl[6291456];
__device__ bf    g_qfh[6291456],  g_qfl[6291456];
__device__ float g_S[33554432];
__device__ bf    g_Ph[33554432],  g_Pl[33554432];
__device__ float g_score[Bn*NHn*NTOK];
__device__ int   g_topk[Bn*NHn*KFn];
__device__ float g_outc[Bn*Cn*1024];
__device__ bf    g_tokh[2097152], g_tokl[2097152];
__device__ float g_outfT[2097152];
__device__ float g_coarse[8388608];
__device__ float g_y0[8388608];
__device__ bf    g_t1h[8388608],  g_t1l[8388608];
__device__ bf    g_wdh[1048576],  g_wdl[1048576];
__device__ bf    g_Wph[1048576],  g_Wpl[1048576];
__device__ bf    g_wqch[12288],   g_wqcl[12288];
__device__ bf    g_wqfh[12288],   g_wqfl[12288];
__device__ bf    g_pwh[65536],    g_pwl[65536];
__device__ float g_bn1sc[Cn], g_bn1sh[Cn], g_bn2sc[Cn], g_bn2sh[Cn];

// ================= helpers =================
__device__ __forceinline__ void ldsm4(uint32_t* r, uint32_t addr) {
    asm volatile("ldmatrix.sync.aligned.m8n8.x4.shared.b16 {%0,%1,%2,%3}, [%4];"
                 : "=r"(r[0]), "=r"(r[1]), "=r"(r[2]), "=r"(r[3]) : "r"(addr));
}
__device__ __forceinline__ void ldsm4t(uint32_t* r, uint32_t addr) {
    asm volatile("ldmatrix.sync.aligned.m8n8.x4.trans.shared.b16 {%0,%1,%2,%3}, [%4];"
                 : "=r"(r[0]), "=r"(r[1]), "=r"(r[2]), "=r"(r[3]) : "r"(addr));
}
__device__ __forceinline__ void mma16816(float* d, const uint32_t* a, const uint32_t* b) {
    asm volatile("mma.sync.aligned.m16n8k16.row.col.f32.bf16.bf16.f32 "
                 "{%0,%1,%2,%3},{%4,%5,%6,%7},{%8,%9},{%0,%1,%2,%3};"
                 : "+f"(d[0]), "+f"(d[1]), "+f"(d[2]), "+f"(d[3])
                 : "r"(a[0]), "r"(a[1]), "r"(a[2]), "r"(a[3]), "r"(b[0]), "r"(b[1]));
}
__device__ __forceinline__ void cpa16(uint32_t dst, const void* src) {
    asm volatile("cp.async.cg.shared.global [%0], [%1], 16;" :: "r"(dst), "l"(src));
}
#define CP_COMMIT() asm volatile("cp.async.commit_group;" ::: "memory")
#define CP_WAIT0()  asm volatile("cp.async.wait_group 0;" ::: "memory")

__device__ __forceinline__ uint32_t packbf2(float a, float b) {
    __nv_bfloat162 t;
    t.x = __float2bfloat16_rn(a); t.y = __float2bfloat16_rn(b);
    return *(uint32_t*)&t;
}
__device__ __forceinline__ void split4(float4 f, uint2& hv, uint2& lv) {
    float hx = __bfloat162float(__float2bfloat16_rn(f.x));
    float hy = __bfloat162float(__float2bfloat16_rn(f.y));
    float hz = __bfloat162float(__float2bfloat16_rn(f.z));
    float hw = __bfloat162float(__float2bfloat16_rn(f.w));
    hv.x = packbf2(f.x, f.y);           hv.y = packbf2(f.z, f.w);
    lv.x = packbf2(f.x - hx, f.y - hy); lv.y = packbf2(f.z - hz, f.w - hw);
}
__device__ __forceinline__ void split1(float a, bf* oh, bf* ol) {
    bf h = __float2bfloat16_rn(a);
    *oh = h;
    *ol = __float2bfloat16_rn(a - __bfloat162float(h));
}

// ================= HMMA GEMM =================
// IUP: epilogue scatters interleaved into g_coarse and g_y0 (up-conv mode).
template<bool ATR, bool BKN, bool M64T, bool IUP>
__global__ __launch_bounds__(256, M64T ? 4 : 3) void hgemm(
    const bf* __restrict__ Agh, const bf* __restrict__ Agl,
    const bf* __restrict__ Bgh, const bf* __restrict__ Bgl,
    float* __restrict__ Cf, float* __restrict__ Cf2,
    bf* __restrict__ Ch, bf* __restrict__ Cl,
    int M, int N, int K, int lda, int ldb, int ldc,
    long long sA, long long sB, long long sC, int zamask,
    float alpha, const float* __restrict__ rowScale, const float* __restrict__ rowShift,
    float lo, float hi)
{
    constexpr int MT    = M64T ? 64 : 128;
    constexpr int NFP   = M64T ? 2 : 4;
    constexpr int NWS   = M64T ? 32 : 64;
    constexpr int ASLOT = ATR ? 8704 : MT * 80;
    constexpr int BSLOT = BKN ? 8704 : 10240;
    constexpr int STG   = 2 * (ASLOT + BSLOT);
    extern __shared__ char sm[];
    const uint32_t smb = (uint32_t)__cvta_generic_to_shared(sm);
    const int tid = threadIdx.x;
    const int wid = tid >> 5, lane = tid & 31;
    const int grp = lane >> 2, tig = lane & 3;
    const int z = blockIdx.z;
    const int za = z & zamask;
    Agh += (size_t)za * sA; Agl += (size_t)za * sA;
    Bgh += (size_t)z * sB;  Bgl += (size_t)z * sB;
    if (!IUP && Cf) Cf += (size_t)z * sC;
    if (Ch) { Ch += (size_t)z * sC; Cl += (size_t)z * sC; }
    const int m0 = blockIdx.y * MT, n0 = blockIdx.x * 128;
    const int mw = M64T ? (wid >> 2) : (wid >> 1);
    const int nw = M64T ? (wid & 3) : (wid & 1);

    float acc[2][2*NFP][4];
    #pragma unroll
    for (int i = 0; i < 2; i++)
        #pragma unroll
        for (int j = 0; j < 2*NFP; j++)
            #pragma unroll
            for (int q = 0; q < 4; q++) acc[i][j][q] = 0.f;

    const int nch = K >> 5;

    auto stage_copy = [&](int c, int s) {
        const int k0 = c << 5;
        const uint32_t Ab = smb + s * STG;
        const uint32_t Bb = Ab + 2 * ASLOT;
        #pragma unroll
        for (int p = 0; p < ((!ATR && M64T) ? 1 : 2); p++) {
            int id = tid + (p << 8);
            if (!ATR) {
                int m = id >> 2, part = id & 3;
                size_t off = (size_t)(m0 + m) * lda + k0 + part * 8;
                uint32_t d = Ab + m * 80 + part * 16;
                cpa16(d, Agh + off);
                cpa16(d + ASLOT, Agl + off);
            } else {
                int k = id >> 4, part = id & 15;
                size_t off = (size_t)(k0 + k) * lda + m0 + part * 8;
                uint32_t d = Ab + k * 272 + part * 16;
                cpa16(d, Agh + off);
                cpa16(d + ASLOT, Agl + off);
            }
        }
        #pragma unroll
        for (int p = 0; p < 2; p++) {
            int id = tid + (p << 8);
            if (BKN) {
                int k = id >> 4, part = id & 15;
                size_t off = (size_t)(k0 + k) * ldb + n0 + part * 8;
                uint32_t d = Bb + k * 272 + part * 16;
                cpa16(d, Bgh + off);
                cpa16(d + BSLOT, Bgl + off);
            } else {
                int n = id >> 2, part = id & 3;
                size_t off = (size_t)(n0 + n) * ldb + k0 + part * 8;
                uint32_t d = Bb + n * 80 + part * 16;
                cpa16(d, Bgh + off);
                cpa16(d + BSLOT, Bgl + off);
            }
        }
    };

    auto compute = [&](int s) {
        const uint32_t Ab = smb + s * STG;
        const uint32_t Bb = Ab + 2 * ASLOT;
        const int i = lane >> 3;
        #pragma unroll
        for (int kk = 0; kk < 32; kk += 16) {
            uint32_t ah[2][4], al[2][4];
            #pragma unroll
            for (int mf = 0; mf < 2; mf++) {
                uint32_t addr;
                if (!ATR) {
                    addr = Ab + (uint32_t)((mw * 32 + mf * 16 + (lane & 15)) * 80 + (kk + (lane >> 4) * 8) * 2);
                    ldsm4(ah[mf], addr); ldsm4(al[mf], addr + ASLOT);
                } else {
                    addr = Ab + (uint32_t)((kk + (i >> 1) * 8 + (lane & 7)) * 272 + (mw * 32 + mf * 16 + (i & 1) * 8) * 2);
                    ldsm4t(ah[mf], addr); ldsm4t(al[mf], addr + ASLOT);
                }
            }
            uint32_t bh[NFP][4], bl[NFP][4];
            #pragma unroll
            for (int nfp = 0; nfp < NFP; nfp++) {
                uint32_t addr;
                if (BKN) {
                    addr = Bb + (uint32_t)((kk + (i & 1) * 8 + (lane & 7)) * 272 + (nw * NWS + nfp * 16 + (i >> 1) * 8) * 2);
                    ldsm4t(bh[nfp], addr); ldsm4t(bl[nfp], addr + BSLOT);
                } else {
                    addr = Bb + (uint32_t)((nw * NWS + nfp * 16 + (i >> 1) * 8 + (lane & 7)) * 80 + (kk + (i & 1) * 8) * 2);
                    ldsm4(bh[nfp], addr); ldsm4(bl[nfp], addr + BSLOT);
                }
            }
            #pragma unroll
            for (int pass = 0; pass < 3; pass++) {
                #pragma unroll
                for (int nfp = 0; nfp < NFP; nfp++) {
                    #pragma unroll
                    for (int mf = 0; mf < 2; mf++) {
                        #pragma unroll
                        for (int h = 0; h < 2; h++) {
                            const uint32_t* a = (pass == 2) ? al[mf] : ah[mf];
                            const uint32_t* b = ((pass == 1) ? bl[nfp] : bh[nfp]) + h * 2;
                            mma16816(acc[mf][nfp * 2 + h], a, b);
                        }
                    }
                }
            }
        }
    };

    stage_copy(0, 0); CP_COMMIT();
    for (int c = 0; c < nch; c++) {
        CP_WAIT0();
        __syncthreads();
        if (c + 1 < nch) { stage_copy(c + 1, (c + 1) & 1); CP_COMMIT(); }
        compute(c & 1);
    }
    __syncthreads();

    // ---- epilogue ----
    float* stg = (float*)sm;   // [MT][132]
    #pragma unroll
    for (int mf = 0; mf < 2; mf++) {
        int r0 = mw * 32 + mf * 16 + grp;
        float av0 = alpha, av1 = alpha, sh0 = 0.f, sh1 = 0.f;
        if (rowScale) { av0 *= rowScale[m0 + r0]; av1 *= rowScale[m0 + r0 + 8]; }
        if (rowShift) { sh0 = rowShift[m0 + r0]; sh1 = rowShift[m0 + r0 + 8]; }
        #pragma unroll
        for (int nf = 0; nf < 2*NFP; nf++) {
            int cb = nw * NWS + nf * 8 + tig * 2;
            float* d = acc[mf][nf];
            stg[r0 * 132 + cb]           = fminf(fmaxf(d[0] * av0 + sh0, lo), hi);
            stg[r0 * 132 + cb + 1]       = fminf(fmaxf(d[1] * av0 + sh0, lo), hi);
            stg[(r0 + 8) * 132 + cb]     = fminf(fmaxf(d[2] * av1 + sh1, lo), hi);
            stg[(r0 + 8) * 132 + cb + 1] = fminf(fmaxf(d[3] * av1 + sh1, lo), hi);
        }
    }
    __syncthreads();
    if (IUP) {
        // scatter interleaved: z = b*4 + (py*2+px)
        const int px = z & 1, py = (z >> 1) & 1, zb = z >> 2;
        #pragma unroll
        for (int it = 0; it < MT/8; it++) {
            int lin = tid + (it << 8);
            int rr = lin >> 5, c4 = (lin & 31) << 2;
            float4 v = *(float4*)&stg[rr * 132 + c4];
            int m = m0 + rr;
            int n = n0 + c4;
            int a = n >> 5, cc = n & 31;
            size_t base = ((size_t)zb * Cn + m) * 4096 + (size_t)(2*a + py) * 64 + 2*cc + px;
            Cf[base]     = v.x;  Cf2[base]     = v.x;
            Cf[base + 2] = v.y;  Cf2[base + 2] = v.y;
            Cf[base + 4] = v.z;  Cf2[base + 4] = v.z;
            Cf[base + 6] = v.w;  Cf2[base + 6] = v.w;
        }
    } else if (Cf) {
        #pragma unroll
        for (int it = 0; it < MT/8; it++) {
            int lin = tid + (it << 8);
            int rr = lin >> 5, c4 = (lin & 31) << 2;
            *(float4*)(Cf + (size_t)(m0 + rr) * ldc + n0 + c4) = *(float4*)&stg[rr * 132 + c4];
        }
    } else {
        #pragma unroll
        for (int it = 0; it < MT/8; it++) {
            int lin = tid + (it << 8);
            int rr = lin >> 5, c4 = (lin & 31) << 2;
            float4 v = *(float4*)&stg[rr * 132 + c4];
            uint2 hv, lv;
            split4(v, hv, lv);
            size_t o = (size_t)(m0 + rr) * ldc + n0 + c4;
            *(uint2*)(Ch + o) = hv;
            *(uint2*)(Cl + o) = lv;
        }
    }
}

// ---------------- fused weight prep ----------------
#define PREP_O2 1048576
#define PREP_O3 1060864
#define PREP_O4 1073152
#define PREP_O5 1138688
#define PREP_O6 2187264
#define PREP_END 2187776
__global__ void k_prep_all(const float* __restrict__ down_w,
                           const float* __restrict__ wqkv_c, const float* __restrict__ wqkv_f,
                           const float* __restrict__ pw_w,   const float* __restrict__ up_w,
                           const float* __restrict__ bn1_g, const float* __restrict__ bn1_b,
                           const float* __restrict__ bn1_m, const float* __restrict__ bn1_v,
                           const float* __restrict__ bn2_g, const float* __restrict__ bn2_b,
                           const float* __restrict__ bn2_m, const float* __restrict__ bn2_v) {
    int idx = blockIdx.x * 256 + threadIdx.x;
    if (idx < PREP_O2) {
        split1(down_w[idx], g_wdh + idx, g_wdl + idx);
    } else if (idx < PREP_O3) {
        int i = idx - PREP_O2;
        int m = i / 64, k = i % 64;
        split1(wqkv_c[k * 192 + m], g_wqch + i, g_wqcl + i);
    } else if (idx < PREP_O4) {
        int i = idx - PREP_O3;
        int m = i / 64, k = i % 64;
        split1(wqkv_f[k * 192 + m], g_wqfh + i, g_wqfl + i);
    } else if (idx < PREP_O5) {
        int i = idx - PREP_O4;
        split1(pw_w[i], g_pwh + i, g_pwl + i);
    } else if (idx < PREP_O6) {
        int i = idx - PREP_O5;
        int k = i & 1023, co = (i >> 10) & 255, p = i >> 18;
        int tj = k & 1, ti = (k >> 1) & 1, ci = k >> 2;
        int px = p & 1, py = p >> 1;
        int kh = (py == 0) ? (ti == 0 ? 1 : 3) : (ti == 0 ? 0 : 2);
        int kw = (px == 0) ? (tj == 0 ? 1 : 3) : (tj == 0 ? 0 : 2);
        split1(up_w[((ci << 8) + co) * 16 + kh*4 + kw], g_Wph + i, g_Wpl + i);
    } else if (idx < PREP_END) {
        int i = idx - PREP_O6;
        int c = i & 255;
        if (i < 256) {
            float inv = bn1_g[c] / sqrtf(bn1_v[c] + 1e-5f);
            g_bn1sc[c] = inv;
            g_bn1sh[c] = bn1_b[c] - bn1_m[c] * inv;
        } else {
            float inv = bn2_g[c] / sqrtf(bn2_v[c] + 1e-5f);
            g_bn2sc[c] = inv;
            g_bn2sh[c] = bn2_b[c] - bn2_m[c] * inv;
        }
    }
}

// ---------------- elementwise kernels ----------------
__global__ void k_im2col_down(const float* __restrict__ x) {
    int idx = blockIdx.x * 256 + threadIdx.x;
    int q  = idx & 255;
    int k  = (idx >> 8) & 4095;
    int b  = idx >> 20;
    int kw = k & 3, kh = (k >> 2) & 3, ci = k >> 4;
    int ow0 = (q & 7) << 2, oh = q >> 3;
    int ih = oh*2 - 1 + kh;
    const float* xr = x + ((long long)b*Cn + ci)*(Hn*Wn) + ih*Wn;
    float4 r;
    float* rp = (float*)&r;
    #pragma unroll
    for (int j = 0; j < 4; j++) {
        int iw = (ow0 + j)*2 - 1 + kw;
        rp[j] = (ih >= 0 && ih < Hn && iw >= 0 && iw < Wn) ? xr[iw] : 0.f;
    }
    uint2 hv, lv; split4(r, hv, lv);
    size_t o = ((size_t)idx) << 2;
    *(uint2*)&g_colh[o] = hv;
    *(uint2*)&g_coll[o] = lv;
}

__global__ void k_im2col_up() {
    int idx = blockIdx.x * 256 + threadIdx.x;
    int q = idx & 255;
    int k = (idx >> 8) & 1023;
    int s = idx >> 18;
    int tj = k & 1, ti = (k >> 1) & 1, ci = k >> 2;
    int px = s & 1, py = (s >> 1) & 1, b = s >> 2;
    int c0 = (q & 7) << 2, a = q >> 3;
    int iy = (py == 0) ? (ti == 0 ? a : a - 1) : (ti == 0 ? a + 1 : a);
    int dx = (px == 0) ? (tj == 0 ? 0 : -1) : (tj == 0 ? 1 : 0);
    const float* orow = g_outc + ((long long)b*Cn + ci)*1024 + iy*32;
    float4 r;
    float* rp = (float*)&r;
    bool rowok = (iy >= 0 && iy < 32);
    #pragma unroll
    for (int j = 0; j < 4; j++) {
        int ix = c0 + j + dx;
        rp[j] = (rowok && ix >= 0 && ix < 32) ? orow[ix] : 0.f;
    }
    uint2 hv, lv; split4(r, hv, lv);
    size_t o = ((size_t)idx) << 2;
    *(uint2*)&g_colh[o] = hv;
    *(uint2*)&g_coll[o] = lv;
}

__global__ __launch_bounds__(256) void k_softmax(const float* __restrict__ S,
                                                 bf* __restrict__ Ph, bf* __restrict__ Pl) {
    __shared__ float red[8];
    long long row = blockIdx.x;
    const float* p = S + row * 1024;
    int tid = threadIdx.x;
    float4 v = ((const float4*)p)[tid];
    float mx = fmaxf(fmaxf(v.x, v.y), fmaxf(v.z, v.w));
    #pragma unroll
    for (int o = 16; o; o >>= 1) mx = fmaxf(mx, __shfl_xor_sync(0xffffffffu, mx, o));
    if ((tid & 31) == 0) red[tid >> 5] = mx;
    __syncthreads();
    if (tid == 0) {
        float m = red[0];
        #pragma unroll
        for (int i = 1; i < 8; i++) m = fmaxf(m, red[i]);
        red[0] = m;
    }
    __syncthreads();
    mx = red[0];
    __syncthreads();
    float e0 = __expf(v.x - mx), e1 = __expf(v.y - mx);
    float e2 = __expf(v.z - mx), e3 = __expf(v.w - mx);
    float s = (e0 + e1) + (e2 + e3);
    #pragma unroll
    for (int o = 16; o; o >>= 1) s += __shfl_xor_sync(0xffffffffu, s, o);
    if ((tid & 31) == 0) red[tid >> 5] = s;
    __syncthreads();
    if (tid == 0) {
        float t = 0.f;
        #pragma unroll
        for (int i = 0; i < 8; i++) t += red[i];
        red[0] = t;
    }
    __syncthreads();
    float inv = 1.f / red[0];
    float4 r;
    r.x = e0 * inv; r.y = e1 * inv; r.z = e2 * inv; r.w = e3 * inv;
    uint2 hv, lv; split4(r, hv, lv);
    size_t o = row * 1024 + (size_t)tid * 4;
    *(uint2*)(Ph + o) = hv;
    *(uint2*)(Pl + o) = lv;
}

__global__ void k_colsum() {
    int z = blockIdx.x >> 1;
    int m2 = ((blockIdx.x & 1) << 8) + threadIdx.x;
    const uint32_t* ph = (const uint32_t*)(g_Ph + (long long)z * 1048576) + m2;
    const uint32_t* pl = (const uint32_t*)(g_Pl + (long long)z * 1048576) + m2;
    float s0 = 0.f, s1 = 0.f;
    #pragma unroll 8
    for (int n = 0; n < 1024; n++) {
        long long o = (long long)n << 9;
        __nv_bfloat162 h = *(const __nv_bfloat162*)&ph[o];
        __nv_bfloat162 l = *(const __nv_bfloat162*)&pl[o];
        s0 += __bfloat162float(h.x) + __bfloat162float(l.x);
        s1 += __bfloat162float(h.y) + __bfloat162float(l.y);
    }
    g_score[z * 1024 + m2 * 2]     = s0;
    g_score[z * 1024 + m2 * 2 + 1] = s1;
}

__global__ __launch_bounds__(512) void k_topk() {
    __shared__ float v[1024];
    __shared__ int   ix[1024];
    int z = blockIdx.x, tid = threadIdx.x;
    for (int i = tid; i < 1024; i += 512) { v[i] = g_score[z*1024 + i]; ix[i] = i; }
    __syncthreads();
    for (int k = 2; k <= 1024; k <<= 1) {
        for (int j = k >> 1; j > 0; j >>= 1) {
            for (int i = tid; i < 1024; i += 512) {
                int l = i ^ j;
                if (l > i) {
                    bool up = ((i & k) == 0);
                    bool sw = up ? (v[i] < v[l]) : (v[i] > v[l]);
                    if (sw) {
                        float tv = v[i]; v[i] = v[l]; v[l] = tv;
                        int ti2 = ix[i]; ix[i] = ix[l]; ix[l] = ti2;
                    }
                }
            }
            __syncthreads();
        }
    }
    for (int i = tid; i < KFn; i += 512) g_topk[z*KFn + i] = ix[i];
}

__global__ void k_gather_fine() {
    int idx = blockIdx.x * 256 + threadIdx.x;
    int t = idx & 1023, d = (idx >> 10) & 63, z = idx >> 16;
    int ki = t >> 2, i = (t >> 1) & 1, j = t & 1;
    int p = g_topk[(z << 8) + ki];
    int pi = p >> 5, pj = p & 31;
    int b = z >> 2, h = z & 3;
    float v = g_coarse[((long long)b*Cn + (h*HDn + d))*4096 + (2*pi + i)*64 + (2*pj + j)];
    split1(v, g_tokh + idx, g_tokl + idx);
}

__global__ void k_scatter() {
    int idx = blockIdx.x * 256 + threadIdx.x;
    int t = idx & 1023, d = (idx >> 10) & 63, z = idx >> 16;
    int ki = t >> 2, i = (t >> 1) & 1, j = t & 1;
    int p = g_topk[(z << 8) + ki];
    int pi = p >> 5, pj = p & 31;
    int b = z >> 2, h = z & 3;
    g_y0[((long long)b*Cn + (h*HDn + d))*4096 + (2*pi + i)*64 + (2*pj + j)] += g_outfT[idx];
}

__global__ void k_dw(const float* __restrict__ dw_w) {
    int idx = blockIdx.x * 256 + threadIdx.x;
    int x4 = (idx & 15) << 2, y = (idx >> 4) & 63, c = (idx >> 10) & 255, b = idx >> 18;
    const float* base = g_y0 + ((long long)b*Cn + c)*4096;
    const float* wp = dw_w + c*9;
    float s[4] = {0.f, 0.f, 0.f, 0.f};
    #pragma unroll
    for (int ky = 0; ky < 3; ky++) {
        int yy = y + ky - 1;
        if (yy < 0 || yy >= 64) continue;
        const float* row = base + yy*64;
        float4 mid = *(const float4*)(row + x4);
        float lft = (x4 > 0)  ? row[x4 - 1] : 0.f;
        float rgt = (x4 < 60) ? row[x4 + 4] : 0.f;
        float w0 = wp[ky*3], w1 = wp[ky*3 + 1], w2 = wp[ky*3 + 2];
        s[0] = fmaf(lft,   w0, fmaf(mid.x, w1, fmaf(mid.y, w2, s[0])));
        s[1] = fmaf(mid.x, w0, fmaf(mid.y, w1, fmaf(mid.z, w2, s[1])));
        s[2] = fmaf(mid.y, w0, fmaf(mid.z, w1, fmaf(mid.w, w2, s[2])));
        s[3] = fmaf(mid.z, w0, fmaf(mid.w, w1, fmaf(rgt,   w2, s[3])));
    }
    float sc = g_bn1sc[c], sh = g_bn1sh[c];
    float4 r;
    r.x = fminf(fmaxf(s[0]*sc + sh, 0.f), 6.f);
    r.y = fminf(fmaxf(s[1]*sc + sh, 0.f), 6.f);
    r.z = fminf(fmaxf(s[2]*sc + sh, 0.f), 6.f);
    r.w = fminf(fmaxf(s[3]*sc + sh, 0.f), 6.f);
    uint2 hv, lv; split4(r, hv, lv);
    size_t o = ((size_t)b*Cn + c)*4096 + y*64 + x4;
    *(uint2*)&g_t1h[o] = hv;
    *(uint2*)&g_t1l[o] = lv;
}

// ---------------- host ----------------
struct GArgs {
    const bf *Ah, *Al, *Bh, *Bl;
    float* Cf; float* Cf2; bf *Ch, *Cl;
};
static inline int smem_for(bool atr, bool bkn, bool m64) {
    int aslot = atr ? 8704 : (m64 ? 64 : 128) * 80;
    int bslot = bkn ? 8704 : 10240;
    int two = 2 * 2 * (aslot + bslot);
    int epi = (m64 ? 64 : 128) * 132 * 4;
    return two > epi ? two : epi;
}
// mode 0: A=MxK,B=KxN ; mode 1: A=KxM,B=KxN ; mode 2: A=MxK,B=NxK ; mode 3: mode0-M64 + IUP epilogue
static void tg(int mode, bool m64, GArgs g,
               int M, int N, int K, int lda, int ldb, int ldc,
               long long sA, long long sB, long long sC, int Z, int zamask,
               float alpha, const float* sc, const float* sh, float lo, float hi)
{
    dim3 grid(N / 128, M / (m64 ? 64 : 128), Z), blk(256);
    if (mode == 3) {
        int shm = smem_for(false, true, true);
        cudaFuncSetAttribute(hgemm<false,true,true,true>, cudaFuncAttributeMaxDynamicSharedMemorySize, shm);
        hgemm<false,true,true,true><<<grid, blk, shm>>>(g.Ah, g.Al, g.Bh, g.Bl, g.Cf, g.Cf2, g.Ch, g.Cl,
            M, N, K, lda, ldb, ldc, sA, sB, sC, zamask, alpha, sc, sh, lo, hi);
    } else if (mode == 0 && !m64) {
        int shm = smem_for(false, true, false);
        cudaFuncSetAttribute(hgemm<false,true,false,false>, cudaFuncAttributeMaxDynamicSharedMemorySize, shm);
        hgemm<false,true,false,false><<<grid, blk, shm>>>(g.Ah, g.Al, g.Bh, g.Bl, g.Cf, g.Cf2, g.Ch, g.Cl,
            M, N, K, lda, ldb, ldc, sA, sB, sC, zamask, alpha, sc, sh, lo, hi);
    } else if (mode == 0 && m64) {
        int shm = smem_for(false, true, true);
        cudaFuncSetAttribute(hgemm<false,true,true,false>, cudaFuncAttributeMaxDynamicSharedMemorySize, shm);
        hgemm<false,true,true,false><<<grid, blk, shm>>>(g.Ah, g.Al, g.Bh, g.Bl, g.Cf, g.Cf2, g.Ch, g.Cl,
            M, N, K, lda, ldb, ldc, sA, sB, sC, zamask, alpha, sc, sh, lo, hi);
    } else if (mode == 1) {
        int shm = smem_for(true, true, false);
        cudaFuncSetAttribute(hgemm<true,true,false,false>, cudaFuncAttributeMaxDynamicSharedMemorySize, shm);
        hgemm<true,true,false,false><<<grid, blk, shm>>>(g.Ah, g.Al, g.Bh, g.Bl, g.Cf, g.Cf2, g.Ch, g.Cl,
            M, N, K, lda, ldb, ldc, sA, sB, sC, zamask, alpha, sc, sh, lo, hi);
    } else {
        int shm = smem_for(false, false, true);
        cudaFuncSetAttribute(hgemm<false,false,true,false>, cudaFuncAttributeMaxDynamicSharedMemorySize, shm);
        hgemm<false,false,true,false><<<grid, blk, shm>>>(g.Ah, g.Al, g.Bh, g.Bl, g.Cf, g.Cf2, g.Ch, g.Cl,
            M, N, K, lda, ldb, ldc, sA, sB, sC, zamask, alpha, sc, sh, lo, hi);
    }
}

extern "C" void kernel_launch(void* const* d_in, const int* in_sizes, int n_in,
                              void* d_out, int out_size)
{
    const float* x      = (const float*)d_in[0];
    const float* down_w = (const float*)d_in[1];
    const float* down_b = (const float*)d_in[2];
    const float* up_w   = (const float*)d_in[3];
    const float* up_b   = (const float*)d_in[4];
    const float* wqkv_c = (const float*)d_in[5];
    const float* bqkv_c = (const float*)d_in[6];
    const float* wqkv_f = (const float*)d_in[7];
    const float* bqkv_f = (const float*)d_in[8];
    const float* dw_w   = (const float*)d_in[9];
    const float* bn1_g  = (const float*)d_in[10];
    const float* bn1_b  = (const float*)d_in[11];
    const float* bn1_m  = (const float*)d_in[12];
    const float* bn1_v  = (const float*)d_in[13];
    const float* pw_w   = (const float*)d_in[14];
    const float* bn2_g  = (const float*)d_in[15];
    const float* bn2_b  = (const float*)d_in[16];
    const float* bn2_m  = (const float*)d_in[17];
    const float* bn2_v  = (const float*)d_in[18];
    float* out = (float*)d_out;

    #define SYM(p, s) cudaGetSymbolAddress((void**)&p, s)
    bf *colh, *coll, *xdh, *xdl, *qch, *qcl, *qfh, *qfl, *Ph, *Pl, *tokh, *tokl;
    bf *t1h, *t1l, *wdh, *wdl, *Wph, *Wpl, *wqch, *wqcl, *wqfh, *wqfl, *pwh, *pwl;
    float *S, *outc, *coarse, *y0, *outf;
    float *b2s, *b2h;
    SYM(colh, g_colh); SYM(coll, g_coll); SYM(xdh, g_xdh); SYM(xdl, g_xdl);
    SYM(qch, g_qch); SYM(qcl, g_qcl); SYM(qfh, g_qfh); SYM(qfl, g_qfl);
    SYM(Ph, g_Ph); SYM(Pl, g_Pl); SYM(tokh, g_tokh); SYM(tokl, g_tokl);
    SYM(t1h, g_t1h); SYM(t1l, g_t1l); SYM(wdh, g_wdh); SYM(wdl, g_wdl);
    SYM(Wph, g_Wph); SYM(Wpl, g_Wpl); SYM(wqch, g_wqch); SYM(wqcl, g_wqcl);
    SYM(wqfh, g_wqfh); SYM(wqfl, g_wqfl); SYM(pwh, g_pwh); SYM(pwl, g_pwl);
    SYM(S, g_S); SYM(outc, g_outc); SYM(coarse, g_coarse); SYM(y0, g_y0);
    SYM(outf, g_outfT);
    SYM(b2s, g_bn2sc); SYM(b2h, g_bn2sh);
    #undef SYM

    const float NEG = -3.0e38f, POS = 3.0e38f;
    const int ZM = 0x7fffffff;

    k_prep_all<<<(PREP_END + 255)/256, 256>>>(down_w, wqkv_c, wqkv_f, pw_w, up_w,
        bn1_g, bn1_b, bn1_m, bn1_v, bn2_g, bn2_b, bn2_m, bn2_v);

    // ---- down conv -> xd planes
    k_im2col_down<<<32768, 256>>>(x);
    tg(0, true, {wdh, wdl, colh, coll, nullptr, nullptr, xdh, xdl}, 256, 1024, 4096, 4096, 1024, 1024,
       0, 4096LL*1024, 256LL*1024, Bn, ZM, 1.f, nullptr, down_b, NEG, POS);

    // ---- coarse QKV
    tg(0, true, {wqch, wqcl, xdh, xdl, nullptr, nullptr, qch, qcl}, 192, 1024, 64, 64, 1024, 1024,
       0, 65536, 196608, 32, ZM, 1.f, nullptr, bqkv_c, NEG, POS);

    // ---- coarse S, softmax, colsum, topk
    tg(1, false, {qch, qcl, qch + 65536, qcl + 65536, S, nullptr, nullptr, nullptr}, 1024, 1024, 64, 1024, 1024, 1024,
       196608, 196608, 1048576, 32, ZM, 0.125f, nullptr, nullptr, NEG, POS);
    k_softmax<<<32768, 256>>>(S, Ph, Pl);
    k_colsum<<<64, 256>>>();
    k_topk<<<32, 512>>>();

    // ---- coarse PV
    tg(2, true, {qch + 131072, qcl + 131072, Ph, Pl, outc, nullptr, nullptr, nullptr}, 64, 1024, 1024, 1024, 1024, 1024,
       196608, 1048576, 65536, 32, ZM, 1.f, nullptr, nullptr, NEG, POS);

    // ---- up conv transpose: fused GEMM with interleaved dual-store epilogue
    k_im2col_up<<<32768, 256>>>();
    tg(3, true, {Wph, Wpl, colh, coll, coarse, y0, nullptr, nullptr}, 256, 1024, 1024, 1024, 1024, 1024,
       262144, 1048576, 0, 32, 3, 1.f, nullptr, up_b, NEG, POS);

    // ---- fine attention
    k_gather_fine<<<8192, 256>>>();
    tg(0, true, {wqfh, wqfl, tokh, tokl, nullptr, nullptr, qfh, qfl}, 192, 1024, 64, 64, 1024, 1024,
       0, 65536, 196608, 32, ZM, 1.f, nullptr, bqkv_f, NEG, POS);
    tg(1, false, {qfh, qfl, qfh + 65536, qfl + 65536, S, nullptr, nullptr, nullptr}, 1024, 1024, 64, 1024, 1024, 1024,
       196608, 196608, 1048576, 32, ZM, 0.125f, nullptr, nullptr, NEG, POS);
    k_softmax<<<32768, 256>>>(S, Ph, Pl);
    tg(2, true, {qfh + 131072, qfl + 131072, Ph, Pl, outf, nullptr, nullptr, nullptr}, 64, 1024, 1024, 1024, 1024, 1024,
       196608, 1048576, 65536, 32, ZM, 1.f, nullptr, nullptr, NEG, POS);

    // ---- residual add, depthwise, pointwise
    k_scatter<<<8192, 256>>>();
    k_dw<<<8192, 256>>>(dw_w);
    tg(0, true, {pwh, pwl, t1h, t1l, out, nullptr, nullptr, nullptr}, 256, 4096, 256, 256, 4096, 4096,
       0, 1048576, 1048576, Bn, ZM, 1.f, b2s, b2h, 0.f, 6.f);
}

// round 9
// speedup vs baseline: 1.2032x; 1.2008x over previous
#include <cuda_runtime.h>
#include <cuda_bf16.h>
#include <cuda_fp16.h>
#include <math.h>
#include <stdint.h>

#define Bn 8
#define Cn 256
#define Hn 64
#define Wn 64
#define NHn 4
#define HDn 64
#define NTOK 1024
#define KFn 256

typedef __nv_bfloat16 bf;

// ---------------- static scratch (2-byte plane buffers hold bf16 or fp16 bits) ----------------
__device__ uint16_t g_colh[33554432], g_coll[33554432];
__device__ uint16_t g_xdh[2097152],  g_xdl[2097152];
__device__ uint16_t g_qch[6291456],  g_qcl[6291456];
__device__ uint16_t g_qfh[6291456];
__device__ float    g_S[33554432];
__device__ uint16_t g_Ph[33554432],  g_Pl[33554432];
__device__ float    g_score[Bn*NHn*NTOK];
__device__ int      g_topk[Bn*NHn*KFn];
__device__ float    g_outc[Bn*Cn*1024];
__device__ uint16_t g_tokh[2097152];
__device__ float    g_outfT[2097152];
__device__ float    g_coarse[8388608];
__device__ float    g_y0[8388608];
__device__ uint16_t g_t1h[8388608];
__device__ uint16_t g_wdh[1048576],  g_wdl[1048576];
__device__ uint16_t g_Wph[1048576];
__device__ uint16_t g_wqch[12288],   g_wqcl[12288];
__device__ uint16_t g_wqfh[12288];
__device__ uint16_t g_pwh[65536];
__device__ float g_bn1sc[Cn], g_bn1sh[Cn], g_bn2sc[Cn], g_bn2sh[Cn];

// ================= helpers =================
__device__ __forceinline__ void ldsm4(uint32_t* r, uint32_t addr) {
    asm volatile("ldmatrix.sync.aligned.m8n8.x4.shared.b16 {%0,%1,%2,%3}, [%4];"
                 : "=r"(r[0]), "=r"(r[1]), "=r"(r[2]), "=r"(r[3]) : "r"(addr));
}
__device__ __forceinline__ void ldsm4t(uint32_t* r, uint32_t addr) {
    asm volatile("ldmatrix.sync.aligned.m8n8.x4.trans.shared.b16 {%0,%1,%2,%3}, [%4];"
                 : "=r"(r[0]), "=r"(r[1]), "=r"(r[2]), "=r"(r[3]) : "r"(addr));
}
__device__ __forceinline__ void mma_bf(float* d, const uint32_t* a, const uint32_t* b) {
    asm volatile("mma.sync.aligned.m16n8k16.row.col.f32.bf16.bf16.f32 "
                 "{%0,%1,%2,%3},{%4,%5,%6,%7},{%8,%9},{%0,%1,%2,%3};"
                 : "+f"(d[0]), "+f"(d[1]), "+f"(d[2]), "+f"(d[3])
                 : "r"(a[0]), "r"(a[1]), "r"(a[2]), "r"(a[3]), "r"(b[0]), "r"(b[1]));
}
__device__ __forceinline__ void mma_fp(float* d, const uint32_t* a, const uint32_t* b) {
    asm volatile("mma.sync.aligned.m16n8k16.row.col.f32.f16.f16.f32 "
                 "{%0,%1,%2,%3},{%4,%5,%6,%7},{%8,%9},{%0,%1,%2,%3};"
                 : "+f"(d[0]), "+f"(d[1]), "+f"(d[2]), "+f"(d[3])
                 : "r"(a[0]), "r"(a[1]), "r"(a[2]), "r"(a[3]), "r"(b[0]), "r"(b[1]));
}
__device__ __forceinline__ void cpa16(uint32_t dst, const void* src) {
    asm volatile("cp.async.cg.shared.global [%0], [%1], 16;" :: "r"(dst), "l"(src));
}
#define CP_COMMIT() asm volatile("cp.async.commit_group;" ::: "memory")
#define CP_WAIT0()  asm volatile("cp.async.wait_group 0;" ::: "memory")

__device__ __forceinline__ uint32_t packbf2(float a, float b) {
    __nv_bfloat162 t;
    t.x = __float2bfloat16_rn(a); t.y = __float2bfloat16_rn(b);
    return *(uint32_t*)&t;
}
__device__ __forceinline__ uint32_t packh2(float a, float b) {
    __half2 t;
    t.x = __float2half_rn(a); t.y = __float2half_rn(b);
    return *(uint32_t*)&t;
}
__device__ __forceinline__ void split4(float4 f, uint2& hv, uint2& lv) {
    float hx = __bfloat162float(__float2bfloat16_rn(f.x));
    float hy = __bfloat162float(__float2bfloat16_rn(f.y));
    float hz = __bfloat162float(__float2bfloat16_rn(f.z));
    float hw = __bfloat162float(__float2bfloat16_rn(f.w));
    hv.x = packbf2(f.x, f.y);           hv.y = packbf2(f.z, f.w);
    lv.x = packbf2(f.x - hx, f.y - hy); lv.y = packbf2(f.z - hz, f.w - hw);
}
__device__ __forceinline__ void split1(float a, uint16_t* oh, uint16_t* ol) {
    bf h = __float2bfloat16_rn(a);
    *(bf*)oh = h;
    *(bf*)ol = __float2bfloat16_rn(a - __bfloat162float(h));
}
__device__ __forceinline__ void half1(float a, uint16_t* oh) {
    *(__half*)oh = __float2half_rn(a);
}

// ================= HMMA GEMM =================
// F16: single-plane fp16, 1 MMA pass. Otherwise bf16 hi/lo, 3 passes.
// IUP: epilogue scatters interleaved into g_coarse and g_y0.
template<bool ATR, bool BKN, bool M64T, bool IUP, bool F16>
__global__ __launch_bounds__(256, M64T ? 4 : 3) void hgemm(
    const uint16_t* __restrict__ Agh, const uint16_t* __restrict__ Agl,
    const uint16_t* __restrict__ Bgh, const uint16_t* __restrict__ Bgl,
    float* __restrict__ Cf, float* __restrict__ Cf2,
    uint16_t* __restrict__ Ch, uint16_t* __restrict__ Cl,
    int M, int N, int K, int lda, int ldb, int ldc,
    long long sA, long long sB, long long sC, int zamask,
    float alpha, const float* __restrict__ rowScale, const float* __restrict__ rowShift,
    float lo, float hi)
{
    constexpr int MT    = M64T ? 64 : 128;
    constexpr int NFP   = M64T ? 2 : 4;
    constexpr int NWS   = M64T ? 32 : 64;
    constexpr int ASLOT = ATR ? 8704 : MT * 80;
    constexpr int BSLOT = BKN ? 8704 : 10240;
    constexpr int NPL   = F16 ? 1 : 2;
    constexpr int STG   = NPL * (ASLOT + BSLOT);
    extern __shared__ char sm[];
    const uint32_t smb = (uint32_t)__cvta_generic_to_shared(sm);
    const int tid = threadIdx.x;
    const int wid = tid >> 5, lane = tid & 31;
    const int grp = lane >> 2, tig = lane & 3;
    const int z = blockIdx.z;
    const int za = z & zamask;
    Agh += (size_t)za * sA;
    Bgh += (size_t)z * sB;
    if (!F16) { Agl += (size_t)za * sA; Bgl += (size_t)z * sB; }
    if (!IUP && Cf) Cf += (size_t)z * sC;
    if (Ch) { Ch += (size_t)z * sC; if (!F16) Cl += (size_t)z * sC; }
    const int m0 = blockIdx.y * MT, n0 = blockIdx.x * 128;
    const int mw = M64T ? (wid >> 2) : (wid >> 1);
    const int nw = M64T ? (wid & 3) : (wid & 1);

    float acc[2][2*NFP][4];
    #pragma unroll
    for (int i = 0; i < 2; i++)
        #pragma unroll
        for (int j = 0; j < 2*NFP; j++)
            #pragma unroll
            for (int q = 0; q < 4; q++) acc[i][j][q] = 0.f;

    const int nch = K >> 5;

    auto stage_copy = [&](int c, int s) {
        const int k0 = c << 5;
        const uint32_t Ab = smb + s * STG;
        const uint32_t Bb = Ab + NPL * ASLOT;
        #pragma unroll
        for (int p = 0; p < ((!ATR && M64T) ? 1 : 2); p++) {
            int id = tid + (p << 8);
            if (!ATR) {
                int m = id >> 2, part = id & 3;
                size_t off = (size_t)(m0 + m) * lda + k0 + part * 8;
                uint32_t d = Ab + m * 80 + part * 16;
                cpa16(d, Agh + off);
                if (!F16) cpa16(d + ASLOT, Agl + off);
            } else {
                int k = id >> 4, part = id & 15;
                size_t off = (size_t)(k0 + k) * lda + m0 + part * 8;
                uint32_t d = Ab + k * 272 + part * 16;
                cpa16(d, Agh + off);
                if (!F16) cpa16(d + ASLOT, Agl + off);
            }
        }
        #pragma unroll
        for (int p = 0; p < 2; p++) {
            int id = tid + (p << 8);
            if (BKN) {
                int k = id >> 4, part = id & 15;
                size_t off = (size_t)(k0 + k) * ldb + n0 + part * 8;
                uint32_t d = Bb + k * 272 + part * 16;
                cpa16(d, Bgh + off);
                if (!F16) cpa16(d + BSLOT, Bgl + off);
            } else {
                int n = id >> 2, part = id & 3;
                size_t off = (size_t)(n0 + n) * ldb + k0 + part * 8;
                uint32_t d = Bb + n * 80 + part * 16;
                cpa16(d, Bgh + off);
                if (!F16) cpa16(d + BSLOT, Bgl + off);
            }
        }
    };

    auto compute = [&](int s) {
        const uint32_t Ab = smb + s * STG;
        const uint32_t Bb = Ab + NPL * ASLOT;
        const int i = lane >> 3;
        #pragma unroll
        for (int kk = 0; kk < 32; kk += 16) {
            uint32_t ah[2][4], al[2][4];
            #pragma unroll
            for (int mf = 0; mf < 2; mf++) {
                uint32_t addr;
                if (!ATR) {
                    addr = Ab + (uint32_t)((mw * 32 + mf * 16 + (lane & 15)) * 80 + (kk + (lane >> 4) * 8) * 2);
                    ldsm4(ah[mf], addr);
                    if (!F16) ldsm4(al[mf], addr + ASLOT);
                } else {
                    addr = Ab + (uint32_t)((kk + (i >> 1) * 8 + (lane & 7)) * 272 + (mw * 32 + mf * 16 + (i & 1) * 8) * 2);
                    ldsm4t(ah[mf], addr);
                    if (!F16) ldsm4t(al[mf], addr + ASLOT);
                }
            }
            uint32_t bh[NFP][4], bl[NFP][4];
            #pragma unroll
            for (int nfp = 0; nfp < NFP; nfp++) {
                uint32_t addr;
                if (BKN) {
                    addr = Bb + (uint32_t)((kk + (i & 1) * 8 + (lane & 7)) * 272 + (nw * NWS + nfp * 16 + (i >> 1) * 8) * 2);
                    ldsm4t(bh[nfp], addr);
                    if (!F16) ldsm4t(bl[nfp], addr + BSLOT);
                } else {
                    addr = Bb + (uint32_t)((nw * NWS + nfp * 16 + (i >> 1) * 8 + (lane & 7)) * 80 + (kk + (i & 1) * 8) * 2);
                    ldsm4(bh[nfp], addr);
                    if (!F16) ldsm4(bl[nfp], addr + BSLOT);
                }
            }
            #pragma unroll
            for (int pass = 0; pass < (F16 ? 1 : 3); pass++) {
                #pragma unroll
                for (int nfp = 0; nfp < NFP; nfp++) {
                    #pragma unroll
                    for (int mf = 0; mf < 2; mf++) {
                        #pragma unroll
                        for (int h = 0; h < 2; h++) {
                            const uint32_t* a = (pass == 2) ? al[mf] : ah[mf];
                            const uint32_t* b = ((pass == 1) ? bl[nfp] : bh[nfp]) + h * 2;
                            if (F16) mma_fp(acc[mf][nfp * 2 + h], a, b);
                            else     mma_bf(acc[mf][nfp * 2 + h], a, b);
                        }
                    }
                }
            }
        }
    };

    stage_copy(0, 0); CP_COMMIT();
    for (int c = 0; c < nch; c++) {
        CP_WAIT0();
        __syncthreads();
        if (c + 1 < nch) { stage_copy(c + 1, (c + 1) & 1); CP_COMMIT(); }
        compute(c & 1);
    }
    __syncthreads();

    // ---- epilogue ----
    float* stg = (float*)sm;   // [MT][132]
    #pragma unroll
    for (int mf = 0; mf < 2; mf++) {
        int r0 = mw * 32 + mf * 16 + grp;
        float av0 = alpha, av1 = alpha, sh0 = 0.f, sh1 = 0.f;
        if (rowScale) { av0 *= rowScale[m0 + r0]; av1 *= rowScale[m0 + r0 + 8]; }
        if (rowShift) { sh0 = rowShift[m0 + r0]; sh1 = rowShift[m0 + r0 + 8]; }
        #pragma unroll
        for (int nf = 0; nf < 2*NFP; nf++) {
            int cb = nw * NWS + nf * 8 + tig * 2;
            float* d = acc[mf][nf];
            stg[r0 * 132 + cb]           = fminf(fmaxf(d[0] * av0 + sh0, lo), hi);
            stg[r0 * 132 + cb + 1]       = fminf(fmaxf(d[1] * av0 + sh0, lo), hi);
            stg[(r0 + 8) * 132 + cb]     = fminf(fmaxf(d[2] * av1 + sh1, lo), hi);
            stg[(r0 + 8) * 132 + cb + 1] = fminf(fmaxf(d[3] * av1 + sh1, lo), hi);
        }
    }
    __syncthreads();
    if (IUP) {
        const int px = z & 1, py = (z >> 1) & 1, zb = z >> 2;
        #pragma unroll
        for (int it = 0; it < MT/8; it++) {
            int lin = tid + (it << 8);
            int rr = lin >> 5, c4 = (lin & 31) << 2;
            float4 v = *(float4*)&stg[rr * 132 + c4];
            int m = m0 + rr;
            int n = n0 + c4;
            int a = n >> 5, cc = n & 31;
            size_t base = ((size_t)zb * Cn + m) * 4096 + (size_t)(2*a + py) * 64 + 2*cc + px;
            Cf[base]     = v.x;  Cf2[base]     = v.x;
            Cf[base + 2] = v.y;  Cf2[base + 2] = v.y;
            Cf[base + 4] = v.z;  Cf2[base + 4] = v.z;
            Cf[base + 6] = v.w;  Cf2[base + 6] = v.w;
        }
    } else if (Cf) {
        #pragma unroll
        for (int it = 0; it < MT/8; it++) {
            int lin = tid + (it << 8);
            int rr = lin >> 5, c4 = (lin & 31) << 2;
            *(float4*)(Cf + (size_t)(m0 + rr) * ldc + n0 + c4) = *(float4*)&stg[rr * 132 + c4];
        }
    } else {
        #pragma unroll
        for (int it = 0; it < MT/8; it++) {
            int lin = tid + (it << 8);
            int rr = lin >> 5, c4 = (lin & 31) << 2;
            float4 v = *(float4*)&stg[rr * 132 + c4];
            size_t o = (size_t)(m0 + rr) * ldc + n0 + c4;
            if (F16) {
                uint2 hv;
                hv.x = packh2(v.x, v.y); hv.y = packh2(v.z, v.w);
                *(uint2*)(Ch + o) = hv;
            } else {
                uint2 hv, lv;
                split4(v, hv, lv);
                *(uint2*)(Ch + o) = hv;
                *(uint2*)(Cl + o) = lv;
            }
        }
    }
}

// ---------------- fused weight prep ----------------
#define PREP_O2 1048576
#define PREP_O3 1060864
#define PREP_O4 1073152
#define PREP_O5 1138688
#define PREP_O6 2187264
#define PREP_END 2187776
__global__ void k_prep_all(const float* __restrict__ down_w,
                           const float* __restrict__ wqkv_c, const float* __restrict__ wqkv_f,
                           const float* __restrict__ pw_w,   const float* __restrict__ up_w,
                           const float* __restrict__ bn1_g, const float* __restrict__ bn1_b,
                           const float* __restrict__ bn1_m, const float* __restrict__ bn1_v,
                           const float* __restrict__ bn2_g, const float* __restrict__ bn2_b,
                           const float* __restrict__ bn2_m, const float* __restrict__ bn2_v) {
    int idx = blockIdx.x * 256 + threadIdx.x;
    if (idx < PREP_O2) {
        split1(down_w[idx], g_wdh + idx, g_wdl + idx);
    } else if (idx < PREP_O3) {
        int i = idx - PREP_O2;
        int m = i / 64, k = i % 64;
        split1(wqkv_c[k * 192 + m], g_wqch + i, g_wqcl + i);
    } else if (idx < PREP_O4) {
        int i = idx - PREP_O3;
        int m = i / 64, k = i % 64;
        half1(wqkv_f[k * 192 + m], g_wqfh + i);
    } else if (idx < PREP_O5) {
        int i = idx - PREP_O4;
        half1(pw_w[i], g_pwh + i);
    } else if (idx < PREP_O6) {
        int i = idx - PREP_O5;
        int k = i & 1023, co = (i >> 10) & 255, p = i >> 18;
        int tj = k & 1, ti = (k >> 1) & 1, ci = k >> 2;
        int px = p & 1, py = p >> 1;
        int kh = (py == 0) ? (ti == 0 ? 1 : 3) : (ti == 0 ? 0 : 2);
        int kw = (px == 0) ? (tj == 0 ? 1 : 3) : (tj == 0 ? 0 : 2);
        half1(up_w[((ci << 8) + co) * 16 + kh*4 + kw], g_Wph + i);
    } else if (idx < PREP_END) {
        int i = idx - PREP_O6;
        int c = i & 255;
        if (i < 256) {
            float inv = bn1_g[c] / sqrtf(bn1_v[c] + 1e-5f);
            g_bn1sc[c] = inv;
            g_bn1sh[c] = bn1_b[c] - bn1_m[c] * inv;
        } else {
            float inv = bn2_g[c] / sqrtf(bn2_v[c] + 1e-5f);
            g_bn2sc[c] = inv;
            g_bn2sh[c] = bn2_b[c] - bn2_m[c] * inv;
        }
    }
}

// ---------------- elementwise kernels ----------------
__global__ void k_im2col_down(const float* __restrict__ x) {
    int idx = blockIdx.x * 256 + threadIdx.x;
    int q  = idx & 255;
    int k  = (idx >> 8) & 4095;
    int b  = idx >> 20;
    int kw = k & 3, kh = (k >> 2) & 3, ci = k >> 4;
    int ow0 = (q & 7) << 2, oh = q >> 3;
    int ih = oh*2 - 1 + kh;
    const float* xr = x + ((long long)b*Cn + ci)*(Hn*Wn) + ih*Wn;
    float4 r;
    float* rp = (float*)&r;
    #pragma unroll
    for (int j = 0; j < 4; j++) {
        int iw = (ow0 + j)*2 - 1 + kw;
        rp[j] = (ih >= 0 && ih < Hn && iw >= 0 && iw < Wn) ? xr[iw] : 0.f;
    }
    uint2 hv, lv; split4(r, hv, lv);
    size_t o = ((size_t)idx) << 2;
    *(uint2*)&g_colh[o] = hv;
    *(uint2*)&g_coll[o] = lv;
}

// fp16 single-plane output
__global__ void k_im2col_up() {
    int idx = blockIdx.x * 256 + threadIdx.x;
    int q = idx & 255;
    int k = (idx >> 8) & 1023;
    int s = idx >> 18;
    int tj = k & 1, ti = (k >> 1) & 1, ci = k >> 2;
    int px = s & 1, py = (s >> 1) & 1, b = s >> 2;
    int c0 = (q & 7) << 2, a = q >> 3;
    int iy = (py == 0) ? (ti == 0 ? a : a - 1) : (ti == 0 ? a + 1 : a);
    int dx = (px == 0) ? (tj == 0 ? 0 : -1) : (tj == 0 ? 1 : 0);
    const float* orow = g_outc + ((long long)b*Cn + ci)*1024 + iy*32;
    float4 r;
    float* rp = (float*)&r;
    bool rowok = (iy >= 0 && iy < 32);
    #pragma unroll
    for (int j = 0; j < 4; j++) {
        int ix = c0 + j + dx;
        rp[j] = (rowok && ix >= 0 && ix < 32) ? orow[ix] : 0.f;
    }
    uint2 hv;
    hv.x = packh2(r.x, r.y); hv.y = packh2(r.z, r.w);
    *(uint2*)&g_colh[((size_t)idx) << 2] = hv;
}

// f16out=0: bf16 hi/lo planes; f16out=1: fp16 single plane
__global__ __launch_bounds__(256) void k_softmax(const float* __restrict__ S,
                                                 uint16_t* __restrict__ Ph, uint16_t* __restrict__ Pl,
                                                 int f16out) {
    __shared__ float red[8];
    long long row = blockIdx.x;
    const float* p = S + row * 1024;
    int tid = threadIdx.x;
    float4 v = ((const float4*)p)[tid];
    float mx = fmaxf(fmaxf(v.x, v.y), fmaxf(v.z, v.w));
    #pragma unroll
    for (int o = 16; o; o >>= 1) mx = fmaxf(mx, __shfl_xor_sync(0xffffffffu, mx, o));
    if ((tid & 31) == 0) red[tid >> 5] = mx;
    __syncthreads();
    if (tid == 0) {
        float m = red[0];
        #pragma unroll
        for (int i = 1; i < 8; i++) m = fmaxf(m, red[i]);
        red[0] = m;
    }
    __syncthreads();
    mx = red[0];
    __syncthreads();
    float e0 = __expf(v.x - mx), e1 = __expf(v.y - mx);
    float e2 = __expf(v.z - mx), e3 = __expf(v.w - mx);
    float s = (e0 + e1) + (e2 + e3);
    #pragma unroll
    for (int o = 16; o; o >>= 1) s += __shfl_xor_sync(0xffffffffu, s, o);
    if ((tid & 31) == 0) red[tid >> 5] = s;
    __syncthreads();
    if (tid == 0) {
        float t = 0.f;
        #pragma unroll
        for (int i = 0; i < 8; i++) t += red[i];
        red[0] = t;
    }
    __syncthreads();
    float inv = 1.f / red[0];
    float4 r;
    r.x = e0 * inv; r.y = e1 * inv; r.z = e2 * inv; r.w = e3 * inv;
    size_t o = row * 1024 + (size_t)tid * 4;
    if (f16out) {
        uint2 hv;
        hv.x = packh2(r.x, r.y); hv.y = packh2(r.z, r.w);
        *(uint2*)(Ph + o) = hv;
    } else {
        uint2 hv, lv; split4(r, hv, lv);
        *(uint2*)(Ph + o) = hv;
        *(uint2*)(Pl + o) = lv;
    }
}

__global__ void k_colsum() {
    int z = blockIdx.x >> 1;
    int m2 = ((blockIdx.x & 1) << 8) + threadIdx.x;
    const uint32_t* ph = (const uint32_t*)(g_Ph + (long long)z * 1048576) + m2;
    const uint32_t* pl = (const uint32_t*)(g_Pl + (long long)z * 1048576) + m2;
    float s0 = 0.f, s1 = 0.f;
    #pragma unroll 8
    for (int n = 0; n < 1024; n++) {
        long long o = (long long)n << 9;
        __nv_bfloat162 h = *(const __nv_bfloat162*)&ph[o];
        __nv_bfloat162 l = *(const __nv_bfloat162*)&pl[o];
        s0 += __bfloat162float(h.x) + __bfloat162float(l.x);
        s1 += __bfloat162float(h.y) + __bfloat162float(l.y);
    }
    g_score[z * 1024 + m2 * 2]     = s0;
    g_score[z * 1024 + m2 * 2 + 1] = s1;
}

__global__ __launch_bounds__(512) void k_topk() {
    __shared__ float v[1024];
    __shared__ int   ix[1024];
    int z = blockIdx.x, tid = threadIdx.x;
    for (int i = tid; i < 1024; i += 512) { v[i] = g_score[z*1024 + i]; ix[i] = i; }
    __syncthreads();
    for (int k = 2; k <= 1024; k <<= 1) {
        for (int j = k >> 1; j > 0; j >>= 1) {
            for (int i = tid; i < 1024; i += 512) {
                int l = i ^ j;
                if (l > i) {
                    bool up = ((i & k) == 0);
                    bool sw = up ? (v[i] < v[l]) : (v[i] > v[l]);
                    if (sw) {
                        float tv = v[i]; v[i] = v[l]; v[l] = tv;
                        int ti2 = ix[i]; ix[i] = ix[l]; ix[l] = ti2;
                    }
                }
            }
            __syncthreads();
        }
    }
    for (int i = tid; i < KFn; i += 512) g_topk[z*KFn + i] = ix[i];
}

// fp16 single-plane output
__global__ void k_gather_fine() {
    int idx = blockIdx.x * 256 + threadIdx.x;
    int t = idx & 1023, d = (idx >> 10) & 63, z = idx >> 16;
    int ki = t >> 2, i = (t >> 1) & 1, j = t & 1;
    int p = g_topk[(z << 8) + ki];
    int pi = p >> 5, pj = p & 31;
    int b = z >> 2, h = z & 3;
    float v = g_coarse[((long long)b*Cn + (h*HDn + d))*4096 + (2*pi + i)*64 + (2*pj + j)];
    half1(v, g_tokh + idx);
}

__global__ void k_scatter() {
    int idx = blockIdx.x * 256 + threadIdx.x;
    int t = idx & 1023, d = (idx >> 10) & 63, z = idx >> 16;
    int ki = t >> 2, i = (t >> 1) & 1, j = t & 1;
    int p = g_topk[(z << 8) + ki];
    int pi = p >> 5, pj = p & 31;
    int b = z >> 2, h = z & 3;
    g_y0[((long long)b*Cn + (h*HDn + d))*4096 + (2*pi + i)*64 + (2*pj + j)] += g_outfT[idx];
}

// fp16 single-plane output
__global__ void k_dw(const float* __restrict__ dw_w) {
    int idx = blockIdx.x * 256 + threadIdx.x;
    int x4 = (idx & 15) << 2, y = (idx >> 4) & 63, c = (idx >> 10) & 255, b = idx >> 18;
    const float* base = g_y0 + ((long long)b*Cn + c)*4096;
    const float* wp = dw_w + c*9;
    float s[4] = {0.f, 0.f, 0.f, 0.f};
    #pragma unroll
    for (int ky = 0; ky < 3; ky++) {
        int yy = y + ky - 1;
        if (yy < 0 || yy >= 64) continue;
        const float* row = base + yy*64;
        float4 mid = *(const float4*)(row + x4);
        float lft = (x4 > 0)  ? row[x4 - 1] : 0.f;
        float rgt = (x4 < 60) ? row[x4 + 4] : 0.f;
        float w0 = wp[ky*3], w1 = wp[ky*3 + 1], w2 = wp[ky*3 + 2];
        s[0] = fmaf(lft,   w0, fmaf(mid.x, w1, fmaf(mid.y, w2, s[0])));
        s[1] = fmaf(mid.x, w0, fmaf(mid.y, w1, fmaf(mid.z, w2, s[1])));
        s[2] = fmaf(mid.y, w0, fmaf(mid.z, w1, fmaf(mid.w, w2, s[2])));
        s[3] = fmaf(mid.z, w0, fmaf(mid.w, w1, fmaf(rgt,   w2, s[3])));
    }
    float sc = g_bn1sc[c], sh = g_bn1sh[c];
    float r0 = fminf(fmaxf(s[0]*sc + sh, 0.f), 6.f);
    float r1 = fminf(fmaxf(s[1]*sc + sh, 0.f), 6.f);
    float r2 = fminf(fmaxf(s[2]*sc + sh, 0.f), 6.f);
    float r3 = fminf(fmaxf(s[3]*sc + sh, 0.f), 6.f);
    uint2 hv;
    hv.x = packh2(r0, r1); hv.y = packh2(r2, r3);
    *(uint2*)&g_t1h[((size_t)b*Cn + c)*4096 + y*64 + x4] = hv;
}

// ---------------- host ----------------
struct GArgs {
    const uint16_t *Ah, *Al, *Bh, *Bl;
    float* Cf; float* Cf2; uint16_t *Ch, *Cl;
};
static inline int smem_for(bool atr, bool bkn, bool m64, bool f16) {
    int aslot = atr ? 8704 : (m64 ? 64 : 128) * 80;
    int bslot = bkn ? 8704 : 10240;
    int npl = f16 ? 1 : 2;
    int two = 2 * npl * (aslot + bslot);
    int epi = (m64 ? 64 : 128) * 132 * 4;
    return two > epi ? two : epi;
}

template<bool ATR, bool BKN, bool M64T, bool IUP, bool F16>
static void launch_hgemm(dim3 grid, GArgs g,
                         int M, int N, int K, int lda, int ldb, int ldc,
                         long long sA, long long sB, long long sC, int zamask,
                         float alpha, const float* sc, const float* sh, float lo, float hi) {
    int shm = smem_for(ATR, BKN, M64T, F16);
    cudaFuncSetAttribute(hgemm<ATR,BKN,M64T,IUP,F16>, cudaFuncAttributeMaxDynamicSharedMemorySize, shm);
    hgemm<ATR,BKN,M64T,IUP,F16><<<grid, 256, shm>>>(g.Ah, g.Al, g.Bh, g.Bl, g.Cf, g.Cf2, g.Ch, g.Cl,
        M, N, K, lda, ldb, ldc, sA, sB, sC, zamask, alpha, sc, sh, lo, hi);
}

extern "C" void kernel_launch(void* const* d_in, const int* in_sizes, int n_in,
                              void* d_out, int out_size)
{
    const float* x      = (const float*)d_in[0];
    const float* down_w = (const float*)d_in[1];
    const float* down_b = (const float*)d_in[2];
    const float* up_w   = (const float*)d_in[3];
    const float* up_b   = (const float*)d_in[4];
    const float* wqkv_c = (const float*)d_in[5];
    const float* bqkv_c = (const float*)d_in[6];
    const float* wqkv_f = (const float*)d_in[7];
    const float* bqkv_f = (const float*)d_in[8];
    const float* dw_w   = (const float*)d_in[9];
    const float* bn1_g  = (const float*)d_in[10];
    const float* bn1_b  = (const float*)d_in[11];
    const float* bn1_m  = (const float*)d_in[12];
    const float* bn1_v  = (const float*)d_in[13];
    const float* pw_w   = (const float*)d_in[14];
    const float* bn2_g  = (const float*)d_in[15];
    const float* bn2_b  = (const float*)d_in[16];
    const float* bn2_m  = (const float*)d_in[17];
    const float* bn2_v  = (const float*)d_in[18];
    float* out = (float*)d_out;

    #define SYM(p, s) cudaGetSymbolAddress((void**)&p, s)
    uint16_t *colh, *coll, *xdh, *xdl, *qch, *qcl, *qfh, *Ph, *Pl, *tokh;
    uint16_t *t1h, *wdh, *wdl, *Wph, *wqch, *wqcl, *wqfh, *pwh;
    float *S, *outc, *coarse, *y0, *outf;
    float *b2s, *b2h;
    SYM(colh, g_colh); SYM(coll, g_coll); SYM(xdh, g_xdh); SYM(xdl, g_xdl);
    SYM(qch, g_qch); SYM(qcl, g_qcl); SYM(qfh, g_qfh);
    SYM(Ph, g_Ph); SYM(Pl, g_Pl); SYM(tokh, g_tokh);
    SYM(t1h, g_t1h); SYM(wdh, g_wdh); SYM(wdl, g_wdl);
    SYM(Wph, g_Wph); SYM(wqch, g_wqch); SYM(wqcl, g_wqcl);
    SYM(wqfh, g_wqfh); SYM(pwh, g_pwh);
    SYM(S, g_S); SYM(outc, g_outc); SYM(coarse, g_coarse); SYM(y0, g_y0);
    SYM(outf, g_outfT);
    SYM(b2s, g_bn2sc); SYM(b2h, g_bn2sh);
    #undef SYM

    const float NEG = -3.0e38f, POS = 3.0e38f;
    const int ZM = 0x7fffffff;

    k_prep_all<<<(PREP_END + 255)/256, 256>>>(down_w, wqkv_c, wqkv_f, pw_w, up_w,
        bn1_g, bn1_b, bn1_m, bn1_v, bn2_g, bn2_b, bn2_m, bn2_v);

    // ---- down conv -> xd planes (bf16 3-pass)
    k_im2col_down<<<32768, 256>>>(x);
    launch_hgemm<false,true,true,false,false>(dim3(8,4,Bn),
        {wdh, wdl, colh, coll, nullptr, nullptr, xdh, xdl}, 256, 1024, 4096, 4096, 1024, 1024,
        0, 4096LL*1024, 256LL*1024, ZM, 1.f, nullptr, down_b, NEG, POS);

    // ---- coarse QKV (bf16 3-pass)
    launch_hgemm<false,true,true,false,false>(dim3(8,3,32),
        {wqch, wqcl, xdh, xdl, nullptr, nullptr, qch, qcl}, 192, 1024, 64, 64, 1024, 1024,
        0, 65536, 196608, ZM, 1.f, nullptr, bqkv_c, NEG, POS);

    // ---- coarse S (bf16 3-pass), softmax (bf16 planes), colsum, topk
    launch_hgemm<true,true,false,false,false>(dim3(8,8,32),
        {qch, qcl, qch + 65536, qcl + 65536, S, nullptr, nullptr, nullptr}, 1024, 1024, 64, 1024, 1024, 1024,
        196608, 196608, 1048576, ZM, 0.125f, nullptr, nullptr, NEG, POS);
    k_softmax<<<32768, 256>>>(S, Ph, Pl, 0);
    k_colsum<<<64, 256>>>();
    k_topk<<<32, 512>>>();

    // ---- coarse PV (bf16 3-pass)
    launch_hgemm<false,false,true,false,false>(dim3(8,1,32),
        {qch + 131072, qcl + 131072, Ph, Pl, outc, nullptr, nullptr, nullptr}, 64, 1024, 1024, 1024, 1024, 1024,
        196608, 1048576, 65536, ZM, 1.f, nullptr, nullptr, NEG, POS);

    // ---- up conv transpose: fused fp16 GEMM + interleaved dual store
    k_im2col_up<<<32768, 256>>>();
    launch_hgemm<false,true,true,true,true>(dim3(8,4,32),
        {Wph, nullptr, colh, nullptr, coarse, y0, nullptr, nullptr}, 256, 1024, 1024, 1024, 1024, 1024,
        262144, 1048576, 0, 3, 1.f, nullptr, up_b, NEG, POS);

    // ---- fine attention (fp16 single-pass)
    k_gather_fine<<<8192, 256>>>();
    launch_hgemm<false,true,true,false,true>(dim3(8,3,32),
        {wqfh, nullptr, tokh, nullptr, nullptr, nullptr, qfh, nullptr}, 192, 1024, 64, 64, 1024, 1024,
        0, 65536, 196608, ZM, 1.f, nullptr, bqkv_f, NEG, POS);
    launch_hgemm<true,true,false,false,true>(dim3(8,8,32),
        {qfh, nullptr, qfh + 65536, nullptr, S, nullptr, nullptr, nullptr}, 1024, 1024, 64, 1024, 1024, 1024,
        196608, 196608, 1048576, ZM, 0.125f, nullptr, nullptr, NEG, POS);
    k_softmax<<<32768, 256>>>(S, Ph, Pl, 1);
    launch_hgemm<false,false,true,false,true>(dim3(8,1,32),
        {qfh + 131072, nullptr, Ph, nullptr, outf, nullptr, nullptr, nullptr}, 64, 1024, 1024, 1024, 1024, 1024,
        196608, 1048576, 65536, ZM, 1.f, nullptr, nullptr, NEG, POS);

    // ---- residual add, depthwise, pointwise (fp16 single-pass)
    k_scatter<<<8192, 256>>>();
    k_dw<<<8192, 256>>>(dw_w);
    launch_hgemm<false,true,true,false,true>(dim3(32,4,Bn),
        {pwh, nullptr, t1h, nullptr, out, nullptr, nullptr, nullptr}, 256, 4096, 256, 256, 4096, 4096,
        0, 1048576, 1048576, ZM, 1.f, b2s, b2h, 0.f, 6.f);
}

// round 10
// speedup vs baseline: 1.2084x; 1.0043x over previous
#include <cuda_runtime.h>
#include <cuda_bf16.h>
#include <cuda_fp16.h>
#include <math.h>
#include <stdint.h>

#define Bn 8
#define Cn 256
#define Hn 64
#define Wn 64
#define NHn 4
#define HDn 64
#define NTOK 1024
#define KFn 256

typedef __nv_bfloat16 bf;

// ---------------- static scratch (2-byte plane buffers hold bf16 or fp16 bits) ----------------
__device__ uint16_t g_colh[33554432], g_coll[33554432];
__device__ uint16_t g_xdh[2097152],  g_xdl[2097152];
__device__ uint16_t g_qch[6291456],  g_qcl[6291456];
__device__ uint16_t g_qfh[6291456];
__device__ float    g_S[33554432];
__device__ uint16_t g_Ph[33554432],  g_Pl[33554432];
__device__ float    g_score[Bn*NHn*NTOK];
__device__ int      g_topk[Bn*NHn*KFn];
__device__ float    g_outc[Bn*Cn*1024];
__device__ uint16_t g_tokh[2097152];
__device__ float    g_outfT[2097152];
__device__ float    g_coarse[8388608];
__device__ float    g_y0[8388608];
__device__ uint16_t g_t1h[8388608];
__device__ uint16_t g_wdh[1048576],  g_wdl[1048576];
__device__ uint16_t g_Wph[1048576];
__device__ uint16_t g_wqch[12288],   g_wqcl[12288];
__device__ uint16_t g_wqfh[12288];
__device__ uint16_t g_pwh[65536];
__device__ float g_bn1sc[Cn], g_bn1sh[Cn], g_bn2sc[Cn], g_bn2sh[Cn];

// ================= helpers =================
__device__ __forceinline__ void ldsm4(uint32_t* r, uint32_t addr) {
    asm volatile("ldmatrix.sync.aligned.m8n8.x4.shared.b16 {%0,%1,%2,%3}, [%4];"
                 : "=r"(r[0]), "=r"(r[1]), "=r"(r[2]), "=r"(r[3]) : "r"(addr));
}
__device__ __forceinline__ void ldsm4t(uint32_t* r, uint32_t addr) {
    asm volatile("ldmatrix.sync.aligned.m8n8.x4.trans.shared.b16 {%0,%1,%2,%3}, [%4];"
                 : "=r"(r[0]), "=r"(r[1]), "=r"(r[2]), "=r"(r[3]) : "r"(addr));
}
__device__ __forceinline__ void mma_bf(float* d, const uint32_t* a, const uint32_t* b) {
    asm volatile("mma.sync.aligned.m16n8k16.row.col.f32.bf16.bf16.f32 "
                 "{%0,%1,%2,%3},{%4,%5,%6,%7},{%8,%9},{%0,%1,%2,%3};"
                 : "+f"(d[0]), "+f"(d[1]), "+f"(d[2]), "+f"(d[3])
                 : "r"(a[0]), "r"(a[1]), "r"(a[2]), "r"(a[3]), "r"(b[0]), "r"(b[1]));
}
__device__ __forceinline__ void mma_fp(float* d, const uint32_t* a, const uint32_t* b) {
    asm volatile("mma.sync.aligned.m16n8k16.row.col.f32.f16.f16.f32 "
                 "{%0,%1,%2,%3},{%4,%5,%6,%7},{%8,%9},{%0,%1,%2,%3};"
                 : "+f"(d[0]), "+f"(d[1]), "+f"(d[2]), "+f"(d[3])
                 : "r"(a[0]), "r"(a[1]), "r"(a[2]), "r"(a[3]), "r"(b[0]), "r"(b[1]));
}
__device__ __forceinline__ void cpa16(uint32_t dst, const void* src) {
    asm volatile("cp.async.cg.shared.global [%0], [%1], 16;" :: "r"(dst), "l"(src));
}
#define CP_COMMIT() asm volatile("cp.async.commit_group;" ::: "memory")

__device__ __forceinline__ uint32_t packbf2(float a, float b) {
    __nv_bfloat162 t;
    t.x = __float2bfloat16_rn(a); t.y = __float2bfloat16_rn(b);
    return *(uint32_t*)&t;
}
__device__ __forceinline__ uint32_t packh2(float a, float b) {
    __half2 t;
    t.x = __float2half_rn(a); t.y = __float2half_rn(b);
    return *(uint32_t*)&t;
}
__device__ __forceinline__ void split4(float4 f, uint2& hv, uint2& lv) {
    float hx = __bfloat162float(__float2bfloat16_rn(f.x));
    float hy = __bfloat162float(__float2bfloat16_rn(f.y));
    float hz = __bfloat162float(__float2bfloat16_rn(f.z));
    float hw = __bfloat162float(__float2bfloat16_rn(f.w));
    hv.x = packbf2(f.x, f.y);           hv.y = packbf2(f.z, f.w);
    lv.x = packbf2(f.x - hx, f.y - hy); lv.y = packbf2(f.z - hz, f.w - hw);
}
__device__ __forceinline__ void split1(float a, uint16_t* oh, uint16_t* ol) {
    bf h = __float2bfloat16_rn(a);
    *(bf*)oh = h;
    *(bf*)ol = __float2bfloat16_rn(a - __bfloat162float(h));
}
__device__ __forceinline__ void half1(float a, uint16_t* oh) {
    *(__half*)oh = __float2half_rn(a);
}

// ================= HMMA GEMM: NS-stage cp.async pipeline =================
// F16: single-plane fp16, 1 MMA pass. Otherwise bf16 hi/lo, 3 passes.
// IUP: epilogue scatters interleaved into g_coarse and g_y0.
template<bool ATR, bool BKN, bool M64T, bool IUP, bool F16>
__global__ __launch_bounds__(256, M64T ? 4 : 3) void hgemm(
    const uint16_t* __restrict__ Agh, const uint16_t* __restrict__ Agl,
    const uint16_t* __restrict__ Bgh, const uint16_t* __restrict__ Bgl,
    float* __restrict__ Cf, float* __restrict__ Cf2,
    uint16_t* __restrict__ Ch, uint16_t* __restrict__ Cl,
    int M, int N, int K, int lda, int ldb, int ldc,
    long long sA, long long sB, long long sC, int zamask,
    float alpha, const float* __restrict__ rowScale, const float* __restrict__ rowShift,
    float lo, float hi)
{
    constexpr int MT    = M64T ? 64 : 128;
    constexpr int NFP   = M64T ? 2 : 4;
    constexpr int NWS   = M64T ? 32 : 64;
    constexpr int ASLOT = ATR ? 8704 : MT * 80;
    constexpr int BSLOT = BKN ? 8704 : 10240;
    constexpr int NPL   = F16 ? 1 : 2;
    constexpr int STG   = NPL * (ASLOT + BSLOT);
    constexpr int NS    = (4 * STG <= 114688) ? 4 : 3;   // pipeline depth
    extern __shared__ char sm[];
    const uint32_t smb = (uint32_t)__cvta_generic_to_shared(sm);
    const int tid = threadIdx.x;
    const int wid = tid >> 5, lane = tid & 31;
    const int grp = lane >> 2, tig = lane & 3;
    const int z = blockIdx.z;
    const int za = z & zamask;
    Agh += (size_t)za * sA;
    Bgh += (size_t)z * sB;
    if (!F16) { Agl += (size_t)za * sA; Bgl += (size_t)z * sB; }
    if (!IUP && Cf) Cf += (size_t)z * sC;
    if (Ch) { Ch += (size_t)z * sC; if (!F16) Cl += (size_t)z * sC; }
    const int m0 = blockIdx.y * MT, n0 = blockIdx.x * 128;
    const int mw = M64T ? (wid >> 2) : (wid >> 1);
    const int nw = M64T ? (wid & 3) : (wid & 1);

    float acc[2][2*NFP][4];
    #pragma unroll
    for (int i = 0; i < 2; i++)
        #pragma unroll
        for (int j = 0; j < 2*NFP; j++)
            #pragma unroll
            for (int q = 0; q < 4; q++) acc[i][j][q] = 0.f;

    const int nch = K >> 5;

    auto stage_copy = [&](int c, int s) {
        const int k0 = c << 5;
        const uint32_t Ab = smb + s * STG;
        const uint32_t Bb = Ab + NPL * ASLOT;
        #pragma unroll
        for (int p = 0; p < ((!ATR && M64T) ? 1 : 2); p++) {
            int id = tid + (p << 8);
            if (!ATR) {
                int m = id >> 2, part = id & 3;
                size_t off = (size_t)(m0 + m) * lda + k0 + part * 8;
                uint32_t d = Ab + m * 80 + part * 16;
                cpa16(d, Agh + off);
                if (!F16) cpa16(d + ASLOT, Agl + off);
            } else {
                int k = id >> 4, part = id & 15;
                size_t off = (size_t)(k0 + k) * lda + m0 + part * 8;
                uint32_t d = Ab + k * 272 + part * 16;
                cpa16(d, Agh + off);
                if (!F16) cpa16(d + ASLOT, Agl + off);
            }
        }
        #pragma unroll
        for (int p = 0; p < 2; p++) {
            int id = tid + (p << 8);
            if (BKN) {
                int k = id >> 4, part = id & 15;
                size_t off = (size_t)(k0 + k) * ldb + n0 + part * 8;
                uint32_t d = Bb + k * 272 + part * 16;
                cpa16(d, Bgh + off);
                if (!F16) cpa16(d + BSLOT, Bgl + off);
            } else {
                int n = id >> 2, part = id & 3;
                size_t off = (size_t)(n0 + n) * ldb + k0 + part * 8;
                uint32_t d = Bb + n * 80 + part * 16;
                cpa16(d, Bgh + off);
                if (!F16) cpa16(d + BSLOT, Bgl + off);
            }
        }
    };

    auto compute = [&](int s) {
        const uint32_t Ab = smb + s * STG;
        const uint32_t Bb = Ab + NPL * ASLOT;
        const int i = lane >> 3;
        #pragma unroll
        for (int kk = 0; kk < 32; kk += 16) {
            uint32_t ah[2][4], al[2][4];
            #pragma unroll
            for (int mf = 0; mf < 2; mf++) {
                uint32_t addr;
                if (!ATR) {
                    addr = Ab + (uint32_t)((mw * 32 + mf * 16 + (lane & 15)) * 80 + (kk + (lane >> 4) * 8) * 2);
                    ldsm4(ah[mf], addr);
                    if (!F16) ldsm4(al[mf], addr + ASLOT);
                } else {
                    addr = Ab + (uint32_t)((kk + (i >> 1) * 8 + (lane & 7)) * 272 + (mw * 32 + mf * 16 + (i & 1) * 8) * 2);
                    ldsm4t(ah[mf], addr);
                    if (!F16) ldsm4t(al[mf], addr + ASLOT);
                }
            }
            uint32_t bh[NFP][4], bl[NFP][4];
            #pragma unroll
            for (int nfp = 0; nfp < NFP; nfp++) {
                uint32_t addr;
                if (BKN) {
                    addr = Bb + (uint32_t)((kk + (i & 1) * 8 + (lane & 7)) * 272 + (nw * NWS + nfp * 16 + (i >> 1) * 8) * 2);
                    ldsm4t(bh[nfp], addr);
                    if (!F16) ldsm4t(bl[nfp], addr + BSLOT);
                } else {
                    addr = Bb + (uint32_t)((nw * NWS + nfp * 16 + (i >> 1) * 8 + (lane & 7)) * 80 + (kk + (i & 1) * 8) * 2);
                    ldsm4(bh[nfp], addr);
                    if (!F16) ldsm4(bl[nfp], addr + BSLOT);
                }
            }
            #pragma unroll
            for (int pass = 0; pass < (F16 ? 1 : 3); pass++) {
                #pragma unroll
                for (int nfp = 0; nfp < NFP; nfp++) {
                    #pragma unroll
                    for (int mf = 0; mf < 2; mf++) {
                        #pragma unroll
                        for (int h = 0; h < 2; h++) {
                            const uint32_t* a = (pass == 2) ? al[mf] : ah[mf];
                            const uint32_t* b = ((pass == 1) ? bl[nfp] : bh[nfp]) + h * 2;
                            if (F16) mma_fp(acc[mf][nfp * 2 + h], a, b);
                            else     mma_bf(acc[mf][nfp * 2 + h], a, b);
                        }
                    }
                }
            }
        }
    };

    // ---- NS-stage pipelined mainloop ----
    #pragma unroll
    for (int i = 0; i < NS - 1; i++) {
        if (i < nch) stage_copy(i, i);
        CP_COMMIT();                       // commit (possibly empty) group: keeps accounting exact
    }
    for (int c = 0; c < nch; c++) {
        asm volatile("cp.async.wait_group %0;" :: "n"(NS - 2) : "memory");
        __syncthreads();
        int cn = c + NS - 1;
        if (cn < nch) stage_copy(cn, cn % NS);
        CP_COMMIT();                       // always commit, empty at the tail
        compute(c % NS);
    }
    __syncthreads();

    // ---- epilogue ----
    float* stg = (float*)sm;   // [MT][132]
    #pragma unroll
    for (int mf = 0; mf < 2; mf++) {
        int r0 = mw * 32 + mf * 16 + grp;
        float av0 = alpha, av1 = alpha, sh0 = 0.f, sh1 = 0.f;
        if (rowScale) { av0 *= rowScale[m0 + r0]; av1 *= rowScale[m0 + r0 + 8]; }
        if (rowShift) { sh0 = rowShift[m0 + r0]; sh1 = rowShift[m0 + r0 + 8]; }
        #pragma unroll
        for (int nf = 0; nf < 2*NFP; nf++) {
            int cb = nw * NWS + nf * 8 + tig * 2;
            float* d = acc[mf][nf];
            stg[r0 * 132 + cb]           = fminf(fmaxf(d[0] * av0 + sh0, lo), hi);
            stg[r0 * 132 + cb + 1]       = fminf(fmaxf(d[1] * av0 + sh0, lo), hi);
            stg[(r0 + 8) * 132 + cb]     = fminf(fmaxf(d[2] * av1 + sh1, lo), hi);
            stg[(r0 + 8) * 132 + cb + 1] = fminf(fmaxf(d[3] * av1 + sh1, lo), hi);
        }
    }
    __syncthreads();
    if (IUP) {
        const int px = z & 1, py = (z >> 1) & 1, zb = z >> 2;
        #pragma unroll
        for (int it = 0; it < MT/8; it++) {
            int lin = tid + (it << 8);
            int rr = lin >> 5, c4 = (lin & 31) << 2;
            float4 v = *(float4*)&stg[rr * 132 + c4];
            int m = m0 + rr;
            int n = n0 + c4;
            int a = n >> 5, cc = n & 31;
            size_t base = ((size_t)zb * Cn + m) * 4096 + (size_t)(2*a + py) * 64 + 2*cc + px;
            Cf[base]     = v.x;  Cf2[base]     = v.x;
            Cf[base + 2] = v.y;  Cf2[base + 2] = v.y;
            Cf[base + 4] = v.z;  Cf2[base + 4] = v.z;
            Cf[base + 6] = v.w;  Cf2[base + 6] = v.w;
        }
    } else if (Cf) {
        #pragma unroll
        for (int it = 0; it < MT/8; it++) {
            int lin = tid + (it << 8);
            int rr = lin >> 5, c4 = (lin & 31) << 2;
            *(float4*)(Cf + (size_t)(m0 + rr) * ldc + n0 + c4) = *(float4*)&stg[rr * 132 + c4];
        }
    } else {
        #pragma unroll
        for (int it = 0; it < MT/8; it++) {
            int lin = tid + (it << 8);
            int rr = lin >> 5, c4 = (lin & 31) << 2;
            float4 v = *(float4*)&stg[rr * 132 + c4];
            size_t o = (size_t)(m0 + rr) * ldc + n0 + c4;
            if (F16) {
                uint2 hv;
                hv.x = packh2(v.x, v.y); hv.y = packh2(v.z, v.w);
                *(uint2*)(Ch + o) = hv;
            } else {
                uint2 hv, lv;
                split4(v, hv, lv);
                *(uint2*)(Ch + o) = hv;
                *(uint2*)(Cl + o) = lv;
            }
        }
    }
}

// ---------------- fused weight prep ----------------
#define PREP_O2 1048576
#define PREP_O3 1060864
#define PREP_O4 1073152
#define PREP_O5 1138688
#define PREP_O6 2187264
#define PREP_END 2187776
__global__ void k_prep_all(const float* __restrict__ down_w,
                           const float* __restrict__ wqkv_c, const float* __restrict__ wqkv_f,
                           const float* __restrict__ pw_w,   const float* __restrict__ up_w,
                           const float* __restrict__ bn1_g, const float* __restrict__ bn1_b,
                           const float* __restrict__ bn1_m, const float* __restrict__ bn1_v,
                           const float* __restrict__ bn2_g, const float* __restrict__ bn2_b,
                           const float* __restrict__ bn2_m, const float* __restrict__ bn2_v) {
    int idx = blockIdx.x * 256 + threadIdx.x;
    if (idx < PREP_O2) {
        split1(down_w[idx], g_wdh + idx, g_wdl + idx);
    } else if (idx < PREP_O3) {
        int i = idx - PREP_O2;
        int m = i / 64, k = i % 64;
        split1(wqkv_c[k * 192 + m], g_wqch + i, g_wqcl + i);
    } else if (idx < PREP_O4) {
        int i = idx - PREP_O3;
        int m = i / 64, k = i % 64;
        half1(wqkv_f[k * 192 + m], g_wqfh + i);
    } else if (idx < PREP_O5) {
        int i = idx - PREP_O4;
        half1(pw_w[i], g_pwh + i);
    } else if (idx < PREP_O6) {
        int i = idx - PREP_O5;
        int k = i & 1023, co = (i >> 10) & 255, p = i >> 18;
        int tj = k & 1, ti = (k >> 1) & 1, ci = k >> 2;
        int px = p & 1, py = p >> 1;
        int kh = (py == 0) ? (ti == 0 ? 1 : 3) : (ti == 0 ? 0 : 2);
        int kw = (px == 0) ? (tj == 0 ? 1 : 3) : (tj == 0 ? 0 : 2);
        half1(up_w[((ci << 8) + co) * 16 + kh*4 + kw], g_Wph + i);
    } else if (idx < PREP_END) {
        int i = idx - PREP_O6;
        int c = i & 255;
        if (i < 256) {
            float inv = bn1_g[c] / sqrtf(bn1_v[c] + 1e-5f);
            g_bn1sc[c] = inv;
            g_bn1sh[c] = bn1_b[c] - bn1_m[c] * inv;
        } else {
            float inv = bn2_g[c] / sqrtf(bn2_v[c] + 1e-5f);
            g_bn2sc[c] = inv;
            g_bn2sh[c] = bn2_b[c] - bn2_m[c] * inv;
        }
    }
}

// ---------------- elementwise kernels ----------------
__global__ void k_im2col_down(const float* __restrict__ x) {
    int idx = blockIdx.x * 256 + threadIdx.x;
    int q  = idx & 255;
    int k  = (idx >> 8) & 4095;
    int b  = idx >> 20;
    int kw = k & 3, kh = (k >> 2) & 3, ci = k >> 4;
    int ow0 = (q & 7) << 2, oh = q >> 3;
    int ih = oh*2 - 1 + kh;
    const float* xr = x + ((long long)b*Cn + ci)*(Hn*Wn) + ih*Wn;
    float4 r;
    float* rp = (float*)&r;
    #pragma unroll
    for (int j = 0; j < 4; j++) {
        int iw = (ow0 + j)*2 - 1 + kw;
        rp[j] = (ih >= 0 && ih < Hn && iw >= 0 && iw < Wn) ? xr[iw] : 0.f;
    }
    uint2 hv, lv; split4(r, hv, lv);
    size_t o = ((size_t)idx) << 2;
    *(uint2*)&g_colh[o] = hv;
    *(uint2*)&g_coll[o] = lv;
}

// fp16 single-plane output
__global__ void k_im2col_up() {
    int idx = blockIdx.x * 256 + threadIdx.x;
    int q = idx & 255;
    int k = (idx >> 8) & 1023;
    int s = idx >> 18;
    int tj = k & 1, ti = (k >> 1) & 1, ci = k >> 2;
    int px = s & 1, py = (s >> 1) & 1, b = s >> 2;
    int c0 = (q & 7) << 2, a = q >> 3;
    int iy = (py == 0) ? (ti == 0 ? a : a - 1) : (ti == 0 ? a + 1 : a);
    int dx = (px == 0) ? (tj == 0 ? 0 : -1) : (tj == 0 ? 1 : 0);
    const float* orow = g_outc + ((long long)b*Cn + ci)*1024 + iy*32;
    float4 r;
    float* rp = (float*)&r;
    bool rowok = (iy >= 0 && iy < 32);
    #pragma unroll
    for (int j = 0; j < 4; j++) {
        int ix = c0 + j + dx;
        rp[j] = (rowok && ix >= 0 && ix < 32) ? orow[ix] : 0.f;
    }
    uint2 hv;
    hv.x = packh2(r.x, r.y); hv.y = packh2(r.z, r.w);
    *(uint2*)&g_colh[((size_t)idx) << 2] = hv;
}

// f16out=0: bf16 hi/lo planes; f16out=1: fp16 single plane
__global__ __launch_bounds__(256) void k_softmax(const float* __restrict__ S,
                                                 uint16_t* __restrict__ Ph, uint16_t* __restrict__ Pl,
                                                 int f16out) {
    __shared__ float red[8];
    long long row = blockIdx.x;
    const float* p = S + row * 1024;
    int tid = threadIdx.x;
    float4 v = ((const float4*)p)[tid];
    float mx = fmaxf(fmaxf(v.x, v.y), fmaxf(v.z, v.w));
    #pragma unroll
    for (int o = 16; o; o >>= 1) mx = fmaxf(mx, __shfl_xor_sync(0xffffffffu, mx, o));
    if ((tid & 31) == 0) red[tid >> 5] = mx;
    __syncthreads();
    if (tid == 0) {
        float m = red[0];
        #pragma unroll
        for (int i = 1; i < 8; i++) m = fmaxf(m, red[i]);
        red[0] = m;
    }
    __syncthreads();
    mx = red[0];
    __syncthreads();
    float e0 = __expf(v.x - mx), e1 = __expf(v.y - mx);
    float e2 = __expf(v.z - mx), e3 = __expf(v.w - mx);
    float s = (e0 + e1) + (e2 + e3);
    #pragma unroll
    for (int o = 16; o; o >>= 1) s += __shfl_xor_sync(0xffffffffu, s, o);
    if ((tid & 31) == 0) red[tid >> 5] = s;
    __syncthreads();
    if (tid == 0) {
        float t = 0.f;
        #pragma unroll
        for (int i = 0; i < 8; i++) t += red[i];
        red[0] = t;
    }
    __syncthreads();
    float inv = 1.f / red[0];
    float4 r;
    r.x = e0 * inv; r.y = e1 * inv; r.z = e2 * inv; r.w = e3 * inv;
    size_t o = row * 1024 + (size_t)tid * 4;
    if (f16out) {
        uint2 hv;
        hv.x = packh2(r.x, r.y); hv.y = packh2(r.z, r.w);
        *(uint2*)(Ph + o) = hv;
    } else {
        uint2 hv, lv; split4(r, hv, lv);
        *(uint2*)(Ph + o) = hv;
        *(uint2*)(Pl + o) = lv;
    }
}

__global__ void k_colsum() {
    int z = blockIdx.x >> 1;
    int m2 = ((blockIdx.x & 1) << 8) + threadIdx.x;
    const uint32_t* ph = (const uint32_t*)(g_Ph + (long long)z * 1048576) + m2;
    const uint32_t* pl = (const uint32_t*)(g_Pl + (long long)z * 1048576) + m2;
    float s0 = 0.f, s1 = 0.f;
    #pragma unroll 8
    for (int n = 0; n < 1024; n++) {
        long long o = (long long)n << 9;
        __nv_bfloat162 h = *(const __nv_bfloat162*)&ph[o];
        __nv_bfloat162 l = *(const __nv_bfloat162*)&pl[o];
        s0 += __bfloat162float(h.x) + __bfloat162float(l.x);
        s1 += __bfloat162float(h.y) + __bfloat162float(l.y);
    }
    g_score[z * 1024 + m2 * 2]     = s0;
    g_score[z * 1024 + m2 * 2 + 1] = s1;
}

__global__ __launch_bounds__(512) void k_topk() {
    __shared__ float v[1024];
    __shared__ int   ix[1024];
    int z = blockIdx.x, tid = threadIdx.x;
    for (int i = tid; i < 1024; i += 512) { v[i] = g_score[z*1024 + i]; ix[i] = i; }
    __syncthreads();
    for (int k = 2; k <= 1024; k <<= 1) {
        for (int j = k >> 1; j > 0; j >>= 1) {
            for (int i = tid; i < 1024; i += 512) {
                int l = i ^ j;
                if (l > i) {
                    bool up = ((i & k) == 0);
                    bool sw = up ? (v[i] < v[l]) : (v[i] > v[l]);
                    if (sw) {
                        float tv = v[i]; v[i] = v[l]; v[l] = tv;
                        int ti2 = ix[i]; ix[i] = ix[l]; ix[l] = ti2;
                    }
                }
            }
            __syncthreads();
        }
    }
    for (int i = tid; i < KFn; i += 512) g_topk[z*KFn + i] = ix[i];
}

// fp16 single-plane output
__global__ void k_gather_fine() {
    int idx = blockIdx.x * 256 + threadIdx.x;
    int t = idx & 1023, d = (idx >> 10) & 63, z = idx >> 16;
    int ki = t >> 2, i = (t >> 1) & 1, j = t & 1;
    int p = g_topk[(z << 8) + ki];
    int pi = p >> 5, pj = p & 31;
    int b = z >> 2, h = z & 3;
    float v = g_coarse[((long long)b*Cn + (h*HDn + d))*4096 + (2*pi + i)*64 + (2*pj + j)];
    half1(v, g_tokh + idx);
}

__global__ void k_scatter() {
    int idx = blockIdx.x * 256 + threadIdx.x;
    int t = idx & 1023, d = (idx >> 10) & 63, z = idx >> 16;
    int ki = t >> 2, i = (t >> 1) & 1, j = t & 1;
    int p = g_topk[(z << 8) + ki];
    int pi = p >> 5, pj = p & 31;
    int b = z >> 2, h = z & 3;
    g_y0[((long long)b*Cn + (h*HDn + d))*4096 + (2*pi + i)*64 + (2*pj + j)] += g_outfT[idx];
}

// fp16 single-plane output
__global__ void k_dw(const float* __restrict__ dw_w) {
    int idx = blockIdx.x * 256 + threadIdx.x;
    int x4 = (idx & 15) << 2, y = (idx >> 4) & 63, c = (idx >> 10) & 255, b = idx >> 18;
    const float* base = g_y0 + ((long long)b*Cn + c)*4096;
    const float* wp = dw_w + c*9;
    float s[4] = {0.f, 0.f, 0.f, 0.f};
    #pragma unroll
    for (int ky = 0; ky < 3; ky++) {
        int yy = y + ky - 1;
        if (yy < 0 || yy >= 64) continue;
        const float* row = base + yy*64;
        float4 mid = *(const float4*)(row + x4);
        float lft = (x4 > 0)  ? row[x4 - 1] : 0.f;
        float rgt = (x4 < 60) ? row[x4 + 4] : 0.f;
        float w0 = wp[ky*3], w1 = wp[ky*3 + 1], w2 = wp[ky*3 + 2];
        s[0] = fmaf(lft,   w0, fmaf(mid.x, w1, fmaf(mid.y, w2, s[0])));
        s[1] = fmaf(mid.x, w0, fmaf(mid.y, w1, fmaf(mid.z, w2, s[1])));
        s[2] = fmaf(mid.y, w0, fmaf(mid.z, w1, fmaf(mid.w, w2, s[2])));
        s[3] = fmaf(mid.z, w0, fmaf(mid.w, w1, fmaf(rgt,   w2, s[3])));
    }
    float sc = g_bn1sc[c], sh = g_bn1sh[c];
    float r0 = fminf(fmaxf(s[0]*sc + sh, 0.f), 6.f);
    float r1 = fminf(fmaxf(s[1]*sc + sh, 0.f), 6.f);
    float r2 = fminf(fmaxf(s[2]*sc + sh, 0.f), 6.f);
    float r3 = fminf(fmaxf(s[3]*sc + sh, 0.f), 6.f);
    uint2 hv;
    hv.x = packh2(r0, r1); hv.y = packh2(r2, r3);
    *(uint2*)&g_t1h[((size_t)b*Cn + c)*4096 + y*64 + x4] = hv;
}

// ---------------- host ----------------
struct GArgs {
    const uint16_t *Ah, *Al, *Bh, *Bl;
    float* Cf; float* Cf2; uint16_t *Ch, *Cl;
};
static inline int smem_for(bool atr, bool bkn, bool m64, bool f16) {
    int aslot = atr ? 8704 : (m64 ? 64 : 128) * 80;
    int bslot = bkn ? 8704 : 10240;
    int npl = f16 ? 1 : 2;
    int stg = npl * (aslot + bslot);
    int ns = (4 * stg <= 114688) ? 4 : 3;
    int pipe = ns * stg;
    int epi = (m64 ? 64 : 128) * 132 * 4;
    return pipe > epi ? pipe : epi;
}

template<bool ATR, bool BKN, bool M64T, bool IUP, bool F16>
static void launch_hgemm(dim3 grid, GArgs g,
                         int M, int N, int K, int lda, int ldb, int ldc,
                         long long sA, long long sB, long long sC, int zamask,
                         float alpha, const float* sc, const float* sh, float lo, float hi) {
    int shm = smem_for(ATR, BKN, M64T, F16);
    cudaFuncSetAttribute(hgemm<ATR,BKN,M64T,IUP,F16>, cudaFuncAttributeMaxDynamicSharedMemorySize, shm);
    hgemm<ATR,BKN,M64T,IUP,F16><<<grid, 256, shm>>>(g.Ah, g.Al, g.Bh, g.Bl, g.Cf, g.Cf2, g.Ch, g.Cl,
        M, N, K, lda, ldb, ldc, sA, sB, sC, zamask, alpha, sc, sh, lo, hi);
}

extern "C" void kernel_launch(void* const* d_in, const int* in_sizes, int n_in,
                              void* d_out, int out_size)
{
    const float* x      = (const float*)d_in[0];
    const float* down_w = (const float*)d_in[1];
    const float* down_b = (const float*)d_in[2];
    const float* up_w   = (const float*)d_in[3];
    const float* up_b   = (const float*)d_in[4];
    const float* wqkv_c = (const float*)d_in[5];
    const float* bqkv_c = (const float*)d_in[6];
    const float* wqkv_f = (const float*)d_in[7];
    const float* bqkv_f = (const float*)d_in[8];
    const float* dw_w   = (const float*)d_in[9];
    const float* bn1_g  = (const float*)d_in[10];
    const float* bn1_b  = (const float*)d_in[11];
    const float* bn1_m  = (const float*)d_in[12];
    const float* bn1_v  = (const float*)d_in[13];
    const float* pw_w   = (const float*)d_in[14];
    const float* bn2_g  = (const float*)d_in[15];
    const float* bn2_b  = (const float*)d_in[16];
    const float* bn2_m  = (const float*)d_in[17];
    const float* bn2_v  = (const float*)d_in[18];
    float* out = (float*)d_out;

    #define SYM(p, s) cudaGetSymbolAddress((void**)&p, s)
    uint16_t *colh, *coll, *xdh, *xdl, *qch, *qcl, *qfh, *Ph, *Pl, *tokh;
    uint16_t *t1h, *wdh, *wdl, *Wph, *wqch, *wqcl, *wqfh, *pwh;
    float *S, *outc, *coarse, *y0, *outf;
    float *b2s, *b2h;
    SYM(colh, g_colh); SYM(coll, g_coll); SYM(xdh, g_xdh); SYM(xdl, g_xdl);
    SYM(qch, g_qch); SYM(qcl, g_qcl); SYM(qfh, g_qfh);
    SYM(Ph, g_Ph); SYM(Pl, g_Pl); SYM(tokh, g_tokh);
    SYM(t1h, g_t1h); SYM(wdh, g_wdh); SYM(wdl, g_wdl);
    SYM(Wph, g_Wph); SYM(wqch, g_wqch); SYM(wqcl, g_wqcl);
    SYM(wqfh, g_wqfh); SYM(pwh, g_pwh);
    SYM(S, g_S); SYM(outc, g_outc); SYM(coarse, g_coarse); SYM(y0, g_y0);
    SYM(outf, g_outfT);
    SYM(b2s, g_bn2sc); SYM(b2h, g_bn2sh);
    #undef SYM

    const float NEG = -3.0e38f, POS = 3.0e38f;
    const int ZM = 0x7fffffff;

    k_prep_all<<<(PREP_END + 255)/256, 256>>>(down_w, wqkv_c, wqkv_f, pw_w, up_w,
        bn1_g, bn1_b, bn1_m, bn1_v, bn2_g, bn2_b, bn2_m, bn2_v);

    // ---- down conv -> xd planes (bf16 3-pass)
    k_im2col_down<<<32768, 256>>>(x);
    launch_hgemm<false,true,true,false,false>(dim3(8,4,Bn),
        {wdh, wdl, colh, coll, nullptr, nullptr, xdh, xdl}, 256, 1024, 4096, 4096, 1024, 1024,
        0, 4096LL*1024, 256LL*1024, ZM, 1.f, nullptr, down_b, NEG, POS);

    // ---- coarse QKV (bf16 3-pass)
    launch_hgemm<false,true,true,false,false>(dim3(8,3,32),
        {wqch, wqcl, xdh, xdl, nullptr, nullptr, qch, qcl}, 192, 1024, 64, 64, 1024, 1024,
        0, 65536, 196608, ZM, 1.f, nullptr, bqkv_c, NEG, POS);

    // ---- coarse S (bf16 3-pass), softmax (bf16 planes), colsum, topk
    launch_hgemm<true,true,false,false,false>(dim3(8,8,32),
        {qch, qcl, qch + 65536, qcl + 65536, S, nullptr, nullptr, nullptr}, 1024, 1024, 64, 1024, 1024, 1024,
        196608, 196608, 1048576, ZM, 0.125f, nullptr, nullptr, NEG, POS);
    k_softmax<<<32768, 256>>>(S, Ph, Pl, 0);
    k_colsum<<<64, 256>>>();
    k_topk<<<32, 512>>>();

    // ---- coarse PV (bf16 3-pass)
    launch_hgemm<false,false,true,false,false>(dim3(8,1,32),
        {qch + 131072, qcl + 131072, Ph, Pl, outc, nullptr, nullptr, nullptr}, 64, 1024, 1024, 1024, 1024, 1024,
        196608, 1048576, 65536, ZM, 1.f, nullptr, nullptr, NEG, POS);

    // ---- up conv transpose: fused fp16 GEMM + interleaved dual store
    k_im2col_up<<<32768, 256>>>();
    launch_hgemm<false,true,true,true,true>(dim3(8,4,32),
        {Wph, nullptr, colh, nullptr, coarse, y0, nullptr, nullptr}, 256, 1024, 1024, 1024, 1024, 1024,
        262144, 1048576, 0, 3, 1.f, nullptr, up_b, NEG, POS);

    // ---- fine attention (fp16 single-pass)
    k_gather_fine<<<8192, 256>>>();
    launch_hgemm<false,true,true,false,true>(dim3(8,3,32),
        {wqfh, nullptr, tokh, nullptr, nullptr, nullptr, qfh, nullptr}, 192, 1024, 64, 64, 1024, 1024,
        0, 65536, 196608, ZM, 1.f, nullptr, bqkv_f, NEG, POS);
    launch_hgemm<true,true,false,false,true>(dim3(8,8,32),
        {qfh, nullptr, qfh + 65536, nullptr, S, nullptr, nullptr, nullptr}, 1024, 1024, 64, 1024, 1024, 1024,
        196608, 196608, 1048576, ZM, 0.125f, nullptr, nullptr, NEG, POS);
    k_softmax<<<32768, 256>>>(S, Ph, Pl, 1);
    launch_hgemm<false,false,true,false,true>(dim3(8,1,32),
        {qfh + 131072, nullptr, Ph, nullptr, outf, nullptr, nullptr, nullptr}, 64, 1024, 1024, 1024, 1024, 1024,
        196608, 1048576, 65536, ZM, 1.f, nullptr, nullptr, NEG, POS);

    // ---- residual add, depthwise, pointwise (fp16 single-pass)
    k_scatter<<<8192, 256>>>();
    k_dw<<<8192, 256>>>(dw_w);
    launch_hgemm<false,true,true,false,true>(dim3(32,4,Bn),
        {pwh, nullptr, t1h, nullptr, out, nullptr, nullptr, nullptr}, 256, 4096, 256, 256, 4096, 4096,
        0, 1048576, 1048576, ZM, 1.f, b2s, b2h, 0.f, 6.f);
}

// round 11
// speedup vs baseline: 1.4276x; 1.1814x over previous
#include <cuda_runtime.h>
#include <cuda_bf16.h>
#include <cuda_fp16.h>
#include <math.h>
#include <stdint.h>

#define Bn 8
#define Cn 256
#define Hn 64
#define Wn 64
#define NHn 4
#define HDn 64
#define NTOK 1024
#define KFn 256

typedef __nv_bfloat16 bf;

// ---------------- static scratch ----------------
__device__ uint16_t g_colh[33554432], g_coll[33554432];
__device__ uint16_t g_xdh[2097152],  g_xdl[2097152];
__device__ uint16_t g_qch[6291456],  g_qcl[6291456];
__device__ uint16_t g_qfh[6291456];
__device__ float    g_S[33554432];
__device__ uint16_t g_Ph[33554432],  g_Pl[33554432];
__device__ float    g_score[Bn*NHn*NTOK];
__device__ int      g_topk[Bn*NHn*KFn];
__device__ float    g_outc[Bn*Cn*1024];
__device__ uint16_t g_tokh[2097152];
__device__ float    g_outfT[2097152];
__device__ float    g_coarse[8388608];
__device__ float    g_y0[8388608];
__device__ uint16_t g_t1h[8388608];
__device__ uint16_t g_wdh[1048576],  g_wdl[1048576];
__device__ uint16_t g_Wph[1048576];
__device__ uint16_t g_wqch[12288],   g_wqcl[12288];
__device__ uint16_t g_wqfh[12288];
__device__ uint16_t g_pwh[65536];
__device__ float g_bn1sc[Cn], g_bn1sh[Cn], g_bn2sc[Cn], g_bn2sh[Cn];

// ================= helpers =================
__device__ __forceinline__ void ldsm4(uint32_t* r, uint32_t addr) {
    asm volatile("ldmatrix.sync.aligned.m8n8.x4.shared.b16 {%0,%1,%2,%3}, [%4];"
                 : "=r"(r[0]), "=r"(r[1]), "=r"(r[2]), "=r"(r[3]) : "r"(addr));
}
__device__ __forceinline__ void ldsm4t(uint32_t* r, uint32_t addr) {
    asm volatile("ldmatrix.sync.aligned.m8n8.x4.trans.shared.b16 {%0,%1,%2,%3}, [%4];"
                 : "=r"(r[0]), "=r"(r[1]), "=r"(r[2]), "=r"(r[3]) : "r"(addr));
}
__device__ __forceinline__ void mma_bf(float* d, const uint32_t* a, const uint32_t* b) {
    asm volatile("mma.sync.aligned.m16n8k16.row.col.f32.bf16.bf16.f32 "
                 "{%0,%1,%2,%3},{%4,%5,%6,%7},{%8,%9},{%0,%1,%2,%3};"
                 : "+f"(d[0]), "+f"(d[1]), "+f"(d[2]), "+f"(d[3])
                 : "r"(a[0]), "r"(a[1]), "r"(a[2]), "r"(a[3]), "r"(b[0]), "r"(b[1]));
}
__device__ __forceinline__ void mma_fp(float* d, const uint32_t* a, const uint32_t* b) {
    asm volatile("mma.sync.aligned.m16n8k16.row.col.f32.f16.f16.f32 "
                 "{%0,%1,%2,%3},{%4,%5,%6,%7},{%8,%9},{%0,%1,%2,%3};"
                 : "+f"(d[0]), "+f"(d[1]), "+f"(d[2]), "+f"(d[3])
                 : "r"(a[0]), "r"(a[1]), "r"(a[2]), "r"(a[3]), "r"(b[0]), "r"(b[1]));
}
__device__ __forceinline__ void cpa16(uint32_t dst, const void* src) {
    asm volatile("cp.async.cg.shared.global [%0], [%1], 16;" :: "r"(dst), "l"(src));
}
#define CP_COMMIT() asm volatile("cp.async.commit_group;" ::: "memory")

__device__ __forceinline__ uint32_t packbf2(float a, float b) {
    __nv_bfloat162 t;
    t.x = __float2bfloat16_rn(a); t.y = __float2bfloat16_rn(b);
    return *(uint32_t*)&t;
}
__device__ __forceinline__ uint32_t packh2(float a, float b) {
    __half2 t;
    t.x = __float2half_rn(a); t.y = __float2half_rn(b);
    return *(uint32_t*)&t;
}
__device__ __forceinline__ void split4(float4 f, uint2& hv, uint2& lv) {
    float hx = __bfloat162float(__float2bfloat16_rn(f.x));
    float hy = __bfloat162float(__float2bfloat16_rn(f.y));
    float hz = __bfloat162float(__float2bfloat16_rn(f.z));
    float hw = __bfloat162float(__float2bfloat16_rn(f.w));
    hv.x = packbf2(f.x, f.y);           hv.y = packbf2(f.z, f.w);
    lv.x = packbf2(f.x - hx, f.y - hy); lv.y = packbf2(f.z - hz, f.w - hw);
}
__device__ __forceinline__ void split1(float a, uint16_t* oh, uint16_t* ol) {
    bf h = __float2bfloat16_rn(a);
    *(bf*)oh = h;
    *(bf*)ol = __float2bfloat16_rn(a - __bfloat162float(h));
}
__device__ __forceinline__ void half1(float a, uint16_t* oh) {
    *(__half*)oh = __float2half_rn(a);
}

// ================= HMMA GEMM: NS-stage cp.async pipeline =================
// m-blocks on grid.x (consecutive bids share the B tile -> L2 reuse).
template<bool ATR, bool BKN, bool M64T, bool IUP, bool F16, int NS>
__global__ __launch_bounds__(256, M64T ? 4 : 3) void hgemm(
    const uint16_t* __restrict__ Agh, const uint16_t* __restrict__ Agl,
    const uint16_t* __restrict__ Bgh, const uint16_t* __restrict__ Bgl,
    float* __restrict__ Cf, float* __restrict__ Cf2,
    uint16_t* __restrict__ Ch, uint16_t* __restrict__ Cl,
    int M, int N, int K, int lda, int ldb, int ldc,
    long long sA, long long sB, long long sC, int zamask,
    float alpha, const float* __restrict__ rowScale, const float* __restrict__ rowShift,
    float lo, float hi)
{
    constexpr int MT    = M64T ? 64 : 128;
    constexpr int NFP   = M64T ? 2 : 4;
    constexpr int NWS   = M64T ? 32 : 64;
    constexpr int ASLOT = ATR ? 8704 : MT * 80;
    constexpr int BSLOT = BKN ? 8704 : 10240;
    constexpr int NPL   = F16 ? 1 : 2;
    constexpr int STG   = NPL * (ASLOT + BSLOT);
    extern __shared__ char sm[];
    const uint32_t smb = (uint32_t)__cvta_generic_to_shared(sm);
    const int tid = threadIdx.x;
    const int wid = tid >> 5, lane = tid & 31;
    const int grp = lane >> 2, tig = lane & 3;
    const int z = blockIdx.z;
    const int za = z & zamask;
    Agh += (size_t)za * sA;
    Bgh += (size_t)z * sB;
    if (!F16) { Agl += (size_t)za * sA; Bgl += (size_t)z * sB; }
    if (!IUP && Cf) Cf += (size_t)z * sC;
    if (Ch) { Ch += (size_t)z * sC; if (!F16) Cl += (size_t)z * sC; }
    const int m0 = blockIdx.x * MT, n0 = blockIdx.y * 128;
    const int mw = M64T ? (wid >> 2) : (wid >> 1);
    const int nw = M64T ? (wid & 3) : (wid & 1);

    float acc[2][2*NFP][4];
    #pragma unroll
    for (int i = 0; i < 2; i++)
        #pragma unroll
        for (int j = 0; j < 2*NFP; j++)
            #pragma unroll
            for (int q = 0; q < 4; q++) acc[i][j][q] = 0.f;

    const int nch = K >> 5;

    auto stage_copy = [&](int c, int s) {
        const int k0 = c << 5;
        const uint32_t Ab = smb + s * STG;
        const uint32_t Bb = Ab + NPL * ASLOT;
        #pragma unroll
        for (int p = 0; p < ((!ATR && M64T) ? 1 : 2); p++) {
            int id = tid + (p << 8);
            if (!ATR) {
                int m = id >> 2, part = id & 3;
                size_t off = (size_t)(m0 + m) * lda + k0 + part * 8;
                uint32_t d = Ab + m * 80 + part * 16;
                cpa16(d, Agh + off);
                if (!F16) cpa16(d + ASLOT, Agl + off);
            } else {
                int k = id >> 4, part = id & 15;
                size_t off = (size_t)(k0 + k) * lda + m0 + part * 8;
                uint32_t d = Ab + k * 272 + part * 16;
                cpa16(d, Agh + off);
                if (!F16) cpa16(d + ASLOT, Agl + off);
            }
        }
        #pragma unroll
        for (int p = 0; p < 2; p++) {
            int id = tid + (p << 8);
            if (BKN) {
                int k = id >> 4, part = id & 15;
                size_t off = (size_t)(k0 + k) * ldb + n0 + part * 8;
                uint32_t d = Bb + k * 272 + part * 16;
                cpa16(d, Bgh + off);
                if (!F16) cpa16(d + BSLOT, Bgl + off);
            } else {
                int n = id >> 2, part = id & 3;
                size_t off = (size_t)(n0 + n) * ldb + k0 + part * 8;
                uint32_t d = Bb + n * 80 + part * 16;
                cpa16(d, Bgh + off);
                if (!F16) cpa16(d + BSLOT, Bgl + off);
            }
        }
    };

    auto compute = [&](int s) {
        const uint32_t Ab = smb + s * STG;
        const uint32_t Bb = Ab + NPL * ASLOT;
        const int i = lane >> 3;
        #pragma unroll
        for (int kk = 0; kk < 32; kk += 16) {
            uint32_t ah[2][4], al[2][4];
            #pragma unroll
            for (int mf = 0; mf < 2; mf++) {
                uint32_t addr;
                if (!ATR) {
                    addr = Ab + (uint32_t)((mw * 32 + mf * 16 + (lane & 15)) * 80 + (kk + (lane >> 4) * 8) * 2);
                    ldsm4(ah[mf], addr);
                    if (!F16) ldsm4(al[mf], addr + ASLOT);
                } else {
                    addr = Ab + (uint32_t)((kk + (i >> 1) * 8 + (lane & 7)) * 272 + (mw * 32 + mf * 16 + (i & 1) * 8) * 2);
                    ldsm4t(ah[mf], addr);
                    if (!F16) ldsm4t(al[mf], addr + ASLOT);
                }
            }
            uint32_t bh[NFP][4], bl[NFP][4];
            #pragma unroll
            for (int nfp = 0; nfp < NFP; nfp++) {
                uint32_t addr;
                if (BKN) {
                    addr = Bb + (uint32_t)((kk + (i & 1) * 8 + (lane & 7)) * 272 + (nw * NWS + nfp * 16 + (i >> 1) * 8) * 2);
                    ldsm4t(bh[nfp], addr);
                    if (!F16) ldsm4t(bl[nfp], addr + BSLOT);
                } else {
                    addr = Bb + (uint32_t)((nw * NWS + nfp * 16 + (i >> 1) * 8 + (lane & 7)) * 80 + (kk + (i & 1) * 8) * 2);
                    ldsm4(bh[nfp], addr);
                    if (!F16) ldsm4(bl[nfp], addr + BSLOT);
                }
            }
            #pragma unroll
            for (int pass = 0; pass < (F16 ? 1 : 3); pass++) {
                #pragma unroll
                for (int nfp = 0; nfp < NFP; nfp++) {
                    #pragma unroll
                    for (int mf = 0; mf < 2; mf++) {
                        #pragma unroll
                        for (int h = 0; h < 2; h++) {
                            const uint32_t* a = (pass == 2) ? al[mf] : ah[mf];
                            const uint32_t* b = ((pass == 1) ? bl[nfp] : bh[nfp]) + h * 2;
                            if (F16) mma_fp(acc[mf][nfp * 2 + h], a, b);
                            else     mma_bf(acc[mf][nfp * 2 + h], a, b);
                        }
                    }
                }
            }
        }
    };

    #pragma unroll
    for (int i = 0; i < NS - 1; i++) {
        if (i < nch) stage_copy(i, i);
        CP_COMMIT();
    }
    for (int c = 0; c < nch; c++) {
        asm volatile("cp.async.wait_group %0;" :: "n"(NS - 2) : "memory");
        __syncthreads();
        int cn = c + NS - 1;
        if (cn < nch) stage_copy(cn, cn % NS);
        CP_COMMIT();
        compute(c % NS);
    }
    __syncthreads();

    // ---- epilogue ----
    float* stg = (float*)sm;   // [MT][132]
    #pragma unroll
    for (int mf = 0; mf < 2; mf++) {
        int r0 = mw * 32 + mf * 16 + grp;
        float av0 = alpha, av1 = alpha, sh0 = 0.f, sh1 = 0.f;
        if (rowScale) { av0 *= rowScale[m0 + r0]; av1 *= rowScale[m0 + r0 + 8]; }
        if (rowShift) { sh0 = rowShift[m0 + r0]; sh1 = rowShift[m0 + r0 + 8]; }
        #pragma unroll
        for (int nf = 0; nf < 2*NFP; nf++) {
            int cb = nw * NWS + nf * 8 + tig * 2;
            float* d = acc[mf][nf];
            stg[r0 * 132 + cb]           = fminf(fmaxf(d[0] * av0 + sh0, lo), hi);
            stg[r0 * 132 + cb + 1]       = fminf(fmaxf(d[1] * av0 + sh0, lo), hi);
            stg[(r0 + 8) * 132 + cb]     = fminf(fmaxf(d[2] * av1 + sh1, lo), hi);
            stg[(r0 + 8) * 132 + cb + 1] = fminf(fmaxf(d[3] * av1 + sh1, lo), hi);
        }
    }
    __syncthreads();
    if (IUP) {
        const int px = z & 1, py = (z >> 1) & 1, zb = z >> 2;
        #pragma unroll
        for (int it = 0; it < MT/8; it++) {
            int lin = tid + (it << 8);
            int rr = lin >> 5, c4 = (lin & 31) << 2;
            float4 v = *(float4*)&stg[rr * 132 + c4];
            int m = m0 + rr;
            int n = n0 + c4;
            int a = n >> 5, cc = n & 31;
            size_t base = ((size_t)zb * Cn + m) * 4096 + (size_t)(2*a + py) * 64 + 2*cc + px;
            Cf[base]     = v.x;  Cf2[base]     = v.x;
            Cf[base + 2] = v.y;  Cf2[base + 2] = v.y;
            Cf[base + 4] = v.z;  Cf2[base + 4] = v.z;
            Cf[base + 6] = v.w;  Cf2[base + 6] = v.w;
        }
    } else if (Cf) {
        #pragma unroll
        for (int it = 0; it < MT/8; it++) {
            int lin = tid + (it << 8);
            int rr = lin >> 5, c4 = (lin & 31) << 2;
            *(float4*)(Cf + (size_t)(m0 + rr) * ldc + n0 + c4) = *(float4*)&stg[rr * 132 + c4];
        }
    } else {
        #pragma unroll
        for (int it = 0; it < MT/8; it++) {
            int lin = tid + (it << 8);
            int rr = lin >> 5, c4 = (lin & 31) << 2;
            float4 v = *(float4*)&stg[rr * 132 + c4];
            size_t o = (size_t)(m0 + rr) * ldc + n0 + c4;
            if (F16) {
                uint2 hv;
                hv.x = packh2(v.x, v.y); hv.y = packh2(v.z, v.w);
                *(uint2*)(Ch + o) = hv;
            } else {
                uint2 hv, lv;
                split4(v, hv, lv);
                *(uint2*)(Ch + o) = hv;
                *(uint2*)(Cl + o) = lv;
            }
        }
    }
}

// ---------------- fused weight prep (+ zero g_score for colsum atomics) ----------------
#define PREP_O2 1048576
#define PREP_O3 1060864
#define PREP_O4 1073152
#define PREP_O5 1138688
#define PREP_O6 2187264
#define PREP_O7 2187776
#define PREP_END 2220544
__global__ void k_prep_all(const float* __restrict__ down_w,
                           const float* __restrict__ wqkv_c, const float* __restrict__ wqkv_f,
                           const float* __restrict__ pw_w,   const float* __restrict__ up_w,
                           const float* __restrict__ bn1_g, const float* __restrict__ bn1_b,
                           const float* __restrict__ bn1_m, const float* __restrict__ bn1_v,
                           const float* __restrict__ bn2_g, const float* __restrict__ bn2_b,
                           const float* __restrict__ bn2_m, const float* __restrict__ bn2_v) {
    int idx = blockIdx.x * 256 + threadIdx.x;
    if (idx < PREP_O2) {
        split1(down_w[idx], g_wdh + idx, g_wdl + idx);
    } else if (idx < PREP_O3) {
        int i = idx - PREP_O2;
        int m = i / 64, k = i % 64;
        split1(wqkv_c[k * 192 + m], g_wqch + i, g_wqcl + i);
    } else if (idx < PREP_O4) {
        int i = idx - PREP_O3;
        int m = i / 64, k = i % 64;
        half1(wqkv_f[k * 192 + m], g_wqfh + i);
    } else if (idx < PREP_O5) {
        int i = idx - PREP_O4;
        half1(pw_w[i], g_pwh + i);
    } else if (idx < PREP_O6) {
        int i = idx - PREP_O5;
        int k = i & 1023, co = (i >> 10) & 255, p = i >> 18;
        int tj = k & 1, ti = (k >> 1) & 1, ci = k >> 2;
        int px = p & 1, py = p >> 1;
        int kh = (py == 0) ? (ti == 0 ? 1 : 3) : (ti == 0 ? 0 : 2);
        int kw = (px == 0) ? (tj == 0 ? 1 : 3) : (tj == 0 ? 0 : 2);
        half1(up_w[((ci << 8) + co) * 16 + kh*4 + kw], g_Wph + i);
    } else if (idx < PREP_O7) {
        int i = idx - PREP_O6;
        int c = i & 255;
        if (i < 256) {
            float inv = bn1_g[c] / sqrtf(bn1_v[c] + 1e-5f);
            g_bn1sc[c] = inv;
            g_bn1sh[c] = bn1_b[c] - bn1_m[c] * inv;
        } else {
            float inv = bn2_g[c] / sqrtf(bn2_v[c] + 1e-5f);
            g_bn2sc[c] = inv;
            g_bn2sh[c] = bn2_b[c] - bn2_m[c] * inv;
        }
    } else if (idx < PREP_END) {
        g_score[idx - PREP_O7] = 0.f;
    }
}

// ---------------- elementwise kernels ----------------
__global__ void k_im2col_down(const float* __restrict__ x) {
    int idx = blockIdx.x * 256 + threadIdx.x;
    int q  = idx & 255;
    int k  = (idx >> 8) & 4095;
    int b  = idx >> 20;
    int kw = k & 3, kh = (k >> 2) & 3, ci = k >> 4;
    int ow0 = (q & 7) << 2, oh = q >> 3;
    int ih = oh*2 - 1 + kh;
    const float* xr = x + ((long long)b*Cn + ci)*(Hn*Wn) + ih*Wn;
    float4 r;
    float* rp = (float*)&r;
    #pragma unroll
    for (int j = 0; j < 4; j++) {
        int iw = (ow0 + j)*2 - 1 + kw;
        rp[j] = (ih >= 0 && ih < Hn && iw >= 0 && iw < Wn) ? xr[iw] : 0.f;
    }
    uint2 hv, lv; split4(r, hv, lv);
    size_t o = ((size_t)idx) << 2;
    *(uint2*)&g_colh[o] = hv;
    *(uint2*)&g_coll[o] = lv;
}

__global__ void k_im2col_up() {
    int idx = blockIdx.x * 256 + threadIdx.x;
    int q = idx & 255;
    int k = (idx >> 8) & 1023;
    int s = idx >> 18;
    int tj = k & 1, ti = (k >> 1) & 1, ci = k >> 2;
    int px = s & 1, py = (s >> 1) & 1, b = s >> 2;
    int c0 = (q & 7) << 2, a = q >> 3;
    int iy = (py == 0) ? (ti == 0 ? a : a - 1) : (ti == 0 ? a + 1 : a);
    int dx = (px == 0) ? (tj == 0 ? 0 : -1) : (tj == 0 ? 1 : 0);
    const float* orow = g_outc + ((long long)b*Cn + ci)*1024 + iy*32;
    float4 r;
    float* rp = (float*)&r;
    bool rowok = (iy >= 0 && iy < 32);
    #pragma unroll
    for (int j = 0; j < 4; j++) {
        int ix = c0 + j + dx;
        rp[j] = (rowok && ix >= 0 && ix < 32) ? orow[ix] : 0.f;
    }
    uint2 hv;
    hv.x = packh2(r.x, r.y); hv.y = packh2(r.z, r.w);
    *(uint2*)&g_colh[((size_t)idx) << 2] = hv;
}

// softmax: 1 warp per row, 8 rows per CTA. COLSUM: fuse column-sum accumulation.
template<bool F16OUT, bool COLSUM>
__global__ __launch_bounds__(256) void k_softmax(const float* __restrict__ S,
                                                 uint16_t* __restrict__ Ph, uint16_t* __restrict__ Pl,
                                                 float* __restrict__ score) {
    __shared__ float cs[8][1024];
    const int wid = threadIdx.x >> 5, lane = threadIdx.x & 31;
    const long long row = (long long)blockIdx.x * 8 + wid;
    const float4* p = (const float4*)(S + row * 1024);
    float4 v[8];
    float mx = -3.0e38f;
    #pragma unroll
    for (int i = 0; i < 8; i++) {
        v[i] = p[lane + (i << 5)];
        mx = fmaxf(mx, fmaxf(fmaxf(v[i].x, v[i].y), fmaxf(v[i].z, v[i].w)));
    }
    #pragma unroll
    for (int o = 16; o; o >>= 1) mx = fmaxf(mx, __shfl_xor_sync(0xffffffffu, mx, o));
    float s = 0.f;
    #pragma unroll
    for (int i = 0; i < 8; i++) {
        v[i].x = __expf(v[i].x - mx); v[i].y = __expf(v[i].y - mx);
        v[i].z = __expf(v[i].z - mx); v[i].w = __expf(v[i].w - mx);
        s += (v[i].x + v[i].y) + (v[i].z + v[i].w);
    }
    #pragma unroll
    for (int o = 16; o; o >>= 1) s += __shfl_xor_sync(0xffffffffu, s, o);
    const float inv = 1.f / s;
    const size_t ob = row * 1024;
    #pragma unroll
    for (int i = 0; i < 8; i++) {
        float4 r;
        r.x = v[i].x * inv; r.y = v[i].y * inv;
        r.z = v[i].z * inv; r.w = v[i].w * inv;
        size_t o = ob + ((size_t)(lane + (i << 5)) << 2);
        if (F16OUT) {
            uint2 hv;
            hv.x = packh2(r.x, r.y); hv.y = packh2(r.z, r.w);
            *(uint2*)(Ph + o) = hv;
        } else {
            uint2 hv, lv; split4(r, hv, lv);
            *(uint2*)(Ph + o) = hv;
            *(uint2*)(Pl + o) = lv;
        }
        if (COLSUM) *(float4*)&cs[wid][(lane + (i << 5)) << 2] = r;
    }
    if (COLSUM) {
        __syncthreads();
        const int zb = blockIdx.x >> 7;       // 128 CTAs per z
        for (int col = threadIdx.x; col < 1024; col += 256) {
            float t = 0.f;
            #pragma unroll
            for (int w = 0; w < 8; w++) t += cs[w][col];
            atomicAdd(&score[zb * 1024 + col], t);
        }
    }
}

__global__ __launch_bounds__(512) void k_topk() {
    __shared__ float v[1024];
    __shared__ int   ix[1024];
    int z = blockIdx.x, tid = threadIdx.x;
    for (int i = tid; i < 1024; i += 512) { v[i] = g_score[z*1024 + i]; ix[i] = i; }
    __syncthreads();
    for (int k = 2; k <= 1024; k <<= 1) {
        for (int j = k >> 1; j > 0; j >>= 1) {
            for (int i = tid; i < 1024; i += 512) {
                int l = i ^ j;
                if (l > i) {
                    bool up = ((i & k) == 0);
                    bool sw = up ? (v[i] < v[l]) : (v[i] > v[l]);
                    if (sw) {
                        float tv = v[i]; v[i] = v[l]; v[l] = tv;
                        int ti2 = ix[i]; ix[i] = ix[l]; ix[l] = ti2;
                    }
                }
            }
            __syncthreads();
        }
    }
    for (int i = tid; i < KFn; i += 512) g_topk[z*KFn + i] = ix[i];
}

__global__ void k_gather_fine() {
    int idx = blockIdx.x * 256 + threadIdx.x;
    int t = idx & 1023, d = (idx >> 10) & 63, z = idx >> 16;
    int ki = t >> 2, i = (t >> 1) & 1, j = t & 1;
    int p = g_topk[(z << 8) + ki];
    int pi = p >> 5, pj = p & 31;
    int b = z >> 2, h = z & 3;
    float v = g_coarse[((long long)b*Cn + (h*HDn + d))*4096 + (2*pi + i)*64 + (2*pj + j)];
    half1(v, g_tokh + idx);
}

__global__ void k_scatter() {
    int idx = blockIdx.x * 256 + threadIdx.x;
    int t = idx & 1023, d = (idx >> 10) & 63, z = idx >> 16;
    int ki = t >> 2, i = (t >> 1) & 1, j = t & 1;
    int p = g_topk[(z << 8) + ki];
    int pi = p >> 5, pj = p & 31;
    int b = z >> 2, h = z & 3;
    g_y0[((long long)b*Cn + (h*HDn + d))*4096 + (2*pi + i)*64 + (2*pj + j)] += g_outfT[idx];
}

__global__ void k_dw(const float* __restrict__ dw_w) {
    int idx = blockIdx.x * 256 + threadIdx.x;
    int x4 = (idx & 15) << 2, y = (idx >> 4) & 63, c = (idx >> 10) & 255, b = idx >> 18;
    const float* base = g_y0 + ((long long)b*Cn + c)*4096;
    const float* wp = dw_w + c*9;
    float s[4] = {0.f, 0.f, 0.f, 0.f};
    #pragma unroll
    for (int ky = 0; ky < 3; ky++) {
        int yy = y + ky - 1;
        if (yy < 0 || yy >= 64) continue;
        const float* row = base + yy*64;
        float4 mid = *(const float4*)(row + x4);
        float lft = (x4 > 0)  ? row[x4 - 1] : 0.f;
        float rgt = (x4 < 60) ? row[x4 + 4] : 0.f;
        float w0 = wp[ky*3], w1 = wp[ky*3 + 1], w2 = wp[ky*3 + 2];
        s[0] = fmaf(lft,   w0, fmaf(mid.x, w1, fmaf(mid.y, w2, s[0])));
        s[1] = fmaf(mid.x, w0, fmaf(mid.y, w1, fmaf(mid.z, w2, s[1])));
        s[2] = fmaf(mid.y, w0, fmaf(mid.z, w1, fmaf(mid.w, w2, s[2])));
        s[3] = fmaf(mid.z, w0, fmaf(mid.w, w1, fmaf(rgt,   w2, s[3])));
    }
    float sc = g_bn1sc[c], sh = g_bn1sh[c];
    float r0 = fminf(fmaxf(s[0]*sc + sh, 0.f), 6.f);
    float r1 = fminf(fmaxf(s[1]*sc + sh, 0.f), 6.f);
    float r2 = fminf(fmaxf(s[2]*sc + sh, 0.f), 6.f);
    float r3 = fminf(fmaxf(s[3]*sc + sh, 0.f), 6.f);
    uint2 hv;
    hv.x = packh2(r0, r1); hv.y = packh2(r2, r3);
    *(uint2*)&g_t1h[((size_t)b*Cn + c)*4096 + y*64 + x4] = hv;
}

// ---------------- host ----------------
struct GArgs {
    const uint16_t *Ah, *Al, *Bh, *Bl;
    float* Cf; float* Cf2; uint16_t *Ch, *Cl;
};
static inline int smem_for(bool atr, bool bkn, bool m64, bool f16, int ns) {
    int aslot = atr ? 8704 : (m64 ? 64 : 128) * 80;
    int bslot = bkn ? 8704 : 10240;
    int npl = f16 ? 1 : 2;
    int pipe = ns * npl * (aslot + bslot);
    int epi = (m64 ? 64 : 128) * 132 * 4;
    return pipe > epi ? pipe : epi;
}

template<bool ATR, bool BKN, bool M64T, bool IUP, bool F16, int NS>
static void launch_hgemm(dim3 grid, GArgs g,
                         int M, int N, int K, int lda, int ldb, int ldc,
                         long long sA, long long sB, long long sC, int zamask,
                         float alpha, const float* sc, const float* sh, float lo, float hi) {
    int shm = smem_for(ATR, BKN, M64T, F16, NS);
    cudaFuncSetAttribute(hgemm<ATR,BKN,M64T,IUP,F16,NS>, cudaFuncAttributeMaxDynamicSharedMemorySize, shm);
    hgemm<ATR,BKN,M64T,IUP,F16,NS><<<grid, 256, shm>>>(g.Ah, g.Al, g.Bh, g.Bl, g.Cf, g.Cf2, g.Ch, g.Cl,
        M, N, K, lda, ldb, ldc, sA, sB, sC, zamask, alpha, sc, sh, lo, hi);
}

extern "C" void kernel_launch(void* const* d_in, const int* in_sizes, int n_in,
                              void* d_out, int out_size)
{
    const float* x      = (const float*)d_in[0];
    const float* down_w = (const float*)d_in[1];
    const float* down_b = (const float*)d_in[2];
    const float* up_w   = (const float*)d_in[3];
    const float* up_b   = (const float*)d_in[4];
    const float* wqkv_c = (const float*)d_in[5];
    const float* bqkv_c = (const float*)d_in[6];
    const float* wqkv_f = (const float*)d_in[7];
    const float* bqkv_f = (const float*)d_in[8];
    const float* dw_w   = (const float*)d_in[9];
    const float* bn1_g  = (const float*)d_in[10];
    const float* bn1_b  = (const float*)d_in[11];
    const float* bn1_m  = (const float*)d_in[12];
    const float* bn1_v  = (const float*)d_in[13];
    const float* pw_w   = (const float*)d_in[14];
    const float* bn2_g  = (const float*)d_in[15];
    const float* bn2_b  = (const float*)d_in[16];
    const float* bn2_m  = (const float*)d_in[17];
    const float* bn2_v  = (const float*)d_in[18];
    float* out = (float*)d_out;

    #define SYM(p, s) cudaGetSymbolAddress((void**)&p, s)
    uint16_t *colh, *coll, *xdh, *xdl, *qch, *qcl, *qfh, *Ph, *Pl, *tokh;
    uint16_t *t1h, *wdh, *wdl, *Wph, *wqch, *wqcl, *wqfh, *pwh;
    float *S, *outc, *coarse, *y0, *outf, *score;
    float *b2s, *b2h;
    SYM(colh, g_colh); SYM(coll, g_coll); SYM(xdh, g_xdh); SYM(xdl, g_xdl);
    SYM(qch, g_qch); SYM(qcl, g_qcl); SYM(qfh, g_qfh);
    SYM(Ph, g_Ph); SYM(Pl, g_Pl); SYM(tokh, g_tokh);
    SYM(t1h, g_t1h); SYM(wdh, g_wdh); SYM(wdl, g_wdl);
    SYM(Wph, g_Wph); SYM(wqch, g_wqch); SYM(wqcl, g_wqcl);
    SYM(wqfh, g_wqfh); SYM(pwh, g_pwh);
    SYM(S, g_S); SYM(outc, g_outc); SYM(coarse, g_coarse); SYM(y0, g_y0);
    SYM(outf, g_outfT); SYM(score, g_score);
    SYM(b2s, g_bn2sc); SYM(b2h, g_bn2sh);
    #undef SYM

    const float NEG = -3.0e38f, POS = 3.0e38f;
    const int ZM = 0x7fffffff;

    k_prep_all<<<(PREP_END + 255)/256, 256>>>(down_w, wqkv_c, wqkv_f, pw_w, up_w,
        bn1_g, bn1_b, bn1_m, bn1_v, bn2_g, bn2_b, bn2_m, bn2_v);

    // ---- down conv (bf16 3-pass, K=4096, NS4; m-blocks fastest for B reuse)
    k_im2col_down<<<32768, 256>>>(x);
    launch_hgemm<false,true,true,false,false,4>(dim3(4,8,Bn),
        {wdh, wdl, colh, coll, nullptr, nullptr, xdh, xdl}, 256, 1024, 4096, 4096, 1024, 1024,
        0, 4096LL*1024, 256LL*1024, ZM, 1.f, nullptr, down_b, NEG, POS);

    // ---- coarse QKV (K=64 -> NS2, 4 CTA/SM)
    launch_hgemm<false,true,true,false,false,2>(dim3(3,8,32),
        {wqch, wqcl, xdh, xdl, nullptr, nullptr, qch, qcl}, 192, 1024, 64, 64, 1024, 1024,
        0, 65536, 196608, ZM, 1.f, nullptr, bqkv_c, NEG, POS);

    // ---- coarse S (K=64 -> NS2), softmax+colsum fused, topk
    launch_hgemm<true,true,false,false,false,2>(dim3(8,8,32),
        {qch, qcl, qch + 65536, qcl + 65536, S, nullptr, nullptr, nullptr}, 1024, 1024, 64, 1024, 1024, 1024,
        196608, 196608, 1048576, ZM, 0.125f, nullptr, nullptr, NEG, POS);
    k_softmax<false,true><<<4096, 256>>>(S, Ph, Pl, score);
    k_topk<<<32, 512>>>();

    // ---- coarse PV (K=1024, NS3)
    launch_hgemm<false,false,true,false,false,3>(dim3(1,8,32),
        {qch + 131072, qcl + 131072, Ph, Pl, outc, nullptr, nullptr, nullptr}, 64, 1024, 1024, 1024, 1024, 1024,
        196608, 1048576, 65536, ZM, 1.f, nullptr, nullptr, NEG, POS);

    // ---- up conv transpose (fp16, NS4) + interleaved dual store
    k_im2col_up<<<32768, 256>>>();
    launch_hgemm<false,true,true,true,true,4>(dim3(4,8,32),
        {Wph, nullptr, colh, nullptr, coarse, y0, nullptr, nullptr}, 256, 1024, 1024, 1024, 1024, 1024,
        262144, 1048576, 0, 3, 1.f, nullptr, up_b, NEG, POS);

    // ---- fine attention (fp16; K=64 GEMMs NS2)
    k_gather_fine<<<8192, 256>>>();
    launch_hgemm<false,true,true,false,true,2>(dim3(3,8,32),
        {wqfh, nullptr, tokh, nullptr, nullptr, nullptr, qfh, nullptr}, 192, 1024, 64, 64, 1024, 1024,
        0, 65536, 196608, ZM, 1.f, nullptr, bqkv_f, NEG, POS);
    launch_hgemm<true,true,false,false,true,2>(dim3(8,8,32),
        {qfh, nullptr, qfh + 65536, nullptr, S, nullptr, nullptr, nullptr}, 1024, 1024, 64, 1024, 1024, 1024,
        196608, 196608, 1048576, ZM, 0.125f, nullptr, nullptr, NEG, POS);
    k_softmax<true,false><<<4096, 256>>>(S, Ph, Pl, score);
    launch_hgemm<false,false,true,false,true,4>(dim3(1,8,32),
        {qfh + 131072, nullptr, Ph, nullptr, outf, nullptr, nullptr, nullptr}, 64, 1024, 1024, 1024, 1024, 1024,
        196608, 1048576, 65536, ZM, 1.f, nullptr, nullptr, NEG, POS);

    // ---- residual add, depthwise, pointwise
    k_scatter<<<8192, 256>>>();
    k_dw<<<8192, 256>>>(dw_w);
    launch_hgemm<false,true,true,false,true,4>(dim3(4,32,Bn),
        {pwh, nullptr, t1h, nullptr, out, nullptr, nullptr, nullptr}, 256, 4096, 256, 256, 4096, 4096,
        0, 1048576, 1048576, ZM, 1.f, b2s, b2h, 0.f, 6.f);
}

// round 12
// speedup vs baseline: 1.4899x; 1.0437x over previous
#include <cuda_runtime.h>
#include <cuda_bf16.h>
#include <cuda_fp16.h>
#include <math.h>
#include <stdint.h>

#define Bn 8
#define Cn 256
#define Hn 64
#define Wn 64
#define NHn 4
#define HDn 64
#define NTOK 1024
#define KFn 256

typedef __nv_bfloat16 bf;

// ---------------- static scratch ----------------
__device__ uint16_t g_colh[33554432], g_coll[33554432];
__device__ uint16_t g_xdh[2097152],  g_xdl[2097152];
__device__ uint16_t g_qch[6291456],  g_qcl[6291456];
__device__ uint16_t g_qfh[6291456];
__device__ uint16_t g_Ph[33554432],  g_Pl[33554432];
__device__ float    g_score[Bn*NHn*NTOK];
__device__ float    g_rowsum[Bn*NHn*NTOK];
__device__ int      g_topk[Bn*NHn*KFn];
__device__ float    g_outc[Bn*Cn*1024];
__device__ uint16_t g_tokh[2097152];
__device__ float    g_outfT[2097152];
__device__ float    g_coarse[8388608];
__device__ float    g_y0[8388608];
__device__ uint16_t g_t1h[8388608];
__device__ uint16_t g_wdh[1048576],  g_wdl[1048576];
__device__ uint16_t g_Wph[1048576];
__device__ uint16_t g_wqch[12288],   g_wqcl[12288];
__device__ uint16_t g_wqfh[12288];
__device__ uint16_t g_pwh[65536];
__device__ float g_bn1sc[Cn], g_bn1sh[Cn], g_bn2sc[Cn], g_bn2sh[Cn];

// ================= helpers =================
__device__ __forceinline__ void ldsm4(uint32_t* r, uint32_t addr) {
    asm volatile("ldmatrix.sync.aligned.m8n8.x4.shared.b16 {%0,%1,%2,%3}, [%4];"
                 : "=r"(r[0]), "=r"(r[1]), "=r"(r[2]), "=r"(r[3]) : "r"(addr));
}
__device__ __forceinline__ void ldsm4t(uint32_t* r, uint32_t addr) {
    asm volatile("ldmatrix.sync.aligned.m8n8.x4.trans.shared.b16 {%0,%1,%2,%3}, [%4];"
                 : "=r"(r[0]), "=r"(r[1]), "=r"(r[2]), "=r"(r[3]) : "r"(addr));
}
__device__ __forceinline__ void mma_bf(float* d, const uint32_t* a, const uint32_t* b) {
    asm volatile("mma.sync.aligned.m16n8k16.row.col.f32.bf16.bf16.f32 "
                 "{%0,%1,%2,%3},{%4,%5,%6,%7},{%8,%9},{%0,%1,%2,%3};"
                 : "+f"(d[0]), "+f"(d[1]), "+f"(d[2]), "+f"(d[3])
                 : "r"(a[0]), "r"(a[1]), "r"(a[2]), "r"(a[3]), "r"(b[0]), "r"(b[1]));
}
__device__ __forceinline__ void mma_fp(float* d, const uint32_t* a, const uint32_t* b) {
    asm volatile("mma.sync.aligned.m16n8k16.row.col.f32.f16.f16.f32 "
                 "{%0,%1,%2,%3},{%4,%5,%6,%7},{%8,%9},{%0,%1,%2,%3};"
                 : "+f"(d[0]), "+f"(d[1]), "+f"(d[2]), "+f"(d[3])
                 : "r"(a[0]), "r"(a[1]), "r"(a[2]), "r"(a[3]), "r"(b[0]), "r"(b[1]));
}
__device__ __forceinline__ void cpa16(uint32_t dst, const void* src) {
    asm volatile("cp.async.cg.shared.global [%0], [%1], 16;" :: "r"(dst), "l"(src));
}
#define CP_COMMIT() asm volatile("cp.async.commit_group;" ::: "memory")

__device__ __forceinline__ uint32_t packbf2(float a, float b) {
    __nv_bfloat162 t;
    t.x = __float2bfloat16_rn(a); t.y = __float2bfloat16_rn(b);
    return *(uint32_t*)&t;
}
__device__ __forceinline__ uint32_t packh2(float a, float b) {
    __half2 t;
    t.x = __float2half_rn(a); t.y = __float2half_rn(b);
    return *(uint32_t*)&t;
}
__device__ __forceinline__ void split4(float4 f, uint2& hv, uint2& lv) {
    float hx = __bfloat162float(__float2bfloat16_rn(f.x));
    float hy = __bfloat162float(__float2bfloat16_rn(f.y));
    float hz = __bfloat162float(__float2bfloat16_rn(f.z));
    float hw = __bfloat162float(__float2bfloat16_rn(f.w));
    hv.x = packbf2(f.x, f.y);           hv.y = packbf2(f.z, f.w);
    lv.x = packbf2(f.x - hx, f.y - hy); lv.y = packbf2(f.z - hz, f.w - hw);
}
__device__ __forceinline__ void split1(float a, uint16_t* oh, uint16_t* ol) {
    bf h = __float2bfloat16_rn(a);
    *(bf*)oh = h;
    *(bf*)ol = __float2bfloat16_rn(a - __bfloat162float(h));
}
__device__ __forceinline__ void half1(float a, uint16_t* oh) {
    *(__half*)oh = __float2half_rn(a);
}

// ================= HMMA GEMM =================
// EXPO: epilogue applies exp(acc*alpha), atomically accumulates row sums into aux.
// CDIV: fp32 epilogue divides column n by aux[n] (aux = row sums).
template<bool ATR, bool BKN, bool M64T, bool IUP, bool F16, bool EXPO, bool CDIV, int NS>
__global__ __launch_bounds__(256, M64T ? 4 : 3) void hgemm(
    const uint16_t* __restrict__ Agh, const uint16_t* __restrict__ Agl,
    const uint16_t* __restrict__ Bgh, const uint16_t* __restrict__ Bgl,
    float* __restrict__ Cf, float* __restrict__ Cf2,
    uint16_t* __restrict__ Ch, uint16_t* __restrict__ Cl,
    float* __restrict__ aux,
    int M, int N, int K, int lda, int ldb, int ldc,
    long long sA, long long sB, long long sC, int zamask,
    float alpha, const float* __restrict__ rowScale, const float* __restrict__ rowShift,
    float lo, float hi)
{
    constexpr int MT    = M64T ? 64 : 128;
    constexpr int NFP   = M64T ? 2 : 4;
    constexpr int NWS   = M64T ? 32 : 64;
    constexpr int ASLOT = ATR ? 8704 : MT * 80;
    constexpr int BSLOT = BKN ? 8704 : 10240;
    constexpr int NPL   = F16 ? 1 : 2;
    constexpr int STG   = NPL * (ASLOT + BSLOT);
    extern __shared__ char sm[];
    const uint32_t smb = (uint32_t)__cvta_generic_to_shared(sm);
    const int tid = threadIdx.x;
    const int wid = tid >> 5, lane = tid & 31;
    const int grp = lane >> 2, tig = lane & 3;
    const int z = blockIdx.z;
    const int za = z & zamask;
    Agh += (size_t)za * sA;
    Bgh += (size_t)z * sB;
    if (!F16) { Agl += (size_t)za * sA; Bgl += (size_t)z * sB; }
    if (!IUP && Cf) Cf += (size_t)z * sC;
    if (Ch) { Ch += (size_t)z * sC; if (!F16) Cl += (size_t)z * sC; }
    if (EXPO || CDIV) aux += (size_t)z * 1024;
    const int m0 = blockIdx.x * MT, n0 = blockIdx.y * 128;
    const int mw = M64T ? (wid >> 2) : (wid >> 1);
    const int nw = M64T ? (wid & 3) : (wid & 1);

    float acc[2][2*NFP][4];
    #pragma unroll
    for (int i = 0; i < 2; i++)
        #pragma unroll
        for (int j = 0; j < 2*NFP; j++)
            #pragma unroll
            for (int q = 0; q < 4; q++) acc[i][j][q] = 0.f;

    const int nch = K >> 5;

    auto stage_copy = [&](int c, int s) {
        const int k0 = c << 5;
        const uint32_t Ab = smb + s * STG;
        const uint32_t Bb = Ab + NPL * ASLOT;
        #pragma unroll
        for (int p = 0; p < ((!ATR && M64T) ? 1 : 2); p++) {
            int id = tid + (p << 8);
            if (!ATR) {
                int m = id >> 2, part = id & 3;
                size_t off = (size_t)(m0 + m) * lda + k0 + part * 8;
                uint32_t d = Ab + m * 80 + part * 16;
                cpa16(d, Agh + off);
                if (!F16) cpa16(d + ASLOT, Agl + off);
            } else {
                int k = id >> 4, part = id & 15;
                size_t off = (size_t)(k0 + k) * lda + m0 + part * 8;
                uint32_t d = Ab + k * 272 + part * 16;
                cpa16(d, Agh + off);
                if (!F16) cpa16(d + ASLOT, Agl + off);
            }
        }
        #pragma unroll
        for (int p = 0; p < 2; p++) {
            int id = tid + (p << 8);
            if (BKN) {
                int k = id >> 4, part = id & 15;
                size_t off = (size_t)(k0 + k) * ldb + n0 + part * 8;
                uint32_t d = Bb + k * 272 + part * 16;
                cpa16(d, Bgh + off);
                if (!F16) cpa16(d + BSLOT, Bgl + off);
            } else {
                int n = id >> 2, part = id & 3;
                size_t off = (size_t)(n0 + n) * ldb + k0 + part * 8;
                uint32_t d = Bb + n * 80 + part * 16;
                cpa16(d, Bgh + off);
                if (!F16) cpa16(d + BSLOT, Bgl + off);
            }
        }
    };

    auto compute = [&](int s) {
        const uint32_t Ab = smb + s * STG;
        const uint32_t Bb = Ab + NPL * ASLOT;
        const int i = lane >> 3;
        #pragma unroll
        for (int kk = 0; kk < 32; kk += 16) {
            uint32_t ah[2][4], al[2][4];
            #pragma unroll
            for (int mf = 0; mf < 2; mf++) {
                uint32_t addr;
                if (!ATR) {
                    addr = Ab + (uint32_t)((mw * 32 + mf * 16 + (lane & 15)) * 80 + (kk + (lane >> 4) * 8) * 2);
                    ldsm4(ah[mf], addr);
                    if (!F16) ldsm4(al[mf], addr + ASLOT);
                } else {
                    addr = Ab + (uint32_t)((kk + (i >> 1) * 8 + (lane & 7)) * 272 + (mw * 32 + mf * 16 + (i & 1) * 8) * 2);
                    ldsm4t(ah[mf], addr);
                    if (!F16) ldsm4t(al[mf], addr + ASLOT);
                }
            }
            uint32_t bh[NFP][4], bl[NFP][4];
            #pragma unroll
            for (int nfp = 0; nfp < NFP; nfp++) {
                uint32_t addr;
                if (BKN) {
                    addr = Bb + (uint32_t)((kk + (i & 1) * 8 + (lane & 7)) * 272 + (nw * NWS + nfp * 16 + (i >> 1) * 8) * 2);
                    ldsm4t(bh[nfp], addr);
                    if (!F16) ldsm4t(bl[nfp], addr + BSLOT);
                } else {
                    addr = Bb + (uint32_t)((nw * NWS + nfp * 16 + (i >> 1) * 8 + (lane & 7)) * 80 + (kk + (i & 1) * 8) * 2);
                    ldsm4(bh[nfp], addr);
                    if (!F16) ldsm4(bl[nfp], addr + BSLOT);
                }
            }
            #pragma unroll
            for (int pass = 0; pass < (F16 ? 1 : 3); pass++) {
                #pragma unroll
                for (int nfp = 0; nfp < NFP; nfp++) {
                    #pragma unroll
                    for (int mf = 0; mf < 2; mf++) {
                        #pragma unroll
                        for (int h = 0; h < 2; h++) {
                            const uint32_t* a = (pass == 2) ? al[mf] : ah[mf];
                            const uint32_t* b = ((pass == 1) ? bl[nfp] : bh[nfp]) + h * 2;
                            if (F16) mma_fp(acc[mf][nfp * 2 + h], a, b);
                            else     mma_bf(acc[mf][nfp * 2 + h], a, b);
                        }
                    }
                }
            }
        }
    };

    #pragma unroll
    for (int i = 0; i < NS - 1; i++) {
        if (i < nch) stage_copy(i, i);
        CP_COMMIT();
    }
    for (int c = 0; c < nch; c++) {
        asm volatile("cp.async.wait_group %0;" :: "n"(NS - 2) : "memory");
        __syncthreads();
        int cn = c + NS - 1;
        if (cn < nch) stage_copy(cn, cn % NS);
        CP_COMMIT();
        compute(c % NS);
    }
    __syncthreads();

    // ---- epilogue ----
    float* stg = (float*)sm;   // [MT][132]
    #pragma unroll
    for (int mf = 0; mf < 2; mf++) {
        int r0 = mw * 32 + mf * 16 + grp;
        float av0 = alpha, av1 = alpha, sh0 = 0.f, sh1 = 0.f;
        if (rowScale) { av0 *= rowScale[m0 + r0]; av1 *= rowScale[m0 + r0 + 8]; }
        if (rowShift) { sh0 = rowShift[m0 + r0]; sh1 = rowShift[m0 + r0 + 8]; }
        float rs0 = 0.f, rs1 = 0.f;
        #pragma unroll
        for (int nf = 0; nf < 2*NFP; nf++) {
            int cb = nw * NWS + nf * 8 + tig * 2;
            float* d = acc[mf][nf];
            float e0, e1, e2, e3;
            if (EXPO) {
                e0 = __expf(d[0] * alpha); e1 = __expf(d[1] * alpha);
                e2 = __expf(d[2] * alpha); e3 = __expf(d[3] * alpha);
                rs0 += e0 + e1; rs1 += e2 + e3;
            } else {
                e0 = fminf(fmaxf(d[0] * av0 + sh0, lo), hi);
                e1 = fminf(fmaxf(d[1] * av0 + sh0, lo), hi);
                e2 = fminf(fmaxf(d[2] * av1 + sh1, lo), hi);
                e3 = fminf(fmaxf(d[3] * av1 + sh1, lo), hi);
            }
            stg[r0 * 132 + cb]           = e0;
            stg[r0 * 132 + cb + 1]       = e1;
            stg[(r0 + 8) * 132 + cb]     = e2;
            stg[(r0 + 8) * 132 + cb + 1] = e3;
        }
        if (EXPO) {
            rs0 += __shfl_xor_sync(0xffffffffu, rs0, 1);
            rs0 += __shfl_xor_sync(0xffffffffu, rs0, 2);
            rs1 += __shfl_xor_sync(0xffffffffu, rs1, 1);
            rs1 += __shfl_xor_sync(0xffffffffu, rs1, 2);
            if (tig == 0) {
                atomicAdd(&aux[m0 + r0], rs0);
                atomicAdd(&aux[m0 + r0 + 8], rs1);
            }
        }
    }
    __syncthreads();
    if (IUP) {
        const int px = z & 1, py = (z >> 1) & 1, zb = z >> 2;
        #pragma unroll
        for (int it = 0; it < MT/8; it++) {
            int lin = tid + (it << 8);
            int rr = lin >> 5, c4 = (lin & 31) << 2;
            float4 v = *(float4*)&stg[rr * 132 + c4];
            int m = m0 + rr;
            int n = n0 + c4;
            int a = n >> 5, cc = n & 31;
            size_t base = ((size_t)zb * Cn + m) * 4096 + (size_t)(2*a + py) * 64 + 2*cc + px;
            Cf[base]     = v.x;  Cf2[base]     = v.x;
            Cf[base + 2] = v.y;  Cf2[base + 2] = v.y;
            Cf[base + 4] = v.z;  Cf2[base + 4] = v.z;
            Cf[base + 6] = v.w;  Cf2[base + 6] = v.w;
        }
    } else if (Cf) {
        #pragma unroll
        for (int it = 0; it < MT/8; it++) {
            int lin = tid + (it << 8);
            int rr = lin >> 5, c4 = (lin & 31) << 2;
            float4 v = *(float4*)&stg[rr * 132 + c4];
            if (CDIV) {
                float4 dv = *(const float4*)&aux[n0 + c4];
                v.x /= dv.x; v.y /= dv.y; v.z /= dv.z; v.w /= dv.w;
            }
            *(float4*)(Cf + (size_t)(m0 + rr) * ldc + n0 + c4) = v;
        }
    } else {
        #pragma unroll
        for (int it = 0; it < MT/8; it++) {
            int lin = tid + (it << 8);
            int rr = lin >> 5, c4 = (lin & 31) << 2;
            float4 v = *(float4*)&stg[rr * 132 + c4];
            size_t o = (size_t)(m0 + rr) * ldc + n0 + c4;
            if (F16) {
                uint2 hv;
                hv.x = packh2(v.x, v.y); hv.y = packh2(v.z, v.w);
                *(uint2*)(Ch + o) = hv;
            } else {
                uint2 hv, lv;
                split4(v, hv, lv);
                *(uint2*)(Ch + o) = hv;
                *(uint2*)(Cl + o) = lv;
            }
        }
    }
}

// ---------------- fused weight prep (+ zero score & rowsum) ----------------
#define PREP_O2 1048576
#define PREP_O3 1060864
#define PREP_O4 1073152
#define PREP_O5 1138688
#define PREP_O6 2187264
#define PREP_O7 2187776
#define PREP_O8 2220544
#define PREP_END 2253312
__global__ void k_prep_all(const float* __restrict__ down_w,
                           const float* __restrict__ wqkv_c, const float* __restrict__ wqkv_f,
                           const float* __restrict__ pw_w,   const float* __restrict__ up_w,
                           const float* __restrict__ bn1_g, const float* __restrict__ bn1_b,
                           const float* __restrict__ bn1_m, const float* __restrict__ bn1_v,
                           const float* __restrict__ bn2_g, const float* __restrict__ bn2_b,
                           const float* __restrict__ bn2_m, const float* __restrict__ bn2_v) {
    int idx = blockIdx.x * 256 + threadIdx.x;
    if (idx < PREP_O2) {
        split1(down_w[idx], g_wdh + idx, g_wdl + idx);
    } else if (idx < PREP_O3) {
        int i = idx - PREP_O2;
        int m = i / 64, k = i % 64;
        split1(wqkv_c[k * 192 + m], g_wqch + i, g_wqcl + i);
    } else if (idx < PREP_O4) {
        int i = idx - PREP_O3;
        int m = i / 64, k = i % 64;
        half1(wqkv_f[k * 192 + m], g_wqfh + i);
    } else if (idx < PREP_O5) {
        int i = idx - PREP_O4;
        half1(pw_w[i], g_pwh + i);
    } else if (idx < PREP_O6) {
        int i = idx - PREP_O5;
        int k = i & 1023, co = (i >> 10) & 255, p = i >> 18;
        int tj = k & 1, ti = (k >> 1) & 1, ci = k >> 2;
        int px = p & 1, py = p >> 1;
        int kh = (py == 0) ? (ti == 0 ? 1 : 3) : (ti == 0 ? 0 : 2);
        int kw = (px == 0) ? (tj == 0 ? 1 : 3) : (tj == 0 ? 0 : 2);
        half1(up_w[((ci << 8) + co) * 16 + kh*4 + kw], g_Wph + i);
    } else if (idx < PREP_O7) {
        int i = idx - PREP_O6;
        int c = i & 255;
        if (i < 256) {
            float inv = bn1_g[c] / sqrtf(bn1_v[c] + 1e-5f);
            g_bn1sc[c] = inv;
            g_bn1sh[c] = bn1_b[c] - bn1_m[c] * inv;
        } else {
            float inv = bn2_g[c] / sqrtf(bn2_v[c] + 1e-5f);
            g_bn2sc[c] = inv;
            g_bn2sh[c] = bn2_b[c] - bn2_m[c] * inv;
        }
    } else if (idx < PREP_O8) {
        g_score[idx - PREP_O7] = 0.f;
    } else if (idx < PREP_END) {
        g_rowsum[idx - PREP_O8] = 0.f;
    }
}

// ---------------- elementwise kernels ----------------
__global__ void k_im2col_down(const float* __restrict__ x) {
    int idx = blockIdx.x * 256 + threadIdx.x;
    int q  = idx & 255;
    int k  = (idx >> 8) & 4095;
    int b  = idx >> 20;
    int kw = k & 3, kh = (k >> 2) & 3, ci = k >> 4;
    int ow0 = (q & 7) << 2, oh = q >> 3;
    int ih = oh*2 - 1 + kh;
    const float* xr = x + ((long long)b*Cn + ci)*(Hn*Wn) + ih*Wn;
    float4 r;
    float* rp = (float*)&r;
    #pragma unroll
    for (int j = 0; j < 4; j++) {
        int iw = (ow0 + j)*2 - 1 + kw;
        rp[j] = (ih >= 0 && ih < Hn && iw >= 0 && iw < Wn) ? xr[iw] : 0.f;
    }
    uint2 hv, lv; split4(r, hv, lv);
    size_t o = ((size_t)idx) << 2;
    *(uint2*)&g_colh[o] = hv;
    *(uint2*)&g_coll[o] = lv;
}

__global__ void k_im2col_up() {
    int idx = blockIdx.x * 256 + threadIdx.x;
    int q = idx & 255;
    int k = (idx >> 8) & 1023;
    int s = idx >> 18;
    int tj = k & 1, ti = (k >> 1) & 1, ci = k >> 2;
    int px = s & 1, py = (s >> 1) & 1, b = s >> 2;
    int c0 = (q & 7) << 2, a = q >> 3;
    int iy = (py == 0) ? (ti == 0 ? a : a - 1) : (ti == 0 ? a + 1 : a);
    int dx = (px == 0) ? (tj == 0 ? 0 : -1) : (tj == 0 ? 1 : 0);
    const float* orow = g_outc + ((long long)b*Cn + ci)*1024 + iy*32;
    float4 r;
    float* rp = (float*)&r;
    bool rowok = (iy >= 0 && iy < 32);
    #pragma unroll
    for (int j = 0; j < 4; j++) {
        int ix = c0 + j + dx;
        rp[j] = (rowok && ix >= 0 && ix < 32) ? orow[ix] : 0.f;
    }
    uint2 hv;
    hv.x = packh2(r.x, r.y); hv.y = packh2(r.z, r.w);
    *(uint2*)&g_colh[((size_t)idx) << 2] = hv;
}

// weighted column sum: score[m] += sum_n P~[n][m] / l[n]   (1 warp per row n)
__global__ __launch_bounds__(256) void k_colsum_w() {
    __shared__ float cs[8][1024];
    const int wid = threadIdx.x >> 5, lane = threadIdx.x & 31;
    const long long row = (long long)blockIdx.x * 8 + wid;
    const float w = 1.f / g_rowsum[row];
    const uint2* ph = (const uint2*)(g_Ph + row * 1024);
    const uint2* pl = (const uint2*)(g_Pl + row * 1024);
    #pragma unroll
    for (int i = 0; i < 8; i++) {
        uint2 h = ph[lane + (i << 5)];
        uint2 l = pl[lane + (i << 5)];
        __nv_bfloat162 h0 = *(__nv_bfloat162*)&h.x, h1 = *(__nv_bfloat162*)&h.y;
        __nv_bfloat162 l0 = *(__nv_bfloat162*)&l.x, l1 = *(__nv_bfloat162*)&l.y;
        float4 r;
        r.x = (__bfloat162float(h0.x) + __bfloat162float(l0.x)) * w;
        r.y = (__bfloat162float(h0.y) + __bfloat162float(l0.y)) * w;
        r.z = (__bfloat162float(h1.x) + __bfloat162float(l1.x)) * w;
        r.w = (__bfloat162float(h1.y) + __bfloat162float(l1.y)) * w;
        *(float4*)&cs[wid][(lane + (i << 5)) << 2] = r;
    }
    __syncthreads();
    const int zb = blockIdx.x >> 7;
    for (int col = threadIdx.x; col < 1024; col += 256) {
        float t = 0.f;
        #pragma unroll
        for (int ww = 0; ww < 8; ww++) t += cs[ww][col];
        atomicAdd(&g_score[zb * 1024 + col], t);
    }
}

__global__ __launch_bounds__(512) void k_topk() {
    __shared__ float v[1024];
    __shared__ int   ix[1024];
    int z = blockIdx.x, tid = threadIdx.x;
    for (int i = tid; i < 1024; i += 512) { v[i] = g_score[z*1024 + i]; ix[i] = i; }
    __syncthreads();
    for (int k = 2; k <= 1024; k <<= 1) {
        for (int j = k >> 1; j > 0; j >>= 1) {
            for (int i = tid; i < 1024; i += 512) {
                int l = i ^ j;
                if (l > i) {
                    bool up = ((i & k) == 0);
                    bool sw = up ? (v[i] < v[l]) : (v[i] > v[l]);
                    if (sw) {
                        float tv = v[i]; v[i] = v[l]; v[l] = tv;
                        int ti2 = ix[i]; ix[i] = ix[l]; ix[l] = ti2;
                    }
                }
            }
            __syncthreads();
        }
    }
    for (int i = tid; i < KFn; i += 512) g_topk[z*KFn + i] = ix[i];
}

// gather + zero rowsum for fine pass
__global__ void k_gather_fine() {
    int idx = blockIdx.x * 256 + threadIdx.x;
    if (idx < 32768) g_rowsum[idx] = 0.f;
    int t = idx & 1023, d = (idx >> 10) & 63, z = idx >> 16;
    int ki = t >> 2, i = (t >> 1) & 1, j = t & 1;
    int p = g_topk[(z << 8) + ki];
    int pi = p >> 5, pj = p & 31;
    int b = z >> 2, h = z & 3;
    float v = g_coarse[((long long)b*Cn + (h*HDn + d))*4096 + (2*pi + i)*64 + (2*pj + j)];
    half1(v, g_tokh + idx);
}

__global__ void k_scatter() {
    int idx = blockIdx.x * 256 + threadIdx.x;
    int t = idx & 1023, d = (idx >> 10) & 63, z = idx >> 16;
    int ki = t >> 2, i = (t >> 1) & 1, j = t & 1;
    int p = g_topk[(z << 8) + ki];
    int pi = p >> 5, pj = p & 31;
    int b = z >> 2, h = z & 3;
    g_y0[((long long)b*Cn + (h*HDn + d))*4096 + (2*pi + i)*64 + (2*pj + j)] += g_outfT[idx];
}

__global__ void k_dw(const float* __restrict__ dw_w) {
    int idx = blockIdx.x * 256 + threadIdx.x;
    int x4 = (idx & 15) << 2, y = (idx >> 4) & 63, c = (idx >> 10) & 255, b = idx >> 18;
    const float* base = g_y0 + ((long long)b*Cn + c)*4096;
    const float* wp = dw_w + c*9;
    float s[4] = {0.f, 0.f, 0.f, 0.f};
    #pragma unroll
    for (int ky = 0; ky < 3; ky++) {
        int yy = y + ky - 1;
        if (yy < 0 || yy >= 64) continue;
        const float* row = base + yy*64;
        float4 mid = *(const float4*)(row + x4);
        float lft = (x4 > 0)  ? row[x4 - 1] : 0.f;
        float rgt = (x4 < 60) ? row[x4 + 4] : 0.f;
        float w0 = wp[ky*3], w1 = wp[ky*3 + 1], w2 = wp[ky*3 + 2];
        s[0] = fmaf(lft,   w0, fmaf(mid.x, w1, fmaf(mid.y, w2, s[0])));
        s[1] = fmaf(mid.x, w0, fmaf(mid.y, w1, fmaf(mid.z, w2, s[1])));
        s[2] = fmaf(mid.y, w0, fmaf(mid.z, w1, fmaf(mid.w, w2, s[2])));
        s[3] = fmaf(mid.z, w0, fmaf(mid.w, w1, fmaf(rgt,   w2, s[3])));
    }
    float sc = g_bn1sc[c], sh = g_bn1sh[c];
    float r0 = fminf(fmaxf(s[0]*sc + sh, 0.f), 6.f);
    float r1 = fminf(fmaxf(s[1]*sc + sh, 0.f), 6.f);
    float r2 = fminf(fmaxf(s[2]*sc + sh, 0.f), 6.f);
    float r3 = fminf(fmaxf(s[3]*sc + sh, 0.f), 6.f);
    uint2 hv;
    hv.x = packh2(r0, r1); hv.y = packh2(r2, r3);
    *(uint2*)&g_t1h[((size_t)b*Cn + c)*4096 + y*64 + x4] = hv;
}

// ---------------- host ----------------
struct GArgs {
    const uint16_t *Ah, *Al, *Bh, *Bl;
    float* Cf; float* Cf2; uint16_t *Ch, *Cl; float* aux;
};
static inline int smem_for(bool atr, bool bkn, bool m64, bool f16, int ns) {
    int aslot = atr ? 8704 : (m64 ? 64 : 128) * 80;
    int bslot = bkn ? 8704 : 10240;
    int npl = f16 ? 1 : 2;
    int pipe = ns * npl * (aslot + bslot);
    int epi = (m64 ? 64 : 128) * 132 * 4;
    return pipe > epi ? pipe : epi;
}

template<bool ATR, bool BKN, bool M64T, bool IUP, bool F16, bool EXPO, bool CDIV, int NS>
static void launch_hgemm(dim3 grid, GArgs g,
                         int M, int N, int K, int lda, int ldb, int ldc,
                         long long sA, long long sB, long long sC, int zamask,
                         float alpha, const float* sc, const float* sh, float lo, float hi) {
    int shm = smem_for(ATR, BKN, M64T, F16, NS);
    cudaFuncSetAttribute(hgemm<ATR,BKN,M64T,IUP,F16,EXPO,CDIV,NS>, cudaFuncAttributeMaxDynamicSharedMemorySize, shm);
    hgemm<ATR,BKN,M64T,IUP,F16,EXPO,CDIV,NS><<<grid, 256, shm>>>(g.Ah, g.Al, g.Bh, g.Bl, g.Cf, g.Cf2, g.Ch, g.Cl, g.aux,
        M, N, K, lda, ldb, ldc, sA, sB, sC, zamask, alpha, sc, sh, lo, hi);
}

extern "C" void kernel_launch(void* const* d_in, const int* in_sizes, int n_in,
                              void* d_out, int out_size)
{
    const float* x      = (const float*)d_in[0];
    const float* down_w = (const float*)d_in[1];
    const float* down_b = (const float*)d_in[2];
    const float* up_w   = (const float*)d_in[3];
    const float* up_b   = (const float*)d_in[4];
    const float* wqkv_c = (const float*)d_in[5];
    const float* bqkv_c = (const float*)d_in[6];
    const float* wqkv_f = (const float*)d_in[7];
    const float* bqkv_f = (const float*)d_in[8];
    const float* dw_w   = (const float*)d_in[9];
    const float* bn1_g  = (const float*)d_in[10];
    const float* bn1_b  = (const float*)d_in[11];
    const float* bn1_m  = (const float*)d_in[12];
    const float* bn1_v  = (const float*)d_in[13];
    const float* pw_w   = (const float*)d_in[14];
    const float* bn2_g  = (const float*)d_in[15];
    const float* bn2_b  = (const float*)d_in[16];
    const float* bn2_m  = (const float*)d_in[17];
    const float* bn2_v  = (const float*)d_in[18];
    float* out = (float*)d_out;

    #define SYM(p, s) cudaGetSymbolAddress((void**)&p, s)
    uint16_t *colh, *coll, *xdh, *xdl, *qch, *qcl, *qfh, *Ph, *Pl, *tokh;
    uint16_t *t1h, *wdh, *wdl, *Wph, *wqch, *wqcl, *wqfh, *pwh;
    float *outc, *coarse, *y0, *outf, *rowsum;
    float *b2s, *b2h;
    SYM(colh, g_colh); SYM(coll, g_coll); SYM(xdh, g_xdh); SYM(xdl, g_xdl);
    SYM(qch, g_qch); SYM(qcl, g_qcl); SYM(qfh, g_qfh);
    SYM(Ph, g_Ph); SYM(Pl, g_Pl); SYM(tokh, g_tokh);
    SYM(t1h, g_t1h); SYM(wdh, g_wdh); SYM(wdl, g_wdl);
    SYM(Wph, g_Wph); SYM(wqch, g_wqch); SYM(wqcl, g_wqcl);
    SYM(wqfh, g_wqfh); SYM(pwh, g_pwh);
    SYM(outc, g_outc); SYM(coarse, g_coarse); SYM(y0, g_y0);
    SYM(outf, g_outfT); SYM(rowsum, g_rowsum);
    SYM(b2s, g_bn2sc); SYM(b2h, g_bn2sh);
    #undef SYM

    const float NEG = -3.0e38f, POS = 3.0e38f;
    const int ZM = 0x7fffffff;

    k_prep_all<<<(PREP_END + 255)/256, 256>>>(down_w, wqkv_c, wqkv_f, pw_w, up_w,
        bn1_g, bn1_b, bn1_m, bn1_v, bn2_g, bn2_b, bn2_m, bn2_v);

    // ---- down conv (bf16 3-pass, K=4096, NS4)
    k_im2col_down<<<32768, 256>>>(x);
    launch_hgemm<false,true,true,false,false,false,false,4>(dim3(4,8,Bn),
        {wdh, wdl, colh, coll, nullptr, nullptr, xdh, xdl, nullptr}, 256, 1024, 4096, 4096, 1024, 1024,
        0, 4096LL*1024, 256LL*1024, ZM, 1.f, nullptr, down_b, NEG, POS);

    // ---- coarse QKV (K=64, NS2)
    launch_hgemm<false,true,true,false,false,false,false,2>(dim3(3,8,32),
        {wqch, wqcl, xdh, xdl, nullptr, nullptr, qch, qcl, nullptr}, 192, 1024, 64, 64, 1024, 1024,
        0, 65536, 196608, ZM, 1.f, nullptr, bqkv_c, NEG, POS);

    // ---- coarse S: EXP epilogue -> P~ planes + rowsums; weighted colsum; topk
    launch_hgemm<true,true,false,false,false,true,false,2>(dim3(8,8,32),
        {qch, qcl, qch + 65536, qcl + 65536, nullptr, nullptr, Ph, Pl, rowsum}, 1024, 1024, 64, 1024, 1024, 1024,
        196608, 196608, 1048576, ZM, 0.125f, nullptr, nullptr, NEG, POS);
    k_colsum_w<<<4096, 256>>>();
    k_topk<<<32, 512>>>();

    // ---- coarse PV: divide by rowsum in epilogue
    launch_hgemm<false,false,true,false,false,false,true,3>(dim3(1,8,32),
        {qch + 131072, qcl + 131072, Ph, Pl, outc, nullptr, nullptr, nullptr, rowsum}, 64, 1024, 1024, 1024, 1024, 1024,
        196608, 1048576, 65536, ZM, 1.f, nullptr, nullptr, NEG, POS);

    // ---- up conv transpose (fp16, NS4) + interleaved dual store
    k_im2col_up<<<32768, 256>>>();
    launch_hgemm<false,true,true,true,true,false,false,4>(dim3(4,8,32),
        {Wph, nullptr, colh, nullptr, coarse, y0, nullptr, nullptr, nullptr}, 256, 1024, 1024, 1024, 1024, 1024,
        262144, 1048576, 0, 3, 1.f, nullptr, up_b, NEG, POS);

    // ---- fine attention (fp16): gather (+rowsum zero), QKV, S-exp, PV-div
    k_gather_fine<<<8192, 256>>>();
    launch_hgemm<false,true,true,false,true,false,false,2>(dim3(3,8,32),
        {wqfh, nullptr, tokh, nullptr, nullptr, nullptr, qfh, nullptr, nullptr}, 192, 1024, 64, 64, 1024, 1024,
        0, 65536, 196608, ZM, 1.f, nullptr, bqkv_f, NEG, POS);
    launch_hgemm<true,true,false,false,true,true,false,2>(dim3(8,8,32),
        {qfh, nullptr, qfh + 65536, nullptr, nullptr, nullptr, Ph, nullptr, rowsum}, 1024, 1024, 64, 1024, 1024, 1024,
        196608, 196608, 1048576, ZM, 0.125f, nullptr, nullptr, NEG, POS);
    launch_hgemm<false,false,true,false,true,false,true,4>(dim3(1,8,32),
        {qfh + 131072, nullptr, Ph, nullptr, outf, nullptr, nullptr, nullptr, rowsum}, 64, 1024, 1024, 1024, 1024, 1024,
        196608, 1048576, 65536, ZM, 1.f, nullptr, nullptr, NEG, POS);

    // ---- residual add, depthwise, pointwise
    k_scatter<<<8192, 256>>>();
    k_dw<<<8192, 256>>>(dw_w);
    launch_hgemm<false,true,true,false,true,false,false,4>(dim3(4,32,Bn),
        {pwh, nullptr, t1h, nullptr, out, nullptr, nullptr, nullptr, nullptr}, 256, 4096, 256, 256, 4096, 4096,
        0, 1048576, 1048576, ZM, 1.f, b2s, b2h, 0.f, 6.f);
}